// round 8
// baseline (speedup 1.0000x reference)
#include <cuda_runtime.h>
#include <cuda_bf16.h>
#include <math.h>
#include <cstdint>

typedef unsigned long long ull;
typedef uint32_t u32;

// ---------------------------------------------------------------------------
// f32x2 helpers
// ---------------------------------------------------------------------------
__device__ __forceinline__ float2 unpack2(ull v) {
    float2 r; asm("mov.b64 {%0,%1},%2;" : "=f"(r.x), "=f"(r.y) : "l"(v)); return r;
}
__device__ __forceinline__ void ffma2(ull& d, ull a, ull b) {
    asm("fma.rn.f32x2 %0,%1,%2,%3;" : "=l"(d) : "l"(a), "l"(b), "l"(d));
}

// ===========================================================================
// Static scratch
// ===========================================================================
__device__ float g_buf1[2048 * 32 * 15 * 15];
__device__ float g_buf2[2048 * 64 * 6 * 6];
__device__ float g_buf3[2048 * 1024];
__device__ float g_feats[2048 * 512];
__device__ float g_gatesx[2048 * 1024];
__device__ float g_hbuf[2][32 * 256];
__device__ unsigned g_count;
__device__ unsigned g_gen;

#define SMEML2 ((32 * 264 + 32 * 144 + 512 + 128) * 4)

// ===========================================================================
// bf16 helpers
// ===========================================================================
__device__ __forceinline__ void mma16816(float* d, const u32* a, const u32* b) {
    asm volatile(
        "mma.sync.aligned.m16n8k16.row.col.f32.bf16.bf16.f32 "
        "{%0,%1,%2,%3}, {%4,%5,%6,%7}, {%8,%9}, {%0,%1,%2,%3};"
        : "+f"(d[0]), "+f"(d[1]), "+f"(d[2]), "+f"(d[3])
        : "r"(a[0]), "r"(a[1]), "r"(a[2]), "r"(a[3]), "r"(b[0]), "r"(b[1]));
}

__device__ __forceinline__ ull pack_hi4(float4 v, float4* rem) {
    __nv_bfloat16 h0 = __float2bfloat16_rn(v.x);
    __nv_bfloat16 h1 = __float2bfloat16_rn(v.y);
    __nv_bfloat16 h2 = __float2bfloat16_rn(v.z);
    __nv_bfloat16 h3 = __float2bfloat16_rn(v.w);
    rem->x = v.x - __bfloat162float(h0);
    rem->y = v.y - __bfloat162float(h1);
    rem->z = v.z - __bfloat162float(h2);
    rem->w = v.w - __bfloat162float(h3);
    return (ull)__bfloat16_as_ushort(h0) |
           ((ull)__bfloat16_as_ushort(h1) << 16) |
           ((ull)__bfloat16_as_ushort(h2) << 32) |
           ((ull)__bfloat16_as_ushort(h3) << 48);
}
__device__ __forceinline__ ull pack_lo4(float4 v) {
    return (ull)__bfloat16_as_ushort(__float2bfloat16_rn(v.x)) |
           ((ull)__bfloat16_as_ushort(__float2bfloat16_rn(v.y)) << 16) |
           ((ull)__bfloat16_as_ushort(__float2bfloat16_rn(v.z)) << 32) |
           ((ull)__bfloat16_as_ushort(__float2bfloat16_rn(v.w)) << 48);
}
__device__ __forceinline__ void pack_hl(float v, __nv_bfloat16* hi, __nv_bfloat16* lo) {
    __nv_bfloat16 h = __float2bfloat16_rn(v);
    *hi = h;
    *lo = __float2bfloat16_rn(v - __bfloat162float(h));
}

// ===========================================================================
// conv1 via mma.sync (bf16x3) — validated R6 version
// ===========================================================================
#define A_STRIDE 144
#define A_BYTES  (273 * A_STRIDE)
#define BQ_BYTES (32 * A_STRIDE)
#define OFF_AHI  128
#define OFF_ALO  (OFF_AHI + A_BYTES)
#define OFF_BHI  (OFF_ALO + A_BYTES)
#define OFF_BLO  (OFF_BHI + 4 * BQ_BYTES)
#define C1_SMEM  (OFF_BLO + 4 * BQ_BYTES)

__global__ __launch_bounds__(256, 1)
void conv1_mma_kernel(const float* __restrict__ x, const float* __restrict__ w,
                      const float* __restrict__ bias, float* __restrict__ out)
{
    extern __shared__ __align__(16) char smem[];
    float* sbias = (float*)smem;
    char* Ahi = smem + OFF_AHI;
    char* Alo = smem + OFF_ALO;
    char* Bhi = smem + OFF_BHI;
    char* Blo = smem + OFF_BLO;

    const int tid = threadIdx.x;
    const int n = blockIdx.x;
    const float inv255 = 1.0f / 255.0f;

    if (tid < 32) sbias[tid] = bias[tid];

    for (int idx = tid; idx < 4096; idx += 256) {
        const int row = idx >> 4;
        const int cs  = idx & 15;
        const int c = cs >> 2, s = cs & 3;
        const int gh = row >> 4, gw = row & 15;
        float4 v = *(const float4*)(x + (size_t)((n * 4 + c) * 64 + 4 * gh + s) * 64 + 4 * gw);
        v.x *= inv255; v.y *= inv255; v.z *= inv255; v.w *= inv255;
        float4 rem;
        const ull ph = pack_hi4(v, &rem);
        const ull pl = pack_lo4(rem);
        const int off = row * A_STRIDE + cs * 8;
        *(ull*)(Ahi + off) = ph;
        *(ull*)(Alo + off) = pl;
    }
    for (int i = tid; i < 612; i += 256) {
        const int half = i / 306;
        const int off = 256 * A_STRIDE + (i - half * 306) * 8;
        *(ull*)((half ? Alo : Ahi) + off) = 0ull;
    }
    for (int idx = tid; idx < 2048; idx += 256) {
        const int q  = idx >> 9;
        const int oc = (idx >> 4) & 31;
        const int cs = idx & 15;
        const int c = cs >> 2, s = cs & 3;
        const int dh = q >> 1, dw = q & 1;
        float4 v = *(const float4*)(w + (size_t)((oc * 4 + c) * 8 + 4 * dh + s) * 8 + 4 * dw);
        float4 rem;
        const ull ph = pack_hi4(v, &rem);
        const ull pl = pack_lo4(rem);
        const int off = q * BQ_BYTES + oc * A_STRIDE + cs * 8;
        *(ull*)(Bhi + off) = ph;
        *(ull*)(Blo + off) = pl;
    }
    __syncthreads();

    const int wid = tid >> 5, lane = tid & 31;
    const int g = lane >> 2, t = lane & 3;

    float acc[2][4][4];
    #pragma unroll
    for (int m = 0; m < 2; m++)
        #pragma unroll
        for (int nt = 0; nt < 4; nt++)
            #pragma unroll
            for (int r = 0; r < 4; r++) acc[m][nt][r] = 0.0f;

    const int mt0 = wid, mt1 = wid + 8;

    #pragma unroll
    for (int q = 0; q < 4; q++) {
        const int r0 = (q >> 1) * 16 + (q & 1);
        const char* Bq_hi = Bhi + q * BQ_BYTES;
        const char* Bq_lo = Blo + q * BQ_BYTES;
        const int arow0 = (mt0 * 16 + r0 + g) * A_STRIDE;
        const int arow1 = (mt1 * 16 + r0 + g) * A_STRIDE;

        #pragma unroll
        for (int ks = 0; ks < 4; ks++) {
            const int co = ks * 32 + t * 4;
            u32 ahi[2][4], alo[2][4], bhi[4][2], blo[4][2];
            #pragma unroll
            for (int m = 0; m < 2; m++) {
                const int rb = (m ? arow1 : arow0) + co;
                ahi[m][0] = *(const u32*)(Ahi + rb);
                ahi[m][1] = *(const u32*)(Ahi + rb + 8 * A_STRIDE);
                ahi[m][2] = *(const u32*)(Ahi + rb + 16);
                ahi[m][3] = *(const u32*)(Ahi + rb + 8 * A_STRIDE + 16);
                alo[m][0] = *(const u32*)(Alo + rb);
                alo[m][1] = *(const u32*)(Alo + rb + 8 * A_STRIDE);
                alo[m][2] = *(const u32*)(Alo + rb + 16);
                alo[m][3] = *(const u32*)(Alo + rb + 8 * A_STRIDE + 16);
            }
            #pragma unroll
            for (int nt = 0; nt < 4; nt++) {
                const int bo = (nt * 8 + g) * A_STRIDE + co;
                bhi[nt][0] = *(const u32*)(Bq_hi + bo);
                bhi[nt][1] = *(const u32*)(Bq_hi + bo + 16);
                blo[nt][0] = *(const u32*)(Bq_lo + bo);
                blo[nt][1] = *(const u32*)(Bq_lo + bo + 16);
            }
            #pragma unroll
            for (int m = 0; m < 2; m++)
                #pragma unroll
                for (int nt = 0; nt < 4; nt++) {
                    mma16816(acc[m][nt], ahi[m], bhi[nt]);
                    mma16816(acc[m][nt], alo[m], bhi[nt]);
                    mma16816(acc[m][nt], ahi[m], blo[nt]);
                }
        }
    }

    float* ob = out + (size_t)n * 7200;
    #pragma unroll
    for (int m = 0; m < 2; m++) {
        const int mt = m ? mt1 : mt0;
        const int r1 = mt * 16 + g;
        const int r2 = r1 + 8;
        const int oh1 = r1 >> 4, ow1 = r1 & 15;
        const int oh2 = r2 >> 4, ow2 = r2 & 15;
        #pragma unroll
        for (int nt = 0; nt < 4; nt++) {
            const int c0 = nt * 8 + 2 * t;
            const float b0 = sbias[c0], b1 = sbias[c0 + 1];
            if (oh1 < 15 && ow1 < 15) {
                float v0 = acc[m][nt][0] + b0;
                float v1 = acc[m][nt][1] + b1;
                ob[c0 * 225 + oh1 * 15 + ow1] = v0 > 0.0f ? v0 : 0.0f;
                ob[(c0 + 1) * 225 + oh1 * 15 + ow1] = v1 > 0.0f ? v1 : 0.0f;
            }
            if (oh2 < 15 && ow2 < 15) {
                float v2 = acc[m][nt][2] + b0;
                float v3 = acc[m][nt][3] + b1;
                ob[c0 * 225 + oh2 * 15 + ow2] = v2 > 0.0f ? v2 : 0.0f;
                ob[(c0 + 1) * 225 + oh2 * 15 + ow2] = v3 > 0.0f ? v3 : 0.0f;
            }
        }
    }
}

// ===========================================================================
// conv2 via mma.sync (bf16x3) — validated R7 version
// ===========================================================================
#define C2_STRIDE  272
#define C2_A_SZ    (144 * C2_STRIDE)
#define C2_B_SZ    (128 * C2_STRIDE)
#define C2_OFF_AHI 512
#define C2_OFF_ALO (C2_OFF_AHI + C2_A_SZ)
#define C2_OFF_BHI (C2_OFF_ALO + C2_A_SZ)
#define C2_OFF_BLO (C2_OFF_BHI + C2_B_SZ)
#define C2_SMEM    (C2_OFF_BLO + C2_B_SZ)

__global__ __launch_bounds__(256, 1)
void conv2_mma_kernel(const float* __restrict__ in, const float* __restrict__ w,
                      const float* __restrict__ bias, float* __restrict__ out)
{
    extern __shared__ __align__(16) char smem[];
    float* sbias = (float*)smem;
    char* Ahi = smem + C2_OFF_AHI;
    char* Alo = smem + C2_OFF_ALO;
    char* Bhi = smem + C2_OFF_BHI;
    char* Blo = smem + C2_OFF_BLO;

    const int tid = threadIdx.x;
    const int nb = blockIdx.x * 2;

    if (tid < 64) sbias[tid] = bias[tid];

    for (int idx = tid; idx < 4096; idx += 256) {
        const int im = idx >> 11;
        const int rc = idx & 2047;
        const int c  = rc >> 6;
        const int r  = rc & 63;
        const int gh = r >> 3, gw = r & 7;
        const float* ip = in + (size_t)((nb + im) * 32 + c) * 225;
        float4 v;
        {
            const int ih0 = 2 * gh, iw0 = 2 * gw;
            v.x = (ih0 < 15 && iw0     < 15) ? ip[ih0 * 15 + iw0]     : 0.0f;
            v.y = (ih0 < 15 && iw0 + 1 < 15) ? ip[ih0 * 15 + iw0 + 1] : 0.0f;
            v.z = (ih0 + 1 < 15 && iw0     < 15) ? ip[(ih0 + 1) * 15 + iw0]     : 0.0f;
            v.w = (ih0 + 1 < 15 && iw0 + 1 < 15) ? ip[(ih0 + 1) * 15 + iw0 + 1] : 0.0f;
        }
        float4 rem;
        const ull ph = pack_hi4(v, &rem);
        const ull pl = pack_lo4(rem);
        const int off = (im * 64 + r) * C2_STRIDE + c * 8;
        *(ull*)(Ahi + off) = ph;
        *(ull*)(Alo + off) = pl;
    }
    for (int i = tid; i < 1024; i += 256) {
        const int half = i >> 9;
        const int j = i & 511;
        const int off = (128 + (j >> 5)) * C2_STRIDE + (j & 31) * 8;
        *(ull*)((half ? Alo : Ahi) + off) = 0ull;
    }

    const int wid = tid >> 5, lane = tid & 31;
    const int g = lane >> 2, t = lane & 3;

    float acc[8][4];
    #pragma unroll
    for (int nt = 0; nt < 8; nt++)
        #pragma unroll
        for (int r = 0; r < 4; r++) acc[nt][r] = 0.0f;

    for (int dh = 0; dh < 2; dh++) {
        __syncthreads();
        for (int idx = tid; idx < 4096; idx += 256) {
            const int dw = idx >> 11;
            const int oc_c = idx & 2047;
            const int oc = oc_c >> 5;
            const int c = oc_c & 31;
            const float* wp = w + (size_t)(oc * 32 + c) * 16;
            float4 v;
            v.x = wp[(2 * dh) * 4 + 2 * dw];
            v.y = wp[(2 * dh) * 4 + 2 * dw + 1];
            v.z = wp[(2 * dh + 1) * 4 + 2 * dw];
            v.w = wp[(2 * dh + 1) * 4 + 2 * dw + 1];
            float4 rem;
            const ull ph = pack_hi4(v, &rem);
            const ull pl = pack_lo4(rem);
            const int off = (dw * 64 + oc) * C2_STRIDE + c * 8;
            *(ull*)(Bhi + off) = ph;
            *(ull*)(Blo + off) = pl;
        }
        __syncthreads();

        #pragma unroll
        for (int ql = 0; ql < 2; ql++) {
            const int roff = dh * 8 + ql;
            const char* Bq_hi = Bhi + ql * 64 * C2_STRIDE;
            const char* Bq_lo = Blo + ql * 64 * C2_STRIDE;
            const int arow = (wid * 16 + roff + g) * C2_STRIDE;

            #pragma unroll
            for (int ks = 0; ks < 8; ks++) {
                const int co = ks * 32 + t * 4;
                u32 ahi[4], alo[4], bhi[8][2], blo[8][2];
                const int rb = arow + co;
                ahi[0] = *(const u32*)(Ahi + rb);
                ahi[1] = *(const u32*)(Ahi + rb + 8 * C2_STRIDE);
                ahi[2] = *(const u32*)(Ahi + rb + 16);
                ahi[3] = *(const u32*)(Ahi + rb + 8 * C2_STRIDE + 16);
                alo[0] = *(const u32*)(Alo + rb);
                alo[1] = *(const u32*)(Alo + rb + 8 * C2_STRIDE);
                alo[2] = *(const u32*)(Alo + rb + 16);
                alo[3] = *(const u32*)(Alo + rb + 8 * C2_STRIDE + 16);
                #pragma unroll
                for (int nt = 0; nt < 8; nt++) {
                    const int bo = (nt * 8 + g) * C2_STRIDE + co;
                    bhi[nt][0] = *(const u32*)(Bq_hi + bo);
                    bhi[nt][1] = *(const u32*)(Bq_hi + bo + 16);
                    blo[nt][0] = *(const u32*)(Bq_lo + bo);
                    blo[nt][1] = *(const u32*)(Bq_lo + bo + 16);
                }
                #pragma unroll
                for (int nt = 0; nt < 8; nt++) {
                    mma16816(acc[nt], ahi, bhi[nt]);
                    mma16816(acc[nt], alo, bhi[nt]);
                    mma16816(acc[nt], ahi, blo[nt]);
                }
            }
        }
    }

    #pragma unroll
    for (int half = 0; half < 2; half++) {
        const int r = wid * 16 + g + half * 8;
        const int im = r >> 6;
        const int rl = r & 63;
        const int oh = rl >> 3, ow = rl & 7;
        if (oh < 6 && ow < 6) {
            float* ob = out + (size_t)(nb + im) * 2304 + oh * 6 + ow;
            #pragma unroll
            for (int nt = 0; nt < 8; nt++) {
                const int oc = nt * 8 + 2 * t;
                float v0 = acc[nt][half * 2]     + sbias[oc];
                float v1 = acc[nt][half * 2 + 1] + sbias[oc + 1];
                ob[oc * 36]       = v0 > 0.0f ? v0 : 0.0f;
                ob[(oc + 1) * 36] = v1 > 0.0f ? v1 : 0.0f;
            }
        }
    }
}

// ===========================================================================
// conv3 via mma.sync (bf16x3): 3x3 s=1 on 6x6 -> 4x4, 64ic -> 64oc.
// CTA = 8 images (1 warp each). X'[36 pos][64 ch] transposed in smem
// (144B row stride). 9 offsets, each a 16x64x64 GEMM; m-row = out pos,
// A-row = pos + kh*6+kw (row g+8 = row g + 12).
// ===========================================================================
#define C3_XSTR  144
#define C3_IMG   (36 * C3_XSTR)            // 5184
#define C3_XHI   256
#define C3_XLO   (C3_XHI + 8 * C3_IMG)     // +41472
#define C3_BHI   (C3_XLO + 8 * C3_IMG)
#define C3_BLO   (C3_BHI + 64 * C3_XSTR)
#define C3_SMEM  (C3_BLO + 64 * C3_XSTR)   // 101632

__global__ __launch_bounds__(256, 2)
void conv3_mma_kernel(const float* __restrict__ in, const float* __restrict__ w,
                      const float* __restrict__ bias, float* __restrict__ out)
{
    extern __shared__ __align__(16) char smem[];
    float* sbias = (float*)smem;
    char* Xhi = smem + C3_XHI;
    char* Xlo = smem + C3_XLO;
    char* Bhi = smem + C3_BHI;
    char* Blo = smem + C3_BLO;

    const int tid = threadIdx.x;
    const int n8 = blockIdx.x * 8;

    if (tid < 64) sbias[tid] = bias[tid];

    // fill X' (transpose): 8 img x 64 ic x 9 pos-groups of 4
    for (int idx = tid; idx < 4608; idx += 256) {
        const int im = idx / 576;
        const int r  = idx - im * 576;
        const int ic = r / 9;
        const int pg = r - ic * 9;
        float4 v = *(const float4*)(in + (size_t)(n8 + im) * 2304 + ic * 36 + pg * 4);
        char* xh = Xhi + im * C3_IMG;
        char* xl = Xlo + im * C3_IMG;
        __nv_bfloat16 h, l;
        pack_hl(v.x, &h, &l);
        *(__nv_bfloat16*)(xh + (pg * 4 + 0) * C3_XSTR + ic * 2) = h;
        *(__nv_bfloat16*)(xl + (pg * 4 + 0) * C3_XSTR + ic * 2) = l;
        pack_hl(v.y, &h, &l);
        *(__nv_bfloat16*)(xh + (pg * 4 + 1) * C3_XSTR + ic * 2) = h;
        *(__nv_bfloat16*)(xl + (pg * 4 + 1) * C3_XSTR + ic * 2) = l;
        pack_hl(v.z, &h, &l);
        *(__nv_bfloat16*)(xh + (pg * 4 + 2) * C3_XSTR + ic * 2) = h;
        *(__nv_bfloat16*)(xl + (pg * 4 + 2) * C3_XSTR + ic * 2) = l;
        pack_hl(v.w, &h, &l);
        *(__nv_bfloat16*)(xh + (pg * 4 + 3) * C3_XSTR + ic * 2) = h;
        *(__nv_bfloat16*)(xl + (pg * 4 + 3) * C3_XSTR + ic * 2) = l;
    }

    const int wid = tid >> 5, lane = tid & 31;
    const int g = lane >> 2, t = lane & 3;
    const int n = n8 + wid;

    float acc[8][4];
    #pragma unroll
    for (int nt = 0; nt < 8; nt++)
        #pragma unroll
        for (int r = 0; r < 4; r++) acc[nt][r] = 0.0f;

    const int ri_g = (g >> 2) * 6 + (g & 3);   // base input row for pos=g
    const char* Xh = Xhi + wid * C3_IMG;
    const char* Xl = Xlo + wid * C3_IMG;

    for (int off = 0; off < 9; off++) {
        __syncthreads();
        // B(off): 64 oc x 64 ic
        for (int idx = tid; idx < 4096; idx += 256) {
            const int oc = idx >> 6;
            const int ic = idx & 63;
            const float v = w[(size_t)(oc * 64 + ic) * 9 + off];
            __nv_bfloat16 h, l;
            pack_hl(v, &h, &l);
            *(__nv_bfloat16*)(Bhi + oc * C3_XSTR + ic * 2) = h;
            *(__nv_bfloat16*)(Blo + oc * C3_XSTR + ic * 2) = l;
        }
        __syncthreads();

        const int kh = off / 3, kw = off - kh * 3;
        const int rowA = (ri_g + kh * 6 + kw) * C3_XSTR;

        #pragma unroll
        for (int ks = 0; ks < 4; ks++) {
            const int co = ks * 32 + t * 4;
            u32 ahi[4], alo[4], bhi[8][2], blo[8][2];
            const int rb = rowA + co;
            ahi[0] = *(const u32*)(Xh + rb);
            ahi[1] = *(const u32*)(Xh + rb + 12 * C3_XSTR);
            ahi[2] = *(const u32*)(Xh + rb + 16);
            ahi[3] = *(const u32*)(Xh + rb + 12 * C3_XSTR + 16);
            alo[0] = *(const u32*)(Xl + rb);
            alo[1] = *(const u32*)(Xl + rb + 12 * C3_XSTR);
            alo[2] = *(const u32*)(Xl + rb + 16);
            alo[3] = *(const u32*)(Xl + rb + 12 * C3_XSTR + 16);
            #pragma unroll
            for (int nt = 0; nt < 8; nt++) {
                const int bo = (nt * 8 + g) * C3_XSTR + co;
                bhi[nt][0] = *(const u32*)(Bhi + bo);
                bhi[nt][1] = *(const u32*)(Bhi + bo + 16);
                blo[nt][0] = *(const u32*)(Blo + bo);
                blo[nt][1] = *(const u32*)(Blo + bo + 16);
            }
            #pragma unroll
            for (int nt = 0; nt < 8; nt++) {
                mma16816(acc[nt], ahi, bhi[nt]);
                mma16816(acc[nt], alo, bhi[nt]);
                mma16816(acc[nt], ahi, blo[nt]);
            }
        }
    }

    // epilogue: pos p1=g, p2=g+8; out[n*1024 + oc*16 + p]
    float* ob = out + (size_t)n * 1024;
    #pragma unroll
    for (int nt = 0; nt < 8; nt++) {
        const int oc = nt * 8 + 2 * t;
        const float b0 = sbias[oc], b1 = sbias[oc + 1];
        float v0 = acc[nt][0] + b0;
        float v1 = acc[nt][1] + b1;
        float v2 = acc[nt][2] + b0;
        float v3 = acc[nt][3] + b1;
        ob[oc * 16 + g]           = v0 > 0.0f ? v0 : 0.0f;
        ob[(oc + 1) * 16 + g]     = v1 > 0.0f ? v1 : 0.0f;
        ob[oc * 16 + g + 8]       = v2 > 0.0f ? v2 : 0.0f;
        ob[(oc + 1) * 16 + g + 8] = v3 > 0.0f ? v3 : 0.0f;
    }
}

// ===========================================================================
// GEMM (NT) via mma.sync bf16x3 — validated R7 version
// ===========================================================================
template <bool RELU>
__global__ __launch_bounds__(256, 2)
void gemm_hmma(const float* __restrict__ A, const float* __restrict__ B,
               const float* __restrict__ b1, const float* __restrict__ b2,
               float* __restrict__ C, int K, int N)
{
    __shared__ __align__(16) char Ahi[128 * 80];
    __shared__ __align__(16) char Alo[128 * 80];
    __shared__ __align__(16) char Bhi[64 * 80];
    __shared__ __align__(16) char Blo[64 * 80];

    const int tid = threadIdx.x;
    const int m0 = blockIdx.y * 128;
    const int n0 = blockIdx.x * 64;
    const int wid = tid >> 5, lane = tid & 31;
    const int g = lane >> 2, t = lane & 3;
    const int wm = wid & 3;
    const int wn = wid >> 2;

    float acc[2][4][4];
    #pragma unroll
    for (int ms = 0; ms < 2; ms++)
        #pragma unroll
        for (int nt = 0; nt < 4; nt++)
            #pragma unroll
            for (int r = 0; r < 4; r++) acc[ms][nt][r] = 0.0f;

    for (int k0 = 0; k0 < K; k0 += 32) {
        #pragma unroll
        for (int l = 0; l < 4; l++) {
            const int idx = tid + l * 256;
            const int row = idx >> 3;
            const int c8 = (idx & 7) * 8;
            float4 v = *(const float4*)(A + (size_t)(m0 + row) * K + k0 + (idx & 7) * 4);
            float4 rem;
            const ull ph = pack_hi4(v, &rem);
            const ull pl = pack_lo4(rem);
            *(ull*)(Ahi + row * 80 + c8) = ph;
            *(ull*)(Alo + row * 80 + c8) = pl;
        }
        #pragma unroll
        for (int l = 0; l < 2; l++) {
            const int idx = tid + l * 256;
            const int row = idx >> 3;
            const int c8 = (idx & 7) * 8;
            float4 v = *(const float4*)(B + (size_t)(n0 + row) * K + k0 + (idx & 7) * 4);
            float4 rem;
            const ull ph = pack_hi4(v, &rem);
            const ull pl = pack_lo4(rem);
            *(ull*)(Bhi + row * 80 + c8) = ph;
            *(ull*)(Blo + row * 80 + c8) = pl;
        }
        __syncthreads();

        #pragma unroll
        for (int ks = 0; ks < 2; ks++) {
            const int co = ks * 32 + t * 4;
            u32 ahi[2][4], alo[2][4], bhi[4][2], blo[4][2];
            #pragma unroll
            for (int ms = 0; ms < 2; ms++) {
                const int rb = (wm * 32 + ms * 16 + g) * 80 + co;
                ahi[ms][0] = *(const u32*)(Ahi + rb);
                ahi[ms][1] = *(const u32*)(Ahi + rb + 8 * 80);
                ahi[ms][2] = *(const u32*)(Ahi + rb + 16);
                ahi[ms][3] = *(const u32*)(Ahi + rb + 8 * 80 + 16);
                alo[ms][0] = *(const u32*)(Alo + rb);
                alo[ms][1] = *(const u32*)(Alo + rb + 8 * 80);
                alo[ms][2] = *(const u32*)(Alo + rb + 16);
                alo[ms][3] = *(const u32*)(Alo + rb + 8 * 80 + 16);
            }
            #pragma unroll
            for (int nt = 0; nt < 4; nt++) {
                const int bo = (wn * 32 + nt * 8 + g) * 80 + co;
                bhi[nt][0] = *(const u32*)(Bhi + bo);
                bhi[nt][1] = *(const u32*)(Bhi + bo + 16);
                blo[nt][0] = *(const u32*)(Blo + bo);
                blo[nt][1] = *(const u32*)(Blo + bo + 16);
            }
            #pragma unroll
            for (int ms = 0; ms < 2; ms++)
                #pragma unroll
                for (int nt = 0; nt < 4; nt++) {
                    mma16816(acc[ms][nt], ahi[ms], bhi[nt]);
                    mma16816(acc[ms][nt], alo[ms], bhi[nt]);
                    mma16816(acc[ms][nt], ahi[ms], blo[nt]);
                }
        }
        __syncthreads();
    }

    #pragma unroll
    for (int ms = 0; ms < 2; ms++) {
        #pragma unroll
        for (int half = 0; half < 2; half++) {
            const int row = m0 + wm * 32 + ms * 16 + g + half * 8;
            #pragma unroll
            for (int nt = 0; nt < 4; nt++) {
                const int col = n0 + wn * 32 + nt * 8 + 2 * t;
                float bb0 = b1[col]     + (b2 ? b2[col]     : 0.0f);
                float bb1 = b1[col + 1] + (b2 ? b2[col + 1] : 0.0f);
                float v0 = acc[ms][nt][half * 2]     + bb0;
                float v1 = acc[ms][nt][half * 2 + 1] + bb1;
                if (RELU) { v0 = v0 > 0.0f ? v0 : 0.0f; v1 = v1 > 0.0f ? v1 : 0.0f; }
                C[(size_t)row * N + col]     = v0;
                C[(size_t)row * N + col + 1] = v1;
            }
        }
    }
}

// ===========================================================================
// LSTM v2: 64 blocks x 256 threads, register-resident w_hh + f32x2.
// warp = k-chunk (ks), lane = (j16, bh). Each thread: w[j][ks*32:+32] in regs.
// Partials reduced via padded smem (stride 9 -> conflict-free).
// ===========================================================================
__global__ __launch_bounds__(256, 1)
void lstm2_kernel(const float* __restrict__ gx, const float* __restrict__ whh,
                  const int* __restrict__ done,
                  const float* __restrict__ h0, const float* __restrict__ c0,
                  float* __restrict__ out)
{
    extern __shared__ __align__(16) float sm[];
    float* h_s    = sm;                     // 32 x 264
    float* part   = sm + 32 * 264;          // 32 x 144 (stride 144, j16*9+ks)
    float* gate_s = part + 32 * 144;        // 512
    float* c_s    = gate_s + 512;           // 128

    const int tid = threadIdx.x;
    const int j0 = blockIdx.x * 4;
    const int ks  = tid >> 5;          // warp = k-chunk
    const int lane = tid & 31;
    const int j16 = lane & 15;         // gate-row within block
    const int bh  = lane >> 4;         // batch half
    const int g2 = j16 >> 2, jj = j16 & 3;

    // register-resident w_hh slice: row g2*256 + j0 + jj, cols ks*32..+32
    ull wr[16];
    {
        const float* wp = whh + (size_t)(g2 * 256 + j0 + jj) * 256 + ks * 32;
        #pragma unroll
        for (int i = 0; i < 8; i++) {
            ulonglong2 v = *(const ulonglong2*)(wp + i * 4);
            wr[2 * i] = v.x; wr[2 * i + 1] = v.y;
        }
    }
    if (tid < 128) {
        const int b = tid >> 2, j2 = tid & 3;
        c_s[tid] = c0[b * 256 + j0 + j2];
    }
    unsigned bar_gen = 0;
    if (tid == 0) bar_gen = *((volatile unsigned*)&g_gen);
    __syncthreads();

    for (int t = 0; t < 64; t++) {
        const float* hsrc = (t == 0) ? h0 : g_hbuf[(t - 1) & 1];
        const int* dn = done + t * 32;
        #pragma unroll
        for (int l = 0; l < 8; l++) {
            const int f = tid + l * 256;
            const int bb = f >> 6;
            const int kc = (f & 63) * 4;
            const float m = 1.0f - (float)dn[bb];
            float4 v = *(const float4*)(hsrc + bb * 256 + kc);
            v.x *= m; v.y *= m; v.z *= m; v.w *= m;
            *(float4*)(h_s + bb * 264 + kc) = v;
        }
        __syncthreads();

        // partial dots: 16 batches per thread (its half), k-chunk ks
        #pragma unroll 4
        for (int b16 = 0; b16 < 16; b16++) {
            const int b = bh * 16 + b16;
            const float* hp = h_s + b * 264 + ks * 32;
            ull a0 = 0ull, a1 = 0ull;
            #pragma unroll
            for (int i = 0; i < 8; i++) {
                const ulonglong2 hx = *(const ulonglong2*)(hp + i * 4);
                ffma2(a0, wr[2 * i], hx.x);
                ffma2(a1, wr[2 * i + 1], hx.y);
            }
            const float2 f0 = unpack2(a0), f1 = unpack2(a1);
            part[b * 144 + j16 * 9 + ks] = (f0.x + f0.y) + (f1.x + f1.y);
        }
        __syncthreads();

        // reduce 8 partials + gx -> gate_s[b*16 + j16]
        #pragma unroll
        for (int u = 0; u < 2; u++) {
            const int gi = tid + u * 256;
            const int b = gi >> 4;
            const int j = gi & 15;
            const float* pb = part + b * 144 + j * 9;
            float s = ((pb[0] + pb[1]) + (pb[2] + pb[3])) +
                      ((pb[4] + pb[5]) + (pb[6] + pb[7]));
            s += gx[(size_t)(t * 32 + b) * 1024 + (j >> 2) * 256 + j0 + (j & 3)];
            gate_s[b * 16 + j] = s;
        }
        __syncthreads();

        if (tid < 128) {
            const int bb = tid >> 2, j2 = tid & 3;
            const float gi = gate_s[bb * 16 + j2];
            const float gf = gate_s[bb * 16 + 4 + j2];
            const float gg = gate_s[bb * 16 + 8 + j2];
            const float go = gate_s[bb * 16 + 12 + j2];
            const float m = 1.0f - (float)dn[bb];
            const float cold = c_s[tid] * m;
            const float si = 1.0f / (1.0f + __expf(-gi));
            const float sf = 1.0f / (1.0f + __expf(-gf));
            const float so = 1.0f / (1.0f + __expf(-go));
            const float cn = sf * cold + si * tanhf(gg);
            const float h = so * tanhf(cn);
            c_s[tid] = cn;
            const int j = j0 + j2;
            g_hbuf[t & 1][bb * 256 + j] = h;
            out[(size_t)(t * 32 + bb) * 256 + j] = h;
        }
        __threadfence();
        __syncthreads();

        if (t < 63) {
            if (tid == 0) {
                const unsigned prev = atomicAdd(&g_count, 1);
                if (prev == gridDim.x - 1) {
                    g_count = 0;
                    __threadfence();
                    atomicAdd(&g_gen, 1);
                } else {
                    while (*((volatile unsigned*)&g_gen) == bar_gen) { }
                }
                bar_gen++;
                __threadfence();
            }
            __syncthreads();
        }
    }
}

// ===========================================================================
extern "C" void kernel_launch(void* const* d_in, const int* in_sizes, int n_in,
                              void* d_out, int out_size)
{
    const float* x    = (const float*)d_in[0];
    const int*   done = (const int*)d_in[1];
    const float* w1   = (const float*)d_in[2];
    const float* b1   = (const float*)d_in[3];
    const float* w2   = (const float*)d_in[4];
    const float* b2   = (const float*)d_in[5];
    const float* w3   = (const float*)d_in[6];
    const float* b3   = (const float*)d_in[7];
    const float* fcw  = (const float*)d_in[8];
    const float* fcb  = (const float*)d_in[9];
    const float* wih  = (const float*)d_in[10];
    const float* whh  = (const float*)d_in[11];
    const float* bih  = (const float*)d_in[12];
    const float* bhh  = (const float*)d_in[13];
    const float* h0   = (const float*)d_in[14];
    const float* c0   = (const float*)d_in[15];
    float* out = (float*)d_out;

    float *buf1, *buf2, *buf3, *feats, *gatesx;
    cudaGetSymbolAddress((void**)&buf1,   g_buf1);
    cudaGetSymbolAddress((void**)&buf2,   g_buf2);
    cudaGetSymbolAddress((void**)&buf3,   g_buf3);
    cudaGetSymbolAddress((void**)&feats,  g_feats);
    cudaGetSymbolAddress((void**)&gatesx, g_gatesx);

    cudaFuncSetAttribute(conv1_mma_kernel, cudaFuncAttributeMaxDynamicSharedMemorySize, C1_SMEM);
    cudaFuncSetAttribute(conv2_mma_kernel, cudaFuncAttributeMaxDynamicSharedMemorySize, C2_SMEM);
    cudaFuncSetAttribute(conv3_mma_kernel, cudaFuncAttributeMaxDynamicSharedMemorySize, C3_SMEM);
    cudaFuncSetAttribute(lstm2_kernel, cudaFuncAttributeMaxDynamicSharedMemorySize, SMEML2);

    conv1_mma_kernel<<<2048, 256, C1_SMEM>>>(x, w1, b1, buf1);
    conv2_mma_kernel<<<1024, 256, C2_SMEM>>>(buf1, w2, b2, buf2);
    conv3_mma_kernel<<<256, 256, C3_SMEM>>>(buf2, w3, b3, buf3);
    gemm_hmma<true><<<dim3(8, 16), 256>>>(buf3, fcw, fcb, nullptr, feats, 1024, 512);
    gemm_hmma<false><<<dim3(16, 16), 256>>>(feats, wih, bih, bhh, gatesx, 512, 1024);
    lstm2_kernel<<<64, 256, SMEML2>>>(gatesx, whh, done, h0, c0, out);
}

// round 9
// speedup vs baseline: 1.0462x; 1.0462x over previous
#include <cuda_runtime.h>
#include <cuda_bf16.h>
#include <math.h>
#include <cstdint>

typedef unsigned long long ull;
typedef uint32_t u32;

// ===========================================================================
// Static scratch
// ===========================================================================
__device__ float g_buf1[2048 * 32 * 15 * 15];
__device__ float g_buf2[2048 * 64 * 6 * 6];
__device__ float g_buf3[2048 * 1024];
__device__ float g_gatesx[2048 * 1024];
__device__ float g_hbuf[2][32 * 256];
__device__ unsigned g_count;
__device__ unsigned g_gen;
// bf16 hi/lo pre-converted operands
__device__ __nv_bfloat16 g_b3h[2048 * 1024], g_b3l[2048 * 1024];
__device__ __nv_bfloat16 g_fcwh[512 * 1024], g_fcwl[512 * 1024];
__device__ __nv_bfloat16 g_wihh[1024 * 512], g_wihl[1024 * 512];
__device__ __nv_bfloat16 g_fh[2048 * 512],  g_fl[2048 * 512];

#define SMEM3 ((9216 + 32 * 577) * 4)
#define SMEML ((16 * 264 + 32 * 264 + 512 + 128) * 4)

// ===========================================================================
// bf16 helpers
// ===========================================================================
__device__ __forceinline__ void mma16816(float* d, const u32* a, const u32* b) {
    asm volatile(
        "mma.sync.aligned.m16n8k16.row.col.f32.bf16.bf16.f32 "
        "{%0,%1,%2,%3}, {%4,%5,%6,%7}, {%8,%9}, {%0,%1,%2,%3};"
        : "+f"(d[0]), "+f"(d[1]), "+f"(d[2]), "+f"(d[3])
        : "r"(a[0]), "r"(a[1]), "r"(a[2]), "r"(a[3]), "r"(b[0]), "r"(b[1]));
}

__device__ __forceinline__ ull pack_hi4(float4 v, float4* rem) {
    __nv_bfloat16 h0 = __float2bfloat16_rn(v.x);
    __nv_bfloat16 h1 = __float2bfloat16_rn(v.y);
    __nv_bfloat16 h2 = __float2bfloat16_rn(v.z);
    __nv_bfloat16 h3 = __float2bfloat16_rn(v.w);
    rem->x = v.x - __bfloat162float(h0);
    rem->y = v.y - __bfloat162float(h1);
    rem->z = v.z - __bfloat162float(h2);
    rem->w = v.w - __bfloat162float(h3);
    return (ull)__bfloat16_as_ushort(h0) |
           ((ull)__bfloat16_as_ushort(h1) << 16) |
           ((ull)__bfloat16_as_ushort(h2) << 32) |
           ((ull)__bfloat16_as_ushort(h3) << 48);
}
__device__ __forceinline__ ull pack_lo4(float4 v) {
    return (ull)__bfloat16_as_ushort(__float2bfloat16_rn(v.x)) |
           ((ull)__bfloat16_as_ushort(__float2bfloat16_rn(v.y)) << 16) |
           ((ull)__bfloat16_as_ushort(__float2bfloat16_rn(v.z)) << 32) |
           ((ull)__bfloat16_as_ushort(__float2bfloat16_rn(v.w)) << 48);
}
__device__ __forceinline__ void pack_hl(float v, __nv_bfloat16* hi, __nv_bfloat16* lo) {
    __nv_bfloat16 h = __float2bfloat16_rn(v);
    *hi = h;
    *lo = __float2bfloat16_rn(v - __bfloat162float(h));
}

// ===========================================================================
// cvt_hilo: fp32 -> bf16 hi/lo split (memory-bound, one pass)
// ===========================================================================
__global__ __launch_bounds__(256)
void cvt_hilo(const float4* __restrict__ src, ull* __restrict__ hi,
              ull* __restrict__ lo, int n4)
{
    const int i = blockIdx.x * 256 + threadIdx.x;
    if (i < n4) {
        float4 v = src[i];
        float4 rem;
        const ull ph = pack_hi4(v, &rem);
        hi[i] = ph;
        lo[i] = pack_lo4(rem);
    }
}

// ===========================================================================
// conv1 via mma.sync (bf16x3) — validated R6/R7 version
// ===========================================================================
#define A_STRIDE 144
#define A_BYTES  (273 * A_STRIDE)
#define BQ_BYTES (32 * A_STRIDE)
#define OFF_AHI  128
#define OFF_ALO  (OFF_AHI + A_BYTES)
#define OFF_BHI  (OFF_ALO + A_BYTES)
#define OFF_BLO  (OFF_BHI + 4 * BQ_BYTES)
#define C1_SMEM  (OFF_BLO + 4 * BQ_BYTES)

__global__ __launch_bounds__(256, 1)
void conv1_mma_kernel(const float* __restrict__ x, const float* __restrict__ w,
                      const float* __restrict__ bias, float* __restrict__ out)
{
    extern __shared__ __align__(16) char smem[];
    float* sbias = (float*)smem;
    char* Ahi = smem + OFF_AHI;
    char* Alo = smem + OFF_ALO;
    char* Bhi = smem + OFF_BHI;
    char* Blo = smem + OFF_BLO;

    const int tid = threadIdx.x;
    const int n = blockIdx.x;
    const float inv255 = 1.0f / 255.0f;

    if (tid < 32) sbias[tid] = bias[tid];

    for (int idx = tid; idx < 4096; idx += 256) {
        const int row = idx >> 4;
        const int cs  = idx & 15;
        const int c = cs >> 2, s = cs & 3;
        const int gh = row >> 4, gw = row & 15;
        float4 v = *(const float4*)(x + (size_t)((n * 4 + c) * 64 + 4 * gh + s) * 64 + 4 * gw);
        v.x *= inv255; v.y *= inv255; v.z *= inv255; v.w *= inv255;
        float4 rem;
        const ull ph = pack_hi4(v, &rem);
        const ull pl = pack_lo4(rem);
        const int off = row * A_STRIDE + cs * 8;
        *(ull*)(Ahi + off) = ph;
        *(ull*)(Alo + off) = pl;
    }
    for (int i = tid; i < 612; i += 256) {
        const int half = i / 306;
        const int off = 256 * A_STRIDE + (i - half * 306) * 8;
        *(ull*)((half ? Alo : Ahi) + off) = 0ull;
    }
    for (int idx = tid; idx < 2048; idx += 256) {
        const int q  = idx >> 9;
        const int oc = (idx >> 4) & 31;
        const int cs = idx & 15;
        const int c = cs >> 2, s = cs & 3;
        const int dh = q >> 1, dw = q & 1;
        float4 v = *(const float4*)(w + (size_t)((oc * 4 + c) * 8 + 4 * dh + s) * 8 + 4 * dw);
        float4 rem;
        const ull ph = pack_hi4(v, &rem);
        const ull pl = pack_lo4(rem);
        const int off = q * BQ_BYTES + oc * A_STRIDE + cs * 8;
        *(ull*)(Bhi + off) = ph;
        *(ull*)(Blo + off) = pl;
    }
    __syncthreads();

    const int wid = tid >> 5, lane = tid & 31;
    const int g = lane >> 2, t = lane & 3;

    float acc[2][4][4];
    #pragma unroll
    for (int m = 0; m < 2; m++)
        #pragma unroll
        for (int nt = 0; nt < 4; nt++)
            #pragma unroll
            for (int r = 0; r < 4; r++) acc[m][nt][r] = 0.0f;

    const int mt0 = wid, mt1 = wid + 8;

    #pragma unroll
    for (int q = 0; q < 4; q++) {
        const int r0 = (q >> 1) * 16 + (q & 1);
        const char* Bq_hi = Bhi + q * BQ_BYTES;
        const char* Bq_lo = Blo + q * BQ_BYTES;
        const int arow0 = (mt0 * 16 + r0 + g) * A_STRIDE;
        const int arow1 = (mt1 * 16 + r0 + g) * A_STRIDE;

        #pragma unroll
        for (int ks = 0; ks < 4; ks++) {
            const int co = ks * 32 + t * 4;
            u32 ahi[2][4], alo[2][4], bhi[4][2], blo[4][2];
            #pragma unroll
            for (int m = 0; m < 2; m++) {
                const int rb = (m ? arow1 : arow0) + co;
                ahi[m][0] = *(const u32*)(Ahi + rb);
                ahi[m][1] = *(const u32*)(Ahi + rb + 8 * A_STRIDE);
                ahi[m][2] = *(const u32*)(Ahi + rb + 16);
                ahi[m][3] = *(const u32*)(Ahi + rb + 8 * A_STRIDE + 16);
                alo[m][0] = *(const u32*)(Alo + rb);
                alo[m][1] = *(const u32*)(Alo + rb + 8 * A_STRIDE);
                alo[m][2] = *(const u32*)(Alo + rb + 16);
                alo[m][3] = *(const u32*)(Alo + rb + 8 * A_STRIDE + 16);
            }
            #pragma unroll
            for (int nt = 0; nt < 4; nt++) {
                const int bo = (nt * 8 + g) * A_STRIDE + co;
                bhi[nt][0] = *(const u32*)(Bq_hi + bo);
                bhi[nt][1] = *(const u32*)(Bq_hi + bo + 16);
                blo[nt][0] = *(const u32*)(Bq_lo + bo);
                blo[nt][1] = *(const u32*)(Bq_lo + bo + 16);
            }
            #pragma unroll
            for (int m = 0; m < 2; m++)
                #pragma unroll
                for (int nt = 0; nt < 4; nt++) {
                    mma16816(acc[m][nt], ahi[m], bhi[nt]);
                    mma16816(acc[m][nt], alo[m], bhi[nt]);
                    mma16816(acc[m][nt], ahi[m], blo[nt]);
                }
        }
    }

    float* ob = out + (size_t)n * 7200;
    #pragma unroll
    for (int m = 0; m < 2; m++) {
        const int mt = m ? mt1 : mt0;
        const int r1 = mt * 16 + g;
        const int r2 = r1 + 8;
        const int oh1 = r1 >> 4, ow1 = r1 & 15;
        const int oh2 = r2 >> 4, ow2 = r2 & 15;
        #pragma unroll
        for (int nt = 0; nt < 4; nt++) {
            const int c0 = nt * 8 + 2 * t;
            const float b0 = sbias[c0], b1 = sbias[c0 + 1];
            if (oh1 < 15 && ow1 < 15) {
                float v0 = acc[m][nt][0] + b0;
                float v1 = acc[m][nt][1] + b1;
                ob[c0 * 225 + oh1 * 15 + ow1] = v0 > 0.0f ? v0 : 0.0f;
                ob[(c0 + 1) * 225 + oh1 * 15 + ow1] = v1 > 0.0f ? v1 : 0.0f;
            }
            if (oh2 < 15 && ow2 < 15) {
                float v2 = acc[m][nt][2] + b0;
                float v3 = acc[m][nt][3] + b1;
                ob[c0 * 225 + oh2 * 15 + ow2] = v2 > 0.0f ? v2 : 0.0f;
                ob[(c0 + 1) * 225 + oh2 * 15 + ow2] = v3 > 0.0f ? v3 : 0.0f;
            }
        }
    }
}

// ===========================================================================
// conv2 via mma.sync (bf16x3) — validated R7 version
// ===========================================================================
#define C2_STRIDE  272
#define C2_A_SZ    (144 * C2_STRIDE)
#define C2_B_SZ    (128 * C2_STRIDE)
#define C2_OFF_AHI 512
#define C2_OFF_ALO (C2_OFF_AHI + C2_A_SZ)
#define C2_OFF_BHI (C2_OFF_ALO + C2_A_SZ)
#define C2_OFF_BLO (C2_OFF_BHI + C2_B_SZ)
#define C2_SMEM    (C2_OFF_BLO + C2_B_SZ)

__global__ __launch_bounds__(256, 1)
void conv2_mma_kernel(const float* __restrict__ in, const float* __restrict__ w,
                      const float* __restrict__ bias, float* __restrict__ out)
{
    extern __shared__ __align__(16) char smem[];
    float* sbias = (float*)smem;
    char* Ahi = smem + C2_OFF_AHI;
    char* Alo = smem + C2_OFF_ALO;
    char* Bhi = smem + C2_OFF_BHI;
    char* Blo = smem + C2_OFF_BLO;

    const int tid = threadIdx.x;
    const int nb = blockIdx.x * 2;

    if (tid < 64) sbias[tid] = bias[tid];

    for (int idx = tid; idx < 4096; idx += 256) {
        const int im = idx >> 11;
        const int rc = idx & 2047;
        const int c  = rc >> 6;
        const int r  = rc & 63;
        const int gh = r >> 3, gw = r & 7;
        const float* ip = in + (size_t)((nb + im) * 32 + c) * 225;
        float4 v;
        {
            const int ih0 = 2 * gh, iw0 = 2 * gw;
            v.x = (ih0 < 15 && iw0     < 15) ? ip[ih0 * 15 + iw0]     : 0.0f;
            v.y = (ih0 < 15 && iw0 + 1 < 15) ? ip[ih0 * 15 + iw0 + 1] : 0.0f;
            v.z = (ih0 + 1 < 15 && iw0     < 15) ? ip[(ih0 + 1) * 15 + iw0]     : 0.0f;
            v.w = (ih0 + 1 < 15 && iw0 + 1 < 15) ? ip[(ih0 + 1) * 15 + iw0 + 1] : 0.0f;
        }
        float4 rem;
        const ull ph = pack_hi4(v, &rem);
        const ull pl = pack_lo4(rem);
        const int off = (im * 64 + r) * C2_STRIDE + c * 8;
        *(ull*)(Ahi + off) = ph;
        *(ull*)(Alo + off) = pl;
    }
    for (int i = tid; i < 1024; i += 256) {
        const int half = i >> 9;
        const int j = i & 511;
        const int off = (128 + (j >> 5)) * C2_STRIDE + (j & 31) * 8;
        *(ull*)((half ? Alo : Ahi) + off) = 0ull;
    }

    const int wid = tid >> 5, lane = tid & 31;
    const int g = lane >> 2, t = lane & 3;

    float acc[8][4];
    #pragma unroll
    for (int nt = 0; nt < 8; nt++)
        #pragma unroll
        for (int r = 0; r < 4; r++) acc[nt][r] = 0.0f;

    for (int dh = 0; dh < 2; dh++) {
        __syncthreads();
        for (int idx = tid; idx < 4096; idx += 256) {
            const int dw = idx >> 11;
            const int oc_c = idx & 2047;
            const int oc = oc_c >> 5;
            const int c = oc_c & 31;
            const float* wp = w + (size_t)(oc * 32 + c) * 16;
            float4 v;
            v.x = wp[(2 * dh) * 4 + 2 * dw];
            v.y = wp[(2 * dh) * 4 + 2 * dw + 1];
            v.z = wp[(2 * dh + 1) * 4 + 2 * dw];
            v.w = wp[(2 * dh + 1) * 4 + 2 * dw + 1];
            float4 rem;
            const ull ph = pack_hi4(v, &rem);
            const ull pl = pack_lo4(rem);
            const int off = (dw * 64 + oc) * C2_STRIDE + c * 8;
            *(ull*)(Bhi + off) = ph;
            *(ull*)(Blo + off) = pl;
        }
        __syncthreads();

        #pragma unroll
        for (int ql = 0; ql < 2; ql++) {
            const int roff = dh * 8 + ql;
            const char* Bq_hi = Bhi + ql * 64 * C2_STRIDE;
            const char* Bq_lo = Blo + ql * 64 * C2_STRIDE;
            const int arow = (wid * 16 + roff + g) * C2_STRIDE;

            #pragma unroll
            for (int ks = 0; ks < 8; ks++) {
                const int co = ks * 32 + t * 4;
                u32 ahi[4], alo[4], bhi[8][2], blo[8][2];
                const int rb = arow + co;
                ahi[0] = *(const u32*)(Ahi + rb);
                ahi[1] = *(const u32*)(Ahi + rb + 8 * C2_STRIDE);
                ahi[2] = *(const u32*)(Ahi + rb + 16);
                ahi[3] = *(const u32*)(Ahi + rb + 8 * C2_STRIDE + 16);
                alo[0] = *(const u32*)(Alo + rb);
                alo[1] = *(const u32*)(Alo + rb + 8 * C2_STRIDE);
                alo[2] = *(const u32*)(Alo + rb + 16);
                alo[3] = *(const u32*)(Alo + rb + 8 * C2_STRIDE + 16);
                #pragma unroll
                for (int nt = 0; nt < 8; nt++) {
                    const int bo = (nt * 8 + g) * C2_STRIDE + co;
                    bhi[nt][0] = *(const u32*)(Bq_hi + bo);
                    bhi[nt][1] = *(const u32*)(Bq_hi + bo + 16);
                    blo[nt][0] = *(const u32*)(Bq_lo + bo);
                    blo[nt][1] = *(const u32*)(Bq_lo + bo + 16);
                }
                #pragma unroll
                for (int nt = 0; nt < 8; nt++) {
                    mma16816(acc[nt], ahi, bhi[nt]);
                    mma16816(acc[nt], alo, bhi[nt]);
                    mma16816(acc[nt], ahi, blo[nt]);
                }
            }
        }
    }

    #pragma unroll
    for (int half = 0; half < 2; half++) {
        const int r = wid * 16 + g + half * 8;
        const int im = r >> 6;
        const int rl = r & 63;
        const int oh = rl >> 3, ow = rl & 7;
        if (oh < 6 && ow < 6) {
            float* ob = out + (size_t)(nb + im) * 2304 + oh * 6 + ow;
            #pragma unroll
            for (int nt = 0; nt < 8; nt++) {
                const int oc = nt * 8 + 2 * t;
                float v0 = acc[nt][half * 2]     + sbias[oc];
                float v1 = acc[nt][half * 2 + 1] + sbias[oc + 1];
                ob[oc * 36]       = v0 > 0.0f ? v0 : 0.0f;
                ob[(oc + 1) * 36] = v1 > 0.0f ? v1 : 0.0f;
            }
        }
    }
}

// ===========================================================================
// conv3 (scalar, R2): in (n,64,6,6) -> relu -> flatten (n, 1024), k=3 s=1
// ===========================================================================
__global__ __launch_bounds__(128, 2)
void conv3_kernel(const float* __restrict__ in, const float* __restrict__ w,
                  const float* __restrict__ bias, float* __restrict__ out)
{
    extern __shared__ float sm[];
    float* img = sm;
    float* wk  = sm + 9216;

    const int tid = threadIdx.x;
    const int nbase = (blockIdx.x >> 1) * 4;
    const int oc0base = (blockIdx.x & 1) * 32;

    const float4* ip = (const float4*)(in + (size_t)nbase * 2304);
    for (int i = tid; i < 2304; i += 128) ((float4*)img)[i] = ip[i];
    for (int e = tid; e < 18432; e += 128) {
        int ocl = e / 576, rr = e - ocl * 576;
        wk[ocl * 577 + rr] = w[(oc0base + ocl) * 576 + rr];
    }
    __syncthreads();

    const int im = tid >> 5;
    const int r  = tid & 31;
    const int ocg = r & 7, oh = r >> 3;
    const int oc0 = ocg * 4;

    float acc[4][4];
    #pragma unroll
    for (int i = 0; i < 4; i++)
        #pragma unroll
        for (int j = 0; j < 4; j++) acc[i][j] = 0.0f;

    const float* ibase = img + im * 2304 + oh * 6;
    for (int ic = 0; ic < 64; ic++) {
        const float* ib = ibase + ic * 36;
        const float* wb = wk + ic * 9;
        #pragma unroll
        for (int kh = 0; kh < 3; kh++) {
            #pragma unroll
            for (int kw = 0; kw < 3; kw++) {
                const float x0 = ib[kh * 6 + kw];
                const float x1 = ib[kh * 6 + kw + 1];
                const float x2 = ib[kh * 6 + kw + 2];
                const float x3 = ib[kh * 6 + kw + 3];
                #pragma unroll
                for (int i = 0; i < 4; i++) {
                    const float wv = wb[(oc0 + i) * 577 + kh * 3 + kw];
                    acc[i][0] += wv * x0;
                    acc[i][1] += wv * x1;
                    acc[i][2] += wv * x2;
                    acc[i][3] += wv * x3;
                }
            }
        }
    }
    const int n = nbase + im;
    #pragma unroll
    for (int i = 0; i < 4; i++) {
        const int oc = oc0base + oc0 + i;
        const float bi = bias[oc];
        #pragma unroll
        for (int j = 0; j < 4; j++) {
            float v = acc[i][j] + bi;
            out[(size_t)n * 1024 + oc * 16 + oh * 4 + j] = v > 0.0f ? v : 0.0f;
        }
    }
}

// ===========================================================================
// GEMM (NT) via mma.sync on PRE-CONVERTED bf16 hi/lo inputs.
// CTA tile 128x64, 8 warps (4m x 2n), warp tile 32x32, BK=32.
// Inner loop: pure LDG.128 -> STS.128 -> HMMA (register prefetch of next chunk).
// OUTBF: epilogue emits bf16 hi/lo pairs (relu'd) instead of fp32.
// ===========================================================================
template <bool RELU, bool OUTBF>
__global__ __launch_bounds__(256, 2)
void gemm_hmma_pre(const __nv_bfloat16* __restrict__ Ah, const __nv_bfloat16* __restrict__ Al,
                   const __nv_bfloat16* __restrict__ Bh, const __nv_bfloat16* __restrict__ Bl,
                   const float* __restrict__ b1, const float* __restrict__ b2,
                   float* __restrict__ C,
                   __nv_bfloat16* __restrict__ Chi, __nv_bfloat16* __restrict__ Clo,
                   int K, int N)
{
    __shared__ __align__(16) char Ahi_s[128 * 80];
    __shared__ __align__(16) char Alo_s[128 * 80];
    __shared__ __align__(16) char Bhi_s[64 * 80];
    __shared__ __align__(16) char Blo_s[64 * 80];

    const int tid = threadIdx.x;
    const int m0 = blockIdx.y * 128;
    const int n0 = blockIdx.x * 64;
    const int wid = tid >> 5, lane = tid & 31;
    const int g = lane >> 2, t = lane & 3;
    const int wm = wid & 3;
    const int wn = wid >> 2;

    // per-thread load coords (ulonglong2 = 8 bf16 = 16B)
    const int arow0 = tid >> 2;            // A part 0: rows 0..63
    const int arow1 = (tid >> 2) + 64;     // A part 1: rows 64..127
    const int brow  = tid >> 2;            // B: rows 0..63
    const int cgrp  = (tid & 3) * 8;       // element offset within 32-col chunk

    float acc[2][4][4];
    #pragma unroll
    for (int ms = 0; ms < 2; ms++)
        #pragma unroll
        for (int nt = 0; nt < 4; nt++)
            #pragma unroll
            for (int r = 0; r < 4; r++) acc[ms][nt][r] = 0.0f;

    ulonglong2 pah0, pah1, pal0, pal1, pbh, pbl;
    // prefetch chunk 0
    pah0 = *(const ulonglong2*)(Ah + (size_t)(m0 + arow0) * K + cgrp);
    pah1 = *(const ulonglong2*)(Ah + (size_t)(m0 + arow1) * K + cgrp);
    pal0 = *(const ulonglong2*)(Al + (size_t)(m0 + arow0) * K + cgrp);
    pal1 = *(const ulonglong2*)(Al + (size_t)(m0 + arow1) * K + cgrp);
    pbh  = *(const ulonglong2*)(Bh + (size_t)(n0 + brow) * K + cgrp);
    pbl  = *(const ulonglong2*)(Bl + (size_t)(n0 + brow) * K + cgrp);

    for (int k0 = 0; k0 < K; k0 += 32) {
        *(ulonglong2*)(Ahi_s + arow0 * 80 + cgrp * 2) = pah0;
        *(ulonglong2*)(Ahi_s + arow1 * 80 + cgrp * 2) = pah1;
        *(ulonglong2*)(Alo_s + arow0 * 80 + cgrp * 2) = pal0;
        *(ulonglong2*)(Alo_s + arow1 * 80 + cgrp * 2) = pal1;
        *(ulonglong2*)(Bhi_s + brow * 80 + cgrp * 2) = pbh;
        *(ulonglong2*)(Blo_s + brow * 80 + cgrp * 2) = pbl;
        __syncthreads();

        if (k0 + 32 < K) {
            const int kn = k0 + 32;
            pah0 = *(const ulonglong2*)(Ah + (size_t)(m0 + arow0) * K + kn + cgrp);
            pah1 = *(const ulonglong2*)(Ah + (size_t)(m0 + arow1) * K + kn + cgrp);
            pal0 = *(const ulonglong2*)(Al + (size_t)(m0 + arow0) * K + kn + cgrp);
            pal1 = *(const ulonglong2*)(Al + (size_t)(m0 + arow1) * K + kn + cgrp);
            pbh  = *(const ulonglong2*)(Bh + (size_t)(n0 + brow) * K + kn + cgrp);
            pbl  = *(const ulonglong2*)(Bl + (size_t)(n0 + brow) * K + kn + cgrp);
        }

        #pragma unroll
        for (int ks = 0; ks < 2; ks++) {
            const int co = ks * 32 + t * 4;
            u32 ahi[2][4], alo[2][4], bhi[4][2], blo[4][2];
            #pragma unroll
            for (int ms = 0; ms < 2; ms++) {
                const int rb = (wm * 32 + ms * 16 + g) * 80 + co;
                ahi[ms][0] = *(const u32*)(Ahi_s + rb);
                ahi[ms][1] = *(const u32*)(Ahi_s + rb + 8 * 80);
                ahi[ms][2] = *(const u32*)(Ahi_s + rb + 16);
                ahi[ms][3] = *(const u32*)(Ahi_s + rb + 8 * 80 + 16);
                alo[ms][0] = *(const u32*)(Alo_s + rb);
                alo[ms][1] = *(const u32*)(Alo_s + rb + 8 * 80);
                alo[ms][2] = *(const u32*)(Alo_s + rb + 16);
                alo[ms][3] = *(const u32*)(Alo_s + rb + 8 * 80 + 16);
            }
            #pragma unroll
            for (int nt = 0; nt < 4; nt++) {
                const int bo = (wn * 32 + nt * 8 + g) * 80 + co;
                bhi[nt][0] = *(const u32*)(Bhi_s + bo);
                bhi[nt][1] = *(const u32*)(Bhi_s + bo + 16);
                blo[nt][0] = *(const u32*)(Blo_s + bo);
                blo[nt][1] = *(const u32*)(Blo_s + bo + 16);
            }
            #pragma unroll
            for (int ms = 0; ms < 2; ms++)
                #pragma unroll
                for (int nt = 0; nt < 4; nt++) {
                    mma16816(acc[ms][nt], ahi[ms], bhi[nt]);
                    mma16816(acc[ms][nt], alo[ms], bhi[nt]);
                    mma16816(acc[ms][nt], ahi[ms], blo[nt]);
                }
        }
        __syncthreads();
    }

    #pragma unroll
    for (int ms = 0; ms < 2; ms++) {
        #pragma unroll
        for (int half = 0; half < 2; half++) {
            const int row = m0 + wm * 32 + ms * 16 + g + half * 8;
            #pragma unroll
            for (int nt = 0; nt < 4; nt++) {
                const int col = n0 + wn * 32 + nt * 8 + 2 * t;
                float bb0 = b1[col]     + (b2 ? b2[col]     : 0.0f);
                float bb1 = b1[col + 1] + (b2 ? b2[col + 1] : 0.0f);
                float v0 = acc[ms][nt][half * 2]     + bb0;
                float v1 = acc[ms][nt][half * 2 + 1] + bb1;
                if (RELU) { v0 = v0 > 0.0f ? v0 : 0.0f; v1 = v1 > 0.0f ? v1 : 0.0f; }
                if (OUTBF) {
                    __nv_bfloat16 h0, l0, h1, l1;
                    pack_hl(v0, &h0, &l0);
                    pack_hl(v1, &h1, &l1);
                    __nv_bfloat162 ph; ph.x = h0; ph.y = h1;
                    __nv_bfloat162 pl; pl.x = l0; pl.y = l1;
                    *(__nv_bfloat162*)(Chi + (size_t)row * N + col) = ph;
                    *(__nv_bfloat162*)(Clo + (size_t)row * N + col) = pl;
                } else {
                    C[(size_t)row * N + col]     = v0;
                    C[(size_t)row * N + col + 1] = v1;
                }
            }
        }
    }
}

// ===========================================================================
// LSTM (R2, known-good): 64 blocks x 256 threads
// ===========================================================================
__global__ __launch_bounds__(256, 1)
void lstm_kernel(const float* __restrict__ gx, const float* __restrict__ whh,
                 const int* __restrict__ done,
                 const float* __restrict__ h0, const float* __restrict__ c0,
                 float* __restrict__ out)
{
    extern __shared__ float sm[];
    float* ws     = sm;
    float* h_s    = sm + 16 * 264;
    float* gate_s = h_s + 32 * 264;
    float* c_s    = gate_s + 512;

    const int tid = threadIdx.x;
    const int j0 = blockIdx.x * 4;

    #pragma unroll
    for (int l = 0; l < 4; l++) {
        const int id = tid + l * 256;
        const int r = id >> 6;
        const int c4 = (id & 63) * 4;
        const int g = r >> 2, jj = r & 3;
        *(float4*)(ws + r * 264 + c4) =
            *(const float4*)(whh + (size_t)(g * 256 + j0 + jj) * 256 + c4);
    }
    if (tid < 128) {
        const int b = tid >> 2, jj = tid & 3;
        c_s[tid] = c0[b * 256 + j0 + jj];
    }
    unsigned bar_gen = 0;
    if (tid == 0) bar_gen = *((volatile unsigned*)&g_gen);
    __syncthreads();

    const int u = tid & 7;
    const int b = tid >> 3;
    const int jj = u & 3, gh = u >> 2;
    const float* w0 = ws + ((2 * gh) * 4 + jj) * 264;
    const float* w1 = ws + ((2 * gh + 1) * 4 + jj) * 264;
    const float* hb = h_s + b * 264;

    for (int t = 0; t < 64; t++) {
        const float* hsrc = (t == 0) ? h0 : g_hbuf[(t - 1) & 1];
        const int* dn = done + t * 32;
        #pragma unroll
        for (int l = 0; l < 8; l++) {
            const int f = tid + l * 256;
            const int bb = f >> 6;
            const int kc = (f & 63) * 4;
            const float m = 1.0f - (float)dn[bb];
            float4 v = *(const float4*)(hsrc + bb * 256 + kc);
            v.x *= m; v.y *= m; v.z *= m; v.w *= m;
            *(float4*)(h_s + bb * 264 + kc) = v;
        }
        __syncthreads();

        float s00 = 0, s01 = 0, s02 = 0, s03 = 0;
        float s10 = 0, s11 = 0, s12 = 0, s13 = 0;
        #pragma unroll 8
        for (int k = 0; k < 256; k += 4) {
            const float4 h4 = *(const float4*)(hb + k);
            const float4 wa = *(const float4*)(w0 + k);
            const float4 wb4 = *(const float4*)(w1 + k);
            s00 += h4.x * wa.x;  s01 += h4.y * wa.y;
            s02 += h4.z * wa.z;  s03 += h4.w * wa.w;
            s10 += h4.x * wb4.x; s11 += h4.y * wb4.y;
            s12 += h4.z * wb4.z; s13 += h4.w * wb4.w;
        }
        const int row = t * 32 + b;
        const float g0v = ((s00 + s01) + (s02 + s03)) +
                          gx[(size_t)row * 1024 + (2 * gh) * 256 + j0 + jj];
        const float g1v = ((s10 + s11) + (s12 + s13)) +
                          gx[(size_t)row * 1024 + (2 * gh + 1) * 256 + j0 + jj];
        gate_s[(b * 4 + jj) * 4 + 2 * gh] = g0v;
        gate_s[(b * 4 + jj) * 4 + 2 * gh + 1] = g1v;
        __syncthreads();

        if (tid < 128) {
            const int bb = tid >> 2, j2 = tid & 3;
            const float* gp = gate_s + tid * 4;
            const float gi = gp[0], gf = gp[1], gg = gp[2], go = gp[3];
            const float m = 1.0f - (float)dn[bb];
            const float cold = c_s[tid] * m;
            const float si = 1.0f / (1.0f + __expf(-gi));
            const float sf = 1.0f / (1.0f + __expf(-gf));
            const float so = 1.0f / (1.0f + __expf(-go));
            const float cn = sf * cold + si * tanhf(gg);
            const float h = so * tanhf(cn);
            c_s[tid] = cn;
            const int j = j0 + j2;
            g_hbuf[t & 1][bb * 256 + j] = h;
            out[(size_t)(t * 32 + bb) * 256 + j] = h;
        }
        __threadfence();
        __syncthreads();

        if (t < 63) {
            if (tid == 0) {
                const unsigned prev = atomicAdd(&g_count, 1);
                if (prev == gridDim.x - 1) {
                    g_count = 0;
                    __threadfence();
                    atomicAdd(&g_gen, 1);
                } else {
                    while (*((volatile unsigned*)&g_gen) == bar_gen) { }
                }
                bar_gen++;
                __threadfence();
            }
            __syncthreads();
        }
    }
}

// ===========================================================================
extern "C" void kernel_launch(void* const* d_in, const int* in_sizes, int n_in,
                              void* d_out, int out_size)
{
    const float* x    = (const float*)d_in[0];
    const int*   done = (const int*)d_in[1];
    const float* w1   = (const float*)d_in[2];
    const float* b1   = (const float*)d_in[3];
    const float* w2   = (const float*)d_in[4];
    const float* b2   = (const float*)d_in[5];
    const float* w3   = (const float*)d_in[6];
    const float* b3   = (const float*)d_in[7];
    const float* fcw  = (const float*)d_in[8];
    const float* fcb  = (const float*)d_in[9];
    const float* wih  = (const float*)d_in[10];
    const float* whh  = (const float*)d_in[11];
    const float* bih  = (const float*)d_in[12];
    const float* bhh  = (const float*)d_in[13];
    const float* h0   = (const float*)d_in[14];
    const float* c0   = (const float*)d_in[15];
    float* out = (float*)d_out;

    float *buf1, *buf2, *buf3, *gatesx;
    __nv_bfloat16 *b3h, *b3l, *fcwh, *fcwl, *wihh, *wihl, *fh, *fl;
    cudaGetSymbolAddress((void**)&buf1,   g_buf1);
    cudaGetSymbolAddress((void**)&buf2,   g_buf2);
    cudaGetSymbolAddress((void**)&buf3,   g_buf3);
    cudaGetSymbolAddress((void**)&gatesx, g_gatesx);
    cudaGetSymbolAddress((void**)&b3h,  g_b3h);
    cudaGetSymbolAddress((void**)&b3l,  g_b3l);
    cudaGetSymbolAddress((void**)&fcwh, g_fcwh);
    cudaGetSymbolAddress((void**)&fcwl, g_fcwl);
    cudaGetSymbolAddress((void**)&wihh, g_wihh);
    cudaGetSymbolAddress((void**)&wihl, g_wihl);
    cudaGetSymbolAddress((void**)&fh,   g_fh);
    cudaGetSymbolAddress((void**)&fl,   g_fl);

    cudaFuncSetAttribute(conv1_mma_kernel, cudaFuncAttributeMaxDynamicSharedMemorySize, C1_SMEM);
    cudaFuncSetAttribute(conv2_mma_kernel, cudaFuncAttributeMaxDynamicSharedMemorySize, C2_SMEM);
    cudaFuncSetAttribute(conv3_kernel, cudaFuncAttributeMaxDynamicSharedMemorySize, SMEM3);
    cudaFuncSetAttribute(lstm_kernel,  cudaFuncAttributeMaxDynamicSharedMemorySize, SMEML);

    conv1_mma_kernel<<<2048, 256, C1_SMEM>>>(x, w1, b1, buf1);
    // weight conversions (independent of conv chain; issued here, overlap-free but tiny)
    cvt_hilo<<<512, 256>>>((const float4*)fcw, (ull*)fcwh, (ull*)fcwl, 131072);
    cvt_hilo<<<512, 256>>>((const float4*)wih, (ull*)wihh, (ull*)wihl, 131072);
    conv2_mma_kernel<<<1024, 256, C2_SMEM>>>(buf1, w2, b2, buf2);
    conv3_kernel<<<1024, 128, SMEM3>>>(buf2, w3, b3, buf3);
    cvt_hilo<<<2048, 256>>>((const float4*)buf3, (ull*)b3h, (ull*)b3l, 524288);
    gemm_hmma_pre<true, true><<<dim3(8, 16), 256>>>(
        b3h, b3l, fcwh, fcwl, fcb, nullptr, nullptr, fh, fl, 1024, 512);
    gemm_hmma_pre<false, false><<<dim3(16, 16), 256>>>(
        fh, fl, wihh, wihl, bih, bhh, gatesx, nullptr, nullptr, 512, 1024);
    lstm_kernel<<<64, 256, SMEML>>>(gatesx, whh, done, h0, c0, out);
}

// round 11
// speedup vs baseline: 1.0960x; 1.0476x over previous
#include <cuda_runtime.h>
#include <cuda_bf16.h>
#include <math.h>
#include <cstdint>

typedef unsigned long long ull;
typedef uint32_t u32;

// ===========================================================================
// Static scratch
// ===========================================================================
__device__ float g_buf2[2048 * 64 * 6 * 6];
__device__ float g_buf3[2048 * 1024];
__device__ float g_gatesx[2048 * 1024];
__device__ float g_hbuf[2][32 * 256];
__device__ unsigned g_count;
__device__ unsigned g_gen;
// pre-converted bf16 hi/lo operands
__device__ __nv_bfloat16 g_c2a_h[2048 * 64 * 128], g_c2a_l[2048 * 64 * 128]; // conv1 out, phase layout
__device__ ull g_c1w_h[2048], g_c1w_l[2048];       // conv1 weights, quadrant layout
__device__ ull g_c2w_h[8192], g_c2w_l[8192];       // conv2 weights, phase layout
__device__ __nv_bfloat16 g_b3h[2048 * 1024], g_b3l[2048 * 1024];
__device__ __nv_bfloat16 g_fcwh[512 * 1024], g_fcwl[512 * 1024];
__device__ __nv_bfloat16 g_wihh[1024 * 512], g_wihl[1024 * 512];
__device__ __nv_bfloat16 g_fh[2048 * 512],  g_fl[2048 * 512];

#define SMEM3 ((9216 + 32 * 577) * 4)
#define SMEML ((16 * 264 + 32 * 264 + 512 + 128) * 4)

// ===========================================================================
// bf16 helpers
// ===========================================================================
__device__ __forceinline__ void mma16816(float* d, const u32* a, const u32* b) {
    asm volatile(
        "mma.sync.aligned.m16n8k16.row.col.f32.bf16.bf16.f32 "
        "{%0,%1,%2,%3}, {%4,%5,%6,%7}, {%8,%9}, {%0,%1,%2,%3};"
        : "+f"(d[0]), "+f"(d[1]), "+f"(d[2]), "+f"(d[3])
        : "r"(a[0]), "r"(a[1]), "r"(a[2]), "r"(a[3]), "r"(b[0]), "r"(b[1]));
}

__device__ __forceinline__ ull pack_hi4(float4 v, float4* rem) {
    __nv_bfloat16 h0 = __float2bfloat16_rn(v.x);
    __nv_bfloat16 h1 = __float2bfloat16_rn(v.y);
    __nv_bfloat16 h2 = __float2bfloat16_rn(v.z);
    __nv_bfloat16 h3 = __float2bfloat16_rn(v.w);
    rem->x = v.x - __bfloat162float(h0);
    rem->y = v.y - __bfloat162float(h1);
    rem->z = v.z - __bfloat162float(h2);
    rem->w = v.w - __bfloat162float(h3);
    return (ull)__bfloat16_as_ushort(h0) |
           ((ull)__bfloat16_as_ushort(h1) << 16) |
           ((ull)__bfloat16_as_ushort(h2) << 32) |
           ((ull)__bfloat16_as_ushort(h3) << 48);
}
__device__ __forceinline__ ull pack_lo4(float4 v) {
    return (ull)__bfloat16_as_ushort(__float2bfloat16_rn(v.x)) |
           ((ull)__bfloat16_as_ushort(__float2bfloat16_rn(v.y)) << 16) |
           ((ull)__bfloat16_as_ushort(__float2bfloat16_rn(v.z)) << 32) |
           ((ull)__bfloat16_as_ushort(__float2bfloat16_rn(v.w)) << 48);
}
__device__ __forceinline__ void pack_hl(float v, __nv_bfloat16* hi, __nv_bfloat16* lo) {
    __nv_bfloat16 h = __float2bfloat16_rn(v);
    *hi = h;
    *lo = __float2bfloat16_rn(v - __bfloat162float(h));
}

// ===========================================================================
// conversion kernels (run once per launch, tiny)
// ===========================================================================
__global__ __launch_bounds__(256)
void cvt_hilo(const float4* __restrict__ src, ull* __restrict__ hi,
              ull* __restrict__ lo, int n4)
{
    const int i = blockIdx.x * 256 + threadIdx.x;
    if (i < n4) {
        float4 v = src[i];
        float4 rem;
        const ull ph = pack_hi4(v, &rem);
        hi[i] = ph;
        lo[i] = pack_lo4(rem);
    }
}

__global__ __launch_bounds__(256)
void cvt_c1w(const float* __restrict__ w, ull* __restrict__ hi, ull* __restrict__ lo)
{
    const int idx = blockIdx.x * 256 + threadIdx.x;   // 2048
    if (idx < 2048) {
        const int q  = idx >> 9;
        const int oc = (idx >> 4) & 31;
        const int cs = idx & 15;
        const int c = cs >> 2, s = cs & 3;
        const int dh = q >> 1, dw = q & 1;
        float4 v = *(const float4*)(w + (size_t)((oc * 4 + c) * 8 + 4 * dh + s) * 8 + 4 * dw);
        float4 rem;
        hi[idx] = pack_hi4(v, &rem);
        lo[idx] = pack_lo4(rem);
    }
}

__global__ __launch_bounds__(256)
void cvt_c2w(const float* __restrict__ w, ull* __restrict__ hi, ull* __restrict__ lo)
{
    const int idx = blockIdx.x * 256 + threadIdx.x;   // 8192
    if (idx < 8192) {
        const int dh = idx >> 12;
        const int dw = (idx >> 11) & 1;
        const int oc = (idx >> 5) & 63;
        const int c  = idx & 31;
        const float* wp = w + (size_t)(oc * 32 + c) * 16;
        float4 v;
        v.x = wp[(2 * dh) * 4 + 2 * dw];
        v.y = wp[(2 * dh) * 4 + 2 * dw + 1];
        v.z = wp[(2 * dh + 1) * 4 + 2 * dw];
        v.w = wp[(2 * dh + 1) * 4 + 2 * dw + 1];
        float4 rem;
        const int row = dh * 128 + dw * 64 + oc;
        hi[row * 32 + c] = pack_hi4(v, &rem);
        lo[row * 32 + c] = pack_lo4(rem);
    }
}

// ===========================================================================
// conv1 via mma.sync (bf16x3): pre-converted weights; output written directly
// into conv2's A phase layout (bf16 hi/lo), boundary entries zero.
// ===========================================================================
#define A_STRIDE 144
#define A_BYTES  (273 * A_STRIDE)
#define BQ_BYTES (32 * A_STRIDE)
#define OFF_AHI  128
#define OFF_ALO  (OFF_AHI + A_BYTES)
#define OFF_BHI  (OFF_ALO + A_BYTES)
#define OFF_BLO  (OFF_BHI + 4 * BQ_BYTES)
#define C1_SMEM  (OFF_BLO + 4 * BQ_BYTES)

__global__ __launch_bounds__(256, 1)
void conv1_mma_kernel(const float* __restrict__ x,
                      const ull* __restrict__ c1wh, const ull* __restrict__ c1wl,
                      const float* __restrict__ bias,
                      __nv_bfloat16* __restrict__ oAh, __nv_bfloat16* __restrict__ oAl)
{
    extern __shared__ __align__(16) char smem[];
    float* sbias = (float*)smem;
    char* Ahi = smem + OFF_AHI;
    char* Alo = smem + OFF_ALO;
    char* Bhi = smem + OFF_BHI;
    char* Blo = smem + OFF_BLO;

    const int tid = threadIdx.x;
    const int n = blockIdx.x;
    const float inv255 = 1.0f / 255.0f;

    if (tid < 32) sbias[tid] = bias[tid];

    for (int idx = tid; idx < 4096; idx += 256) {
        const int row = idx >> 4;
        const int cs  = idx & 15;
        const int c = cs >> 2, s = cs & 3;
        const int gh = row >> 4, gw = row & 15;
        float4 v = *(const float4*)(x + (size_t)((n * 4 + c) * 64 + 4 * gh + s) * 64 + 4 * gw);
        v.x *= inv255; v.y *= inv255; v.z *= inv255; v.w *= inv255;
        float4 rem;
        const ull ph = pack_hi4(v, &rem);
        const ull pl = pack_lo4(rem);
        const int off = row * A_STRIDE + cs * 8;
        *(ull*)(Ahi + off) = ph;
        *(ull*)(Alo + off) = pl;
    }
    for (int i = tid; i < 612; i += 256) {
        const int half = i / 306;
        const int off = 256 * A_STRIDE + (i - half * 306) * 8;
        *(ull*)((half ? Alo : Ahi) + off) = 0ull;
    }
    // B from pre-converted weights (pure copy)
    for (int i = tid; i < 2048; i += 256) {
        const int q = i >> 9, oc = (i >> 4) & 31, cs = i & 15;
        const int off = q * BQ_BYTES + oc * A_STRIDE + cs * 8;
        *(ull*)(Bhi + off) = c1wh[i];
        *(ull*)(Blo + off) = c1wl[i];
    }
    __syncthreads();

    const int wid = tid >> 5, lane = tid & 31;
    const int g = lane >> 2, t = lane & 3;

    float acc[2][4][4];
    #pragma unroll
    for (int m = 0; m < 2; m++)
        #pragma unroll
        for (int nt = 0; nt < 4; nt++)
            #pragma unroll
            for (int r = 0; r < 4; r++) acc[m][nt][r] = 0.0f;

    const int mt0 = wid, mt1 = wid + 8;

    #pragma unroll
    for (int q = 0; q < 4; q++) {
        const int r0 = (q >> 1) * 16 + (q & 1);
        const char* Bq_hi = Bhi + q * BQ_BYTES;
        const char* Bq_lo = Blo + q * BQ_BYTES;
        const int arow0 = (mt0 * 16 + r0 + g) * A_STRIDE;
        const int arow1 = (mt1 * 16 + r0 + g) * A_STRIDE;

        #pragma unroll
        for (int ks = 0; ks < 4; ks++) {
            const int co = ks * 32 + t * 4;
            u32 ahi[2][4], alo[2][4], bhi[4][2], blo[4][2];
            #pragma unroll
            for (int m = 0; m < 2; m++) {
                const int rb = (m ? arow1 : arow0) + co;
                ahi[m][0] = *(const u32*)(Ahi + rb);
                ahi[m][1] = *(const u32*)(Ahi + rb + 8 * A_STRIDE);
                ahi[m][2] = *(const u32*)(Ahi + rb + 16);
                ahi[m][3] = *(const u32*)(Ahi + rb + 8 * A_STRIDE + 16);
                alo[m][0] = *(const u32*)(Alo + rb);
                alo[m][1] = *(const u32*)(Alo + rb + 8 * A_STRIDE);
                alo[m][2] = *(const u32*)(Alo + rb + 16);
                alo[m][3] = *(const u32*)(Alo + rb + 8 * A_STRIDE + 16);
            }
            #pragma unroll
            for (int nt = 0; nt < 4; nt++) {
                const int bo = (nt * 8 + g) * A_STRIDE + co;
                bhi[nt][0] = *(const u32*)(Bq_hi + bo);
                bhi[nt][1] = *(const u32*)(Bq_hi + bo + 16);
                blo[nt][0] = *(const u32*)(Bq_lo + bo);
                blo[nt][1] = *(const u32*)(Bq_lo + bo + 16);
            }
            #pragma unroll
            for (int m = 0; m < 2; m++)
                #pragma unroll
                for (int nt = 0; nt < 4; nt++) {
                    mma16816(acc[m][nt], ahi[m], bhi[nt]);
                    mma16816(acc[m][nt], alo[m], bhi[nt]);
                    mma16816(acc[m][nt], ahi[m], blo[nt]);
                }
        }
    }

    // epilogue -> conv2 phase layout: [n][gh*8+gw][oc*4 + (oh&1)*2 + (ow&1)]
    __nv_bfloat16* oh_b = oAh + (size_t)n * 8192;
    __nv_bfloat16* ol_b = oAl + (size_t)n * 8192;
    #pragma unroll
    for (int m = 0; m < 2; m++) {
        const int mt = m ? mt1 : mt0;
        #pragma unroll
        for (int half = 0; half < 2; half++) {
            const int r = mt * 16 + g + half * 8;
            const int oh = r >> 4, ow = r & 15;
            const bool valid = (oh < 15) && (ow < 15);
            const int prow = (oh >> 1) * 8 + (ow >> 1);
            const int sp = (oh & 1) * 2 + (ow & 1);
            const int base = prow * 128 + sp;
            #pragma unroll
            for (int nt = 0; nt < 4; nt++) {
                const int c0 = nt * 8 + 2 * t;
                float v0 = 0.0f, v1 = 0.0f;
                if (valid) {
                    v0 = acc[m][nt][half * 2]     + sbias[c0];
                    v1 = acc[m][nt][half * 2 + 1] + sbias[c0 + 1];
                    v0 = v0 > 0.0f ? v0 : 0.0f;
                    v1 = v1 > 0.0f ? v1 : 0.0f;
                }
                __nv_bfloat16 h, l;
                pack_hl(v0, &h, &l);
                oh_b[base + c0 * 4] = h;
                ol_b[base + c0 * 4] = l;
                pack_hl(v1, &h, &l);
                oh_b[base + (c0 + 1) * 4] = h;
                ol_b[base + (c0 + 1) * 4] = l;
            }
        }
    }
}

// ===========================================================================
// conv2 via mma.sync (bf16x3): pre-converted A (from conv1) and weights.
// Both dh phases resident in smem; single sync; pure-copy fills.
// ===========================================================================
#define C2_STRIDE  272
#define C2_A_SZ    (144 * C2_STRIDE)      // 39168
#define C2_B_SZ    (256 * C2_STRIDE)      // 69632
#define C2_OFF_AHI 512
#define C2_OFF_ALO (C2_OFF_AHI + C2_A_SZ)
#define C2_OFF_BHI (C2_OFF_ALO + C2_A_SZ)
#define C2_OFF_BLO (C2_OFF_BHI + C2_B_SZ)
#define C2_SMEM    (C2_OFF_BLO + C2_B_SZ)   // 218112

__global__ __launch_bounds__(256, 1)
void conv2_mma_kernel(const __nv_bfloat16* __restrict__ Agh, const __nv_bfloat16* __restrict__ Agl,
                      const ull* __restrict__ c2wh, const ull* __restrict__ c2wl,
                      const float* __restrict__ bias, float* __restrict__ out)
{
    extern __shared__ __align__(16) char smem[];
    float* sbias = (float*)smem;
    char* Ahi = smem + C2_OFF_AHI;
    char* Alo = smem + C2_OFF_ALO;
    char* Bhi = smem + C2_OFF_BHI;
    char* Blo = smem + C2_OFF_BLO;

    const int tid = threadIdx.x;
    const int nb = blockIdx.x * 2;

    if (tid < 64) sbias[tid] = bias[tid];

    // A: 128 rows x 128 bf16 (pure copy), rows contiguous across the 2 images
    {
        const ulonglong2* sh = (const ulonglong2*)(Agh + (size_t)nb * 8192);
        const ulonglong2* sl = (const ulonglong2*)(Agl + (size_t)nb * 8192);
        for (int idx = tid; idx < 2048; idx += 256) {
            const int row = idx >> 4, ch = idx & 15;
            *(ulonglong2*)(Ahi + row * C2_STRIDE + ch * 16) = sh[idx];
            *(ulonglong2*)(Alo + row * C2_STRIDE + ch * 16) = sl[idx];
        }
    }
    // zero pad rows 128..143 (first 256B of each row)
    for (int i = tid; i < 512; i += 256) {
        const int half = i >> 8;
        const int j = i & 255;
        const int off = (128 + (j >> 4)) * C2_STRIDE + (j & 15) * 16;
        ulonglong2 z; z.x = 0; z.y = 0;
        *(ulonglong2*)((half ? Alo : Ahi) + off) = z;
    }
    // B: 256 rows (both phases) x 128 bf16 (pure copy)
    {
        const ulonglong2* sh = (const ulonglong2*)c2wh;
        const ulonglong2* sl = (const ulonglong2*)c2wl;
        for (int idx = tid; idx < 4096; idx += 256) {
            const int row = idx >> 4, ch = idx & 15;
            *(ulonglong2*)(Bhi + row * C2_STRIDE + ch * 16) = sh[idx];
            *(ulonglong2*)(Blo + row * C2_STRIDE + ch * 16) = sl[idx];
        }
    }
    __syncthreads();

    const int wid = tid >> 5, lane = tid & 31;
    const int g = lane >> 2, t = lane & 3;

    float acc[8][4];
    #pragma unroll
    for (int nt = 0; nt < 8; nt++)
        #pragma unroll
        for (int r = 0; r < 4; r++) acc[nt][r] = 0.0f;

    #pragma unroll
    for (int q = 0; q < 4; q++) {
        const int dh = q >> 1, dw = q & 1;
        const int roff = dh * 8 + dw;
        const char* Bq_hi = Bhi + (dh * 128 + dw * 64) * C2_STRIDE;
        const char* Bq_lo = Blo + (dh * 128 + dw * 64) * C2_STRIDE;
        const int arow = (wid * 16 + roff + g) * C2_STRIDE;

        #pragma unroll
        for (int ks = 0; ks < 8; ks++) {
            const int co = ks * 32 + t * 4;
            u32 ahi[4], alo[4], bhi[8][2], blo[8][2];
            const int rb = arow + co;
            ahi[0] = *(const u32*)(Ahi + rb);
            ahi[1] = *(const u32*)(Ahi + rb + 8 * C2_STRIDE);
            ahi[2] = *(const u32*)(Ahi + rb + 16);
            ahi[3] = *(const u32*)(Ahi + rb + 8 * C2_STRIDE + 16);
            alo[0] = *(const u32*)(Alo + rb);
            alo[1] = *(const u32*)(Alo + rb + 8 * C2_STRIDE);
            alo[2] = *(const u32*)(Alo + rb + 16);
            alo[3] = *(const u32*)(Alo + rb + 8 * C2_STRIDE + 16);
            #pragma unroll
            for (int nt = 0; nt < 8; nt++) {
                const int bo = (nt * 8 + g) * C2_STRIDE + co;
                bhi[nt][0] = *(const u32*)(Bq_hi + bo);
                bhi[nt][1] = *(const u32*)(Bq_hi + bo + 16);
                blo[nt][0] = *(const u32*)(Bq_lo + bo);
                blo[nt][1] = *(const u32*)(Bq_lo + bo + 16);
            }
            #pragma unroll
            for (int nt = 0; nt < 8; nt++) {
                mma16816(acc[nt], ahi, bhi[nt]);
                mma16816(acc[nt], alo, bhi[nt]);
                mma16816(acc[nt], ahi, blo[nt]);
            }
        }
    }

    #pragma unroll
    for (int half = 0; half < 2; half++) {
        const int r = wid * 16 + g + half * 8;
        const int im = r >> 6;
        const int rl = r & 63;
        const int oh = rl >> 3, ow = rl & 7;
        if (oh < 6 && ow < 6) {
            float* ob = out + (size_t)(nb + im) * 2304 + oh * 6 + ow;
            #pragma unroll
            for (int nt = 0; nt < 8; nt++) {
                const int oc = nt * 8 + 2 * t;
                float v0 = acc[nt][half * 2]     + sbias[oc];
                float v1 = acc[nt][half * 2 + 1] + sbias[oc + 1];
                ob[oc * 36]       = v0 > 0.0f ? v0 : 0.0f;
                ob[(oc + 1) * 36] = v1 > 0.0f ? v1 : 0.0f;
            }
        }
    }
}

// ===========================================================================
// conv3 (scalar, R2): in (n,64,6,6) -> relu -> flatten (n, 1024), k=3 s=1
// ===========================================================================
__global__ __launch_bounds__(128, 2)
void conv3_kernel(const float* __restrict__ in, const float* __restrict__ w,
                  const float* __restrict__ bias, float* __restrict__ out)
{
    extern __shared__ float sm[];
    float* img = sm;
    float* wk  = sm + 9216;

    const int tid = threadIdx.x;
    const int nbase = (blockIdx.x >> 1) * 4;
    const int oc0base = (blockIdx.x & 1) * 32;

    const float4* ip = (const float4*)(in + (size_t)nbase * 2304);
    for (int i = tid; i < 2304; i += 128) ((float4*)img)[i] = ip[i];
    for (int e = tid; e < 18432; e += 128) {
        int ocl = e / 576, rr = e - ocl * 576;
        wk[ocl * 577 + rr] = w[(oc0base + ocl) * 576 + rr];
    }
    __syncthreads();

    const int im = tid >> 5;
    const int r  = tid & 31;
    const int ocg = r & 7, oh = r >> 3;
    const int oc0 = ocg * 4;

    float acc[4][4];
    #pragma unroll
    for (int i = 0; i < 4; i++)
        #pragma unroll
        for (int j = 0; j < 4; j++) acc[i][j] = 0.0f;

    const float* ibase = img + im * 2304 + oh * 6;
    for (int ic = 0; ic < 64; ic++) {
        const float* ib = ibase + ic * 36;
        const float* wb = wk + ic * 9;
        #pragma unroll
        for (int kh = 0; kh < 3; kh++) {
            #pragma unroll
            for (int kw = 0; kw < 3; kw++) {
                const float x0 = ib[kh * 6 + kw];
                const float x1 = ib[kh * 6 + kw + 1];
                const float x2 = ib[kh * 6 + kw + 2];
                const float x3 = ib[kh * 6 + kw + 3];
                #pragma unroll
                for (int i = 0; i < 4; i++) {
                    const float wv = wb[(oc0 + i) * 577 + kh * 3 + kw];
                    acc[i][0] += wv * x0;
                    acc[i][1] += wv * x1;
                    acc[i][2] += wv * x2;
                    acc[i][3] += wv * x3;
                }
            }
        }
    }
    const int n = nbase + im;
    #pragma unroll
    for (int i = 0; i < 4; i++) {
        const int oc = oc0base + oc0 + i;
        const float bi = bias[oc];
        #pragma unroll
        for (int j = 0; j < 4; j++) {
            float v = acc[i][j] + bi;
            out[(size_t)n * 1024 + oc * 16 + oh * 4 + j] = v > 0.0f ? v : 0.0f;
        }
    }
}

// ===========================================================================
// GEMM (NT) via mma.sync on pre-converted bf16 hi/lo inputs (R9 validated)
// ===========================================================================
template <bool RELU, bool OUTBF>
__global__ __launch_bounds__(256, 2)
void gemm_hmma_pre(const __nv_bfloat16* __restrict__ Ah, const __nv_bfloat16* __restrict__ Al,
                   const __nv_bfloat16* __restrict__ Bh, const __nv_bfloat16* __restrict__ Bl,
                   const float* __restrict__ b1, const float* __restrict__ b2,
                   float* __restrict__ C,
                   __nv_bfloat16* __restrict__ Chi, __nv_bfloat16* __restrict__ Clo,
                   int K, int N)
{
    __shared__ __align__(16) char Ahi_s[128 * 80];
    __shared__ __align__(16) char Alo_s[128 * 80];
    __shared__ __align__(16) char Bhi_s[64 * 80];
    __shared__ __align__(16) char Blo_s[64 * 80];

    const int tid = threadIdx.x;
    const int m0 = blockIdx.y * 128;
    const int n0 = blockIdx.x * 64;
    const int wid = tid >> 5, lane = tid & 31;
    const int g = lane >> 2, t = lane & 3;
    const int wm = wid & 3;
    const int wn = wid >> 2;

    const int arow0 = tid >> 2;
    const int arow1 = (tid >> 2) + 64;
    const int brow  = tid >> 2;
    const int cgrp  = (tid & 3) * 8;

    float acc[2][4][4];
    #pragma unroll
    for (int ms = 0; ms < 2; ms++)
        #pragma unroll
        for (int nt = 0; nt < 4; nt++)
            #pragma unroll
            for (int r = 0; r < 4; r++) acc[ms][nt][r] = 0.0f;

    ulonglong2 pah0, pah1, pal0, pal1, pbh, pbl;
    pah0 = *(const ulonglong2*)(Ah + (size_t)(m0 + arow0) * K + cgrp);
    pah1 = *(const ulonglong2*)(Ah + (size_t)(m0 + arow1) * K + cgrp);
    pal0 = *(const ulonglong2*)(Al + (size_t)(m0 + arow0) * K + cgrp);
    pal1 = *(const ulonglong2*)(Al + (size_t)(m0 + arow1) * K + cgrp);
    pbh  = *(const ulonglong2*)(Bh + (size_t)(n0 + brow) * K + cgrp);
    pbl  = *(const ulonglong2*)(Bl + (size_t)(n0 + brow) * K + cgrp);

    for (int k0 = 0; k0 < K; k0 += 32) {
        *(ulonglong2*)(Ahi_s + arow0 * 80 + cgrp * 2) = pah0;
        *(ulonglong2*)(Ahi_s + arow1 * 80 + cgrp * 2) = pah1;
        *(ulonglong2*)(Alo_s + arow0 * 80 + cgrp * 2) = pal0;
        *(ulonglong2*)(Alo_s + arow1 * 80 + cgrp * 2) = pal1;
        *(ulonglong2*)(Bhi_s + brow * 80 + cgrp * 2) = pbh;
        *(ulonglong2*)(Blo_s + brow * 80 + cgrp * 2) = pbl;
        __syncthreads();

        if (k0 + 32 < K) {
            const int kn = k0 + 32;
            pah0 = *(const ulonglong2*)(Ah + (size_t)(m0 + arow0) * K + kn + cgrp);
            pah1 = *(const ulonglong2*)(Ah + (size_t)(m0 + arow1) * K + kn + cgrp);
            pal0 = *(const ulonglong2*)(Al + (size_t)(m0 + arow0) * K + kn + cgrp);
            pal1 = *(const ulonglong2*)(Al + (size_t)(m0 + arow1) * K + kn + cgrp);
            pbh  = *(const ulonglong2*)(Bh + (size_t)(n0 + brow) * K + kn + cgrp);
            pbl  = *(const ulonglong2*)(Bl + (size_t)(n0 + brow) * K + kn + cgrp);
        }

        #pragma unroll
        for (int ks = 0; ks < 2; ks++) {
            const int co = ks * 32 + t * 4;
            u32 ahi[2][4], alo[2][4], bhi[4][2], blo[4][2];
            #pragma unroll
            for (int ms = 0; ms < 2; ms++) {
                const int rb = (wm * 32 + ms * 16 + g) * 80 + co;
                ahi[ms][0] = *(const u32*)(Ahi_s + rb);
                ahi[ms][1] = *(const u32*)(Ahi_s + rb + 8 * 80);
                ahi[ms][2] = *(const u32*)(Ahi_s + rb + 16);
                ahi[ms][3] = *(const u32*)(Ahi_s + rb + 8 * 80 + 16);
                alo[ms][0] = *(const u32*)(Alo_s + rb);
                alo[ms][1] = *(const u32*)(Alo_s + rb + 8 * 80);
                alo[ms][2] = *(const u32*)(Alo_s + rb + 16);
                alo[ms][3] = *(const u32*)(Alo_s + rb + 8 * 80 + 16);
            }
            #pragma unroll
            for (int nt = 0; nt < 4; nt++) {
                const int bo = (wn * 32 + nt * 8 + g) * 80 + co;
                bhi[nt][0] = *(const u32*)(Bhi_s + bo);
                bhi[nt][1] = *(const u32*)(Bhi_s + bo + 16);
                blo[nt][0] = *(const u32*)(Blo_s + bo);
                blo[nt][1] = *(const u32*)(Blo_s + bo + 16);
            }
            #pragma unroll
            for (int ms = 0; ms < 2; ms++)
                #pragma unroll
                for (int nt = 0; nt < 4; nt++) {
                    mma16816(acc[ms][nt], ahi[ms], bhi[nt]);
                    mma16816(acc[ms][nt], alo[ms], bhi[nt]);
                    mma16816(acc[ms][nt], ahi[ms], blo[nt]);
                }
        }
        __syncthreads();
    }

    #pragma unroll
    for (int ms = 0; ms < 2; ms++) {
        #pragma unroll
        for (int half = 0; half < 2; half++) {
            const int row = m0 + wm * 32 + ms * 16 + g + half * 8;
            #pragma unroll
            for (int nt = 0; nt < 4; nt++) {
                const int col = n0 + wn * 32 + nt * 8 + 2 * t;
                float bb0 = b1[col]     + (b2 ? b2[col]     : 0.0f);
                float bb1 = b1[col + 1] + (b2 ? b2[col + 1] : 0.0f);
                float v0 = acc[ms][nt][half * 2]     + bb0;
                float v1 = acc[ms][nt][half * 2 + 1] + bb1;
                if (RELU) { v0 = v0 > 0.0f ? v0 : 0.0f; v1 = v1 > 0.0f ? v1 : 0.0f; }
                if (OUTBF) {
                    __nv_bfloat16 h0, l0, h1, l1;
                    pack_hl(v0, &h0, &l0);
                    pack_hl(v1, &h1, &l1);
                    __nv_bfloat162 ph; ph.x = h0; ph.y = h1;
                    __nv_bfloat162 pl; pl.x = l0; pl.y = l1;
                    *(__nv_bfloat162*)(Chi + (size_t)row * N + col) = ph;
                    *(__nv_bfloat162*)(Clo + (size_t)row * N + col) = pl;
                } else {
                    C[(size_t)row * N + col]     = v0;
                    C[(size_t)row * N + col + 1] = v1;
                }
            }
        }
    }
}

// ===========================================================================
// LSTM (R2, known-good): 64 blocks x 256 threads
// ===========================================================================
__global__ __launch_bounds__(256, 1)
void lstm_kernel(const float* __restrict__ gx, const float* __restrict__ whh,
                 const int* __restrict__ done,
                 const float* __restrict__ h0, const float* __restrict__ c0,
                 float* __restrict__ out)
{
    extern __shared__ float sm[];
    float* ws     = sm;
    float* h_s    = sm + 16 * 264;
    float* gate_s = h_s + 32 * 264;
    float* c_s    = gate_s + 512;

    const int tid = threadIdx.x;
    const int j0 = blockIdx.x * 4;

    #pragma unroll
    for (int l = 0; l < 4; l++) {
        const int id = tid + l * 256;
        const int r = id >> 6;
        const int c4 = (id & 63) * 4;
        const int g = r >> 2, jj = r & 3;
        *(float4*)(ws + r * 264 + c4) =
            *(const float4*)(whh + (size_t)(g * 256 + j0 + jj) * 256 + c4);
    }
    if (tid < 128) {
        const int b = tid >> 2, jj = tid & 3;
        c_s[tid] = c0[b * 256 + j0 + jj];
    }
    unsigned bar_gen = 0;
    if (tid == 0) bar_gen = *((volatile unsigned*)&g_gen);
    __syncthreads();

    const int u = tid & 7;
    const int b = tid >> 3;
    const int jj = u & 3, gh = u >> 2;
    const float* w0 = ws + ((2 * gh) * 4 + jj) * 264;
    const float* w1 = ws + ((2 * gh + 1) * 4 + jj) * 264;
    const float* hb = h_s + b * 264;

    for (int t = 0; t < 64; t++) {
        const float* hsrc = (t == 0) ? h0 : g_hbuf[(t - 1) & 1];
        const int* dn = done + t * 32;
        #pragma unroll
        for (int l = 0; l < 8; l++) {
            const int f = tid + l * 256;
            const int bb = f >> 6;
            const int kc = (f & 63) * 4;
            const float m = 1.0f - (float)dn[bb];
            float4 v = *(const float4*)(hsrc + bb * 256 + kc);
            v.x *= m; v.y *= m; v.z *= m; v.w *= m;
            *(float4*)(h_s + bb * 264 + kc) = v;
        }
        __syncthreads();

        float s00 = 0, s01 = 0, s02 = 0, s03 = 0;
        float s10 = 0, s11 = 0, s12 = 0, s13 = 0;
        #pragma unroll 8
        for (int k = 0; k < 256; k += 4) {
            const float4 h4 = *(const float4*)(hb + k);
            const float4 wa = *(const float4*)(w0 + k);
            const float4 wb4 = *(const float4*)(w1 + k);
            s00 += h4.x * wa.x;  s01 += h4.y * wa.y;
            s02 += h4.z * wa.z;  s03 += h4.w * wa.w;
            s10 += h4.x * wb4.x; s11 += h4.y * wb4.y;
            s12 += h4.z * wb4.z; s13 += h4.w * wb4.w;
        }
        const int row = t * 32 + b;
        const float g0v = ((s00 + s01) + (s02 + s03)) +
                          gx[(size_t)row * 1024 + (2 * gh) * 256 + j0 + jj];
        const float g1v = ((s10 + s11) + (s12 + s13)) +
                          gx[(size_t)row * 1024 + (2 * gh + 1) * 256 + j0 + jj];
        gate_s[(b * 4 + jj) * 4 + 2 * gh] = g0v;
        gate_s[(b * 4 + jj) * 4 + 2 * gh + 1] = g1v;
        __syncthreads();

        if (tid < 128) {
            const int bb = tid >> 2, j2 = tid & 3;
            const float* gp = gate_s + tid * 4;
            const float gi = gp[0], gf = gp[1], gg = gp[2], go = gp[3];
            const float m = 1.0f - (float)dn[bb];
            const float cold = c_s[tid] * m;
            const float si = 1.0f / (1.0f + __expf(-gi));
            const float sf = 1.0f / (1.0f + __expf(-gf));
            const float so = 1.0f / (1.0f + __expf(-go));
            const float cn = sf * cold + si * tanhf(gg);
            const float h = so * tanhf(cn);
            c_s[tid] = cn;
            const int j = j0 + j2;
            g_hbuf[t & 1][bb * 256 + j] = h;
            out[(size_t)(t * 32 + bb) * 256 + j] = h;
        }
        __threadfence();
        __syncthreads();

        if (t < 63) {
            if (tid == 0) {
                const unsigned prev = atomicAdd(&g_count, 1);
                if (prev == gridDim.x - 1) {
                    g_count = 0;
                    __threadfence();
                    atomicAdd(&g_gen, 1);
                } else {
                    while (*((volatile unsigned*)&g_gen) == bar_gen) { }
                }
                bar_gen++;
                __threadfence();
            }
            __syncthreads();
        }
    }
}

// ===========================================================================
extern "C" void kernel_launch(void* const* d_in, const int* in_sizes, int n_in,
                              void* d_out, int out_size)
{
    const float* x    = (const float*)d_in[0];
    const int*   done = (const int*)d_in[1];
    const float* w1   = (const float*)d_in[2];
    const float* b1   = (const float*)d_in[3];
    const float* w2   = (const float*)d_in[4];
    const float* b2   = (const float*)d_in[5];
    const float* w3   = (const float*)d_in[6];
    const float* b3   = (const float*)d_in[7];
    const float* fcw  = (const float*)d_in[8];
    const float* fcb  = (const float*)d_in[9];
    const float* wih  = (const float*)d_in[10];
    const float* whh  = (const float*)d_in[11];
    const float* bih  = (const float*)d_in[12];
    const float* bhh  = (const float*)d_in[13];
    const float* h0   = (const float*)d_in[14];
    const float* c0   = (const float*)d_in[15];
    float* out = (float*)d_out;

    float *buf2, *buf3, *gatesx;
    __nv_bfloat16 *c2ah, *c2al, *b3h, *b3l, *fcwh, *fcwl, *wihh, *wihl, *fh, *fl;
    ull *c1wh, *c1wl, *c2wh, *c2wl;
    cudaGetSymbolAddress((void**)&buf2,   g_buf2);
    cudaGetSymbolAddress((void**)&buf3,   g_buf3);
    cudaGetSymbolAddress((void**)&gatesx, g_gatesx);
    cudaGetSymbolAddress((void**)&c2ah, g_c2a_h);
    cudaGetSymbolAddress((void**)&c2al, g_c2a_l);
    cudaGetSymbolAddress((void**)&c1wh, g_c1w_h);
    cudaGetSymbolAddress((void**)&c1wl, g_c1w_l);
    cudaGetSymbolAddress((void**)&c2wh, g_c2w_h);
    cudaGetSymbolAddress((void**)&c2wl, g_c2w_l);
    cudaGetSymbolAddress((void**)&b3h,  g_b3h);
    cudaGetSymbolAddress((void**)&b3l,  g_b3l);
    cudaGetSymbolAddress((void**)&fcwh, g_fcwh);
    cudaGetSymbolAddress((void**)&fcwl, g_fcwl);
    cudaGetSymbolAddress((void**)&wihh, g_wihh);
    cudaGetSymbolAddress((void**)&wihl, g_wihl);
    cudaGetSymbolAddress((void**)&fh,   g_fh);
    cudaGetSymbolAddress((void**)&fl,   g_fl);

    cudaFuncSetAttribute(conv1_mma_kernel, cudaFuncAttributeMaxDynamicSharedMemorySize, C1_SMEM);
    cudaFuncSetAttribute(conv2_mma_kernel, cudaFuncAttributeMaxDynamicSharedMemorySize, C2_SMEM);
    cudaFuncSetAttribute(conv3_kernel, cudaFuncAttributeMaxDynamicSharedMemorySize, SMEM3);
    cudaFuncSetAttribute(lstm_kernel,  cudaFuncAttributeMaxDynamicSharedMemorySize, SMEML);

    cvt_c1w<<<8, 256>>>(w1, c1wh, c1wl);
    cvt_c2w<<<32, 256>>>(w2, c2wh, c2wl);
    cvt_hilo<<<512, 256>>>((const float4*)fcw, (ull*)fcwh, (ull*)fcwl, 131072);
    cvt_hilo<<<512, 256>>>((const float4*)wih, (ull*)wihh, (ull*)wihl, 131072);
    conv1_mma_kernel<<<2048, 256, C1_SMEM>>>(x, c1wh, c1wl, b1, c2ah, c2al);
    conv2_mma_kernel<<<1024, 256, C2_SMEM>>>(c2ah, c2al, c2wh, c2wl, b2, buf2);
    conv3_kernel<<<1024, 128, SMEM3>>>(buf2, w3, b3, buf3);
    cvt_hilo<<<2048, 256>>>((const float4*)buf3, (ull*)b3h, (ull*)b3l, 524288);
    gemm_hmma_pre<true, true><<<dim3(8, 16), 256>>>(
        b3h, b3l, fcwh, fcwl, fcb, nullptr, nullptr, fh, fl, 1024, 512);
    gemm_hmma_pre<false, false><<<dim3(16, 16), 256>>>(
        fh, fl, wihh, wihl, bih, bhh, gatesx, nullptr, nullptr, 512, 1024);
    lstm_kernel<<<64, 256, SMEML>>>(gatesx, whh, done, h0, c0, out);
}

// round 12
// speedup vs baseline: 1.1497x; 1.0490x over previous
#include <cuda_runtime.h>
#include <cuda_bf16.h>
#include <math.h>
#include <cstdint>

typedef unsigned long long ull;
typedef uint32_t u32;

// ===========================================================================
// Static scratch
// ===========================================================================
__device__ float g_buf2[2048 * 64 * 6 * 6];
__device__ float g_gatesx[2048 * 1024];
__device__ float g_hbuf[2][32 * 256];
__device__ unsigned g_count;
__device__ unsigned g_gen;
// pre-converted bf16 hi/lo operands
__device__ __nv_bfloat16 g_c2a_h[2048 * 64 * 128], g_c2a_l[2048 * 64 * 128];
__device__ ull g_c1w_h[2048], g_c1w_l[2048];
__device__ ull g_c2w_h[8192], g_c2w_l[8192];
__device__ ull g_c3w_h[9216], g_c3w_l[9216];       // conv3 weights [off][oc][icq]
__device__ __nv_bfloat16 g_b3h[2048 * 1024], g_b3l[2048 * 1024];
__device__ __nv_bfloat16 g_fcwh[512 * 1024], g_fcwl[512 * 1024];
__device__ __nv_bfloat16 g_wihh[1024 * 512], g_wihl[1024 * 512];
__device__ __nv_bfloat16 g_fh[2048 * 512],  g_fl[2048 * 512];

#define SMEML ((16 * 264 + 32 * 264 + 512 + 128) * 4)

// ===========================================================================
// bf16 helpers
// ===========================================================================
__device__ __forceinline__ void mma16816(float* d, const u32* a, const u32* b) {
    asm volatile(
        "mma.sync.aligned.m16n8k16.row.col.f32.bf16.bf16.f32 "
        "{%0,%1,%2,%3}, {%4,%5,%6,%7}, {%8,%9}, {%0,%1,%2,%3};"
        : "+f"(d[0]), "+f"(d[1]), "+f"(d[2]), "+f"(d[3])
        : "r"(a[0]), "r"(a[1]), "r"(a[2]), "r"(a[3]), "r"(b[0]), "r"(b[1]));
}

__device__ __forceinline__ ull pack_hi4(float4 v, float4* rem) {
    __nv_bfloat16 h0 = __float2bfloat16_rn(v.x);
    __nv_bfloat16 h1 = __float2bfloat16_rn(v.y);
    __nv_bfloat16 h2 = __float2bfloat16_rn(v.z);
    __nv_bfloat16 h3 = __float2bfloat16_rn(v.w);
    rem->x = v.x - __bfloat162float(h0);
    rem->y = v.y - __bfloat162float(h1);
    rem->z = v.z - __bfloat162float(h2);
    rem->w = v.w - __bfloat162float(h3);
    return (ull)__bfloat16_as_ushort(h0) |
           ((ull)__bfloat16_as_ushort(h1) << 16) |
           ((ull)__bfloat16_as_ushort(h2) << 32) |
           ((ull)__bfloat16_as_ushort(h3) << 48);
}
__device__ __forceinline__ ull pack_lo4(float4 v) {
    return (ull)__bfloat16_as_ushort(__float2bfloat16_rn(v.x)) |
           ((ull)__bfloat16_as_ushort(__float2bfloat16_rn(v.y)) << 16) |
           ((ull)__bfloat16_as_ushort(__float2bfloat16_rn(v.z)) << 32) |
           ((ull)__bfloat16_as_ushort(__float2bfloat16_rn(v.w)) << 48);
}
__device__ __forceinline__ void pack_hl(float v, __nv_bfloat16* hi, __nv_bfloat16* lo) {
    __nv_bfloat16 h = __float2bfloat16_rn(v);
    *hi = h;
    *lo = __float2bfloat16_rn(v - __bfloat162float(h));
}

// ===========================================================================
// conversion kernels (run once per launch, tiny)
// ===========================================================================
__global__ __launch_bounds__(256)
void cvt_hilo(const float4* __restrict__ src, ull* __restrict__ hi,
              ull* __restrict__ lo, int n4)
{
    const int i = blockIdx.x * 256 + threadIdx.x;
    if (i < n4) {
        float4 v = src[i];
        float4 rem;
        const ull ph = pack_hi4(v, &rem);
        hi[i] = ph;
        lo[i] = pack_lo4(rem);
    }
}

__global__ __launch_bounds__(256)
void cvt_c1w(const float* __restrict__ w, ull* __restrict__ hi, ull* __restrict__ lo)
{
    const int idx = blockIdx.x * 256 + threadIdx.x;
    if (idx < 2048) {
        const int q  = idx >> 9;
        const int oc = (idx >> 4) & 31;
        const int cs = idx & 15;
        const int c = cs >> 2, s = cs & 3;
        const int dh = q >> 1, dw = q & 1;
        float4 v = *(const float4*)(w + (size_t)((oc * 4 + c) * 8 + 4 * dh + s) * 8 + 4 * dw);
        float4 rem;
        hi[idx] = pack_hi4(v, &rem);
        lo[idx] = pack_lo4(rem);
    }
}

__global__ __launch_bounds__(256)
void cvt_c2w(const float* __restrict__ w, ull* __restrict__ hi, ull* __restrict__ lo)
{
    const int idx = blockIdx.x * 256 + threadIdx.x;
    if (idx < 8192) {
        const int dh = idx >> 12;
        const int dw = (idx >> 11) & 1;
        const int oc = (idx >> 5) & 63;
        const int c  = idx & 31;
        const float* wp = w + (size_t)(oc * 32 + c) * 16;
        float4 v;
        v.x = wp[(2 * dh) * 4 + 2 * dw];
        v.y = wp[(2 * dh) * 4 + 2 * dw + 1];
        v.z = wp[(2 * dh + 1) * 4 + 2 * dw];
        v.w = wp[(2 * dh + 1) * 4 + 2 * dw + 1];
        float4 rem;
        const int row = dh * 128 + dw * 64 + oc;
        hi[row * 32 + c] = pack_hi4(v, &rem);
        lo[row * 32 + c] = pack_lo4(rem);
    }
}

// conv3 weights -> [off][oc][icq] (icq = group of 4 ic)
__global__ __launch_bounds__(256)
void cvt_c3w(const float* __restrict__ w, ull* __restrict__ hi, ull* __restrict__ lo)
{
    const int idx = blockIdx.x * 256 + threadIdx.x;   // 9216
    if (idx < 9216) {
        const int off = idx >> 10;
        const int r   = idx & 1023;
        const int oc  = r >> 4;
        const int icq = r & 15;
        float4 v;
        v.x = w[(size_t)(oc * 64 + icq * 4 + 0) * 9 + off];
        v.y = w[(size_t)(oc * 64 + icq * 4 + 1) * 9 + off];
        v.z = w[(size_t)(oc * 64 + icq * 4 + 2) * 9 + off];
        v.w = w[(size_t)(oc * 64 + icq * 4 + 3) * 9 + off];
        float4 rem;
        hi[idx] = pack_hi4(v, &rem);
        lo[idx] = pack_lo4(rem);
    }
}

// ===========================================================================
// conv1 via mma.sync (bf16x3) — R10/R11 validated
// ===========================================================================
#define A_STRIDE 144
#define A_BYTES  (273 * A_STRIDE)
#define BQ_BYTES (32 * A_STRIDE)
#define OFF_AHI  128
#define OFF_ALO  (OFF_AHI + A_BYTES)
#define OFF_BHI  (OFF_ALO + A_BYTES)
#define OFF_BLO  (OFF_BHI + 4 * BQ_BYTES)
#define C1_SMEM  (OFF_BLO + 4 * BQ_BYTES)

__global__ __launch_bounds__(256, 1)
void conv1_mma_kernel(const float* __restrict__ x,
                      const ull* __restrict__ c1wh, const ull* __restrict__ c1wl,
                      const float* __restrict__ bias,
                      __nv_bfloat16* __restrict__ oAh, __nv_bfloat16* __restrict__ oAl)
{
    extern __shared__ __align__(16) char smem[];
    float* sbias = (float*)smem;
    char* Ahi = smem + OFF_AHI;
    char* Alo = smem + OFF_ALO;
    char* Bhi = smem + OFF_BHI;
    char* Blo = smem + OFF_BLO;

    const int tid = threadIdx.x;
    const int n = blockIdx.x;
    const float inv255 = 1.0f / 255.0f;

    if (tid < 32) sbias[tid] = bias[tid];

    for (int idx = tid; idx < 4096; idx += 256) {
        const int row = idx >> 4;
        const int cs  = idx & 15;
        const int c = cs >> 2, s = cs & 3;
        const int gh = row >> 4, gw = row & 15;
        float4 v = *(const float4*)(x + (size_t)((n * 4 + c) * 64 + 4 * gh + s) * 64 + 4 * gw);
        v.x *= inv255; v.y *= inv255; v.z *= inv255; v.w *= inv255;
        float4 rem;
        const ull ph = pack_hi4(v, &rem);
        const ull pl = pack_lo4(rem);
        const int off = row * A_STRIDE + cs * 8;
        *(ull*)(Ahi + off) = ph;
        *(ull*)(Alo + off) = pl;
    }
    for (int i = tid; i < 612; i += 256) {
        const int half = i / 306;
        const int off = 256 * A_STRIDE + (i - half * 306) * 8;
        *(ull*)((half ? Alo : Ahi) + off) = 0ull;
    }
    for (int i = tid; i < 2048; i += 256) {
        const int q = i >> 9, oc = (i >> 4) & 31, cs = i & 15;
        const int off = q * BQ_BYTES + oc * A_STRIDE + cs * 8;
        *(ull*)(Bhi + off) = c1wh[i];
        *(ull*)(Blo + off) = c1wl[i];
    }
    __syncthreads();

    const int wid = tid >> 5, lane = tid & 31;
    const int g = lane >> 2, t = lane & 3;

    float acc[2][4][4];
    #pragma unroll
    for (int m = 0; m < 2; m++)
        #pragma unroll
        for (int nt = 0; nt < 4; nt++)
            #pragma unroll
            for (int r = 0; r < 4; r++) acc[m][nt][r] = 0.0f;

    const int mt0 = wid, mt1 = wid + 8;

    #pragma unroll
    for (int q = 0; q < 4; q++) {
        const int r0 = (q >> 1) * 16 + (q & 1);
        const char* Bq_hi = Bhi + q * BQ_BYTES;
        const char* Bq_lo = Blo + q * BQ_BYTES;
        const int arow0 = (mt0 * 16 + r0 + g) * A_STRIDE;
        const int arow1 = (mt1 * 16 + r0 + g) * A_STRIDE;

        #pragma unroll
        for (int ks = 0; ks < 4; ks++) {
            const int co = ks * 32 + t * 4;
            u32 ahi[2][4], alo[2][4], bhi[4][2], blo[4][2];
            #pragma unroll
            for (int m = 0; m < 2; m++) {
                const int rb = (m ? arow1 : arow0) + co;
                ahi[m][0] = *(const u32*)(Ahi + rb);
                ahi[m][1] = *(const u32*)(Ahi + rb + 8 * A_STRIDE);
                ahi[m][2] = *(const u32*)(Ahi + rb + 16);
                ahi[m][3] = *(const u32*)(Ahi + rb + 8 * A_STRIDE + 16);
                alo[m][0] = *(const u32*)(Alo + rb);
                alo[m][1] = *(const u32*)(Alo + rb + 8 * A_STRIDE);
                alo[m][2] = *(const u32*)(Alo + rb + 16);
                alo[m][3] = *(const u32*)(Alo + rb + 8 * A_STRIDE + 16);
            }
            #pragma unroll
            for (int nt = 0; nt < 4; nt++) {
                const int bo = (nt * 8 + g) * A_STRIDE + co;
                bhi[nt][0] = *(const u32*)(Bq_hi + bo);
                bhi[nt][1] = *(const u32*)(Bq_hi + bo + 16);
                blo[nt][0] = *(const u32*)(Bq_lo + bo);
                blo[nt][1] = *(const u32*)(Bq_lo + bo + 16);
            }
            #pragma unroll
            for (int m = 0; m < 2; m++)
                #pragma unroll
                for (int nt = 0; nt < 4; nt++) {
                    mma16816(acc[m][nt], ahi[m], bhi[nt]);
                    mma16816(acc[m][nt], alo[m], bhi[nt]);
                    mma16816(acc[m][nt], ahi[m], blo[nt]);
                }
        }
    }

    __nv_bfloat16* oh_b = oAh + (size_t)n * 8192;
    __nv_bfloat16* ol_b = oAl + (size_t)n * 8192;
    #pragma unroll
    for (int m = 0; m < 2; m++) {
        const int mt = m ? mt1 : mt0;
        #pragma unroll
        for (int half = 0; half < 2; half++) {
            const int r = mt * 16 + g + half * 8;
            const int oh = r >> 4, ow = r & 15;
            const bool valid = (oh < 15) && (ow < 15);
            const int prow = (oh >> 1) * 8 + (ow >> 1);
            const int sp = (oh & 1) * 2 + (ow & 1);
            const int base = prow * 128 + sp;
            #pragma unroll
            for (int nt = 0; nt < 4; nt++) {
                const int c0 = nt * 8 + 2 * t;
                float v0 = 0.0f, v1 = 0.0f;
                if (valid) {
                    v0 = acc[m][nt][half * 2]     + sbias[c0];
                    v1 = acc[m][nt][half * 2 + 1] + sbias[c0 + 1];
                    v0 = v0 > 0.0f ? v0 : 0.0f;
                    v1 = v1 > 0.0f ? v1 : 0.0f;
                }
                __nv_bfloat16 h, l;
                pack_hl(v0, &h, &l);
                oh_b[base + c0 * 4] = h;
                ol_b[base + c0 * 4] = l;
                pack_hl(v1, &h, &l);
                oh_b[base + (c0 + 1) * 4] = h;
                ol_b[base + (c0 + 1) * 4] = l;
            }
        }
    }
}

// ===========================================================================
// conv2 via mma.sync (bf16x3) — R10/R11 validated
// ===========================================================================
#define C2_STRIDE  272
#define C2_A_SZ    (144 * C2_STRIDE)
#define C2_B_SZ    (256 * C2_STRIDE)
#define C2_OFF_AHI 512
#define C2_OFF_ALO (C2_OFF_AHI + C2_A_SZ)
#define C2_OFF_BHI (C2_OFF_ALO + C2_A_SZ)
#define C2_OFF_BLO (C2_OFF_BHI + C2_B_SZ)
#define C2_SMEM    (C2_OFF_BLO + C2_B_SZ)

__global__ __launch_bounds__(256, 1)
void conv2_mma_kernel(const __nv_bfloat16* __restrict__ Agh, const __nv_bfloat16* __restrict__ Agl,
                      const ull* __restrict__ c2wh, const ull* __restrict__ c2wl,
                      const float* __restrict__ bias, float* __restrict__ out)
{
    extern __shared__ __align__(16) char smem[];
    float* sbias = (float*)smem;
    char* Ahi = smem + C2_OFF_AHI;
    char* Alo = smem + C2_OFF_ALO;
    char* Bhi = smem + C2_OFF_BHI;
    char* Blo = smem + C2_OFF_BLO;

    const int tid = threadIdx.x;
    const int nb = blockIdx.x * 2;

    if (tid < 64) sbias[tid] = bias[tid];

    {
        const ulonglong2* sh = (const ulonglong2*)(Agh + (size_t)nb * 8192);
        const ulonglong2* sl = (const ulonglong2*)(Agl + (size_t)nb * 8192);
        for (int idx = tid; idx < 2048; idx += 256) {
            const int row = idx >> 4, ch = idx & 15;
            *(ulonglong2*)(Ahi + row * C2_STRIDE + ch * 16) = sh[idx];
            *(ulonglong2*)(Alo + row * C2_STRIDE + ch * 16) = sl[idx];
        }
    }
    for (int i = tid; i < 512; i += 256) {
        const int half = i >> 8;
        const int j = i & 255;
        const int off = (128 + (j >> 4)) * C2_STRIDE + (j & 15) * 16;
        ulonglong2 z; z.x = 0; z.y = 0;
        *(ulonglong2*)((half ? Alo : Ahi) + off) = z;
    }
    {
        const ulonglong2* sh = (const ulonglong2*)c2wh;
        const ulonglong2* sl = (const ulonglong2*)c2wl;
        for (int idx = tid; idx < 4096; idx += 256) {
            const int row = idx >> 4, ch = idx & 15;
            *(ulonglong2*)(Bhi + row * C2_STRIDE + ch * 16) = sh[idx];
            *(ulonglong2*)(Blo + row * C2_STRIDE + ch * 16) = sl[idx];
        }
    }
    __syncthreads();

    const int wid = tid >> 5, lane = tid & 31;
    const int g = lane >> 2, t = lane & 3;

    float acc[8][4];
    #pragma unroll
    for (int nt = 0; nt < 8; nt++)
        #pragma unroll
        for (int r = 0; r < 4; r++) acc[nt][r] = 0.0f;

    #pragma unroll
    for (int q = 0; q < 4; q++) {
        const int dh = q >> 1, dw = q & 1;
        const int roff = dh * 8 + dw;
        const char* Bq_hi = Bhi + (dh * 128 + dw * 64) * C2_STRIDE;
        const char* Bq_lo = Blo + (dh * 128 + dw * 64) * C2_STRIDE;
        const int arow = (wid * 16 + roff + g) * C2_STRIDE;

        #pragma unroll
        for (int ks = 0; ks < 8; ks++) {
            const int co = ks * 32 + t * 4;
            u32 ahi[4], alo[4], bhi[8][2], blo[8][2];
            const int rb = arow + co;
            ahi[0] = *(const u32*)(Ahi + rb);
            ahi[1] = *(const u32*)(Ahi + rb + 8 * C2_STRIDE);
            ahi[2] = *(const u32*)(Ahi + rb + 16);
            ahi[3] = *(const u32*)(Ahi + rb + 8 * C2_STRIDE + 16);
            alo[0] = *(const u32*)(Alo + rb);
            alo[1] = *(const u32*)(Alo + rb + 8 * C2_STRIDE);
            alo[2] = *(const u32*)(Alo + rb + 16);
            alo[3] = *(const u32*)(Alo + rb + 8 * C2_STRIDE + 16);
            #pragma unroll
            for (int nt = 0; nt < 8; nt++) {
                const int bo = (nt * 8 + g) * C2_STRIDE + co;
                bhi[nt][0] = *(const u32*)(Bq_hi + bo);
                bhi[nt][1] = *(const u32*)(Bq_hi + bo + 16);
                blo[nt][0] = *(const u32*)(Bq_lo + bo);
                blo[nt][1] = *(const u32*)(Bq_lo + bo + 16);
            }
            #pragma unroll
            for (int nt = 0; nt < 8; nt++) {
                mma16816(acc[nt], ahi, bhi[nt]);
                mma16816(acc[nt], alo, bhi[nt]);
                mma16816(acc[nt], ahi, blo[nt]);
            }
        }
    }

    #pragma unroll
    for (int half = 0; half < 2; half++) {
        const int r = wid * 16 + g + half * 8;
        const int im = r >> 6;
        const int rl = r & 63;
        const int oh = rl >> 3, ow = rl & 7;
        if (oh < 6 && ow < 6) {
            float* ob = out + (size_t)(nb + im) * 2304 + oh * 6 + ow;
            #pragma unroll
            for (int nt = 0; nt < 8; nt++) {
                const int oc = nt * 8 + 2 * t;
                float v0 = acc[nt][half * 2]     + sbias[oc];
                float v1 = acc[nt][half * 2 + 1] + sbias[oc + 1];
                ob[oc * 36]       = v0 > 0.0f ? v0 : 0.0f;
                ob[(oc + 1) * 36] = v1 > 0.0f ? v1 : 0.0f;
            }
        }
    }
}

// ===========================================================================
// conv3 via mma.sync (bf16x3) v2: pre-converted weights, all 9 offsets
// resident in smem, pure-copy fills, single sync. CTA = 4 images.
// Output written directly as bf16 hi/lo for gemm1.
// ===========================================================================
#define C3_XSTR  144
#define C3_IMG   (36 * C3_XSTR)            // 5184
#define C3_XHI   256
#define C3_XLO   (C3_XHI + 4 * C3_IMG)     // +20736
#define C3_BHI   (C3_XLO + 4 * C3_IMG)
#define C3_B_SZ  (576 * C3_XSTR)           // 82944
#define C3_BLO   (C3_BHI + C3_B_SZ)
#define C3_SMEM  (C3_BLO + C3_B_SZ)        // 207616

__global__ __launch_bounds__(256, 1)
void conv3_mma_kernel(const float* __restrict__ in,
                      const ull* __restrict__ c3wh, const ull* __restrict__ c3wl,
                      const float* __restrict__ bias,
                      __nv_bfloat16* __restrict__ oh_g, __nv_bfloat16* __restrict__ ol_g)
{
    extern __shared__ __align__(16) char smem[];
    float* sbias = (float*)smem;
    char* Xhi = smem + C3_XHI;
    char* Xlo = smem + C3_XLO;
    char* Bhi = smem + C3_BHI;
    char* Blo = smem + C3_BLO;

    const int tid = threadIdx.x;
    const int n4 = blockIdx.x * 4;

    if (tid < 64) sbias[tid] = bias[tid];

    // X fill (transpose): 4 img x 64 ic x 9 pos-groups of 4
    for (int idx = tid; idx < 2304; idx += 256) {
        const int im = idx / 576;
        const int r  = idx - im * 576;
        const int ic = r / 9;
        const int pg = r - ic * 9;
        float4 v = *(const float4*)(in + (size_t)(n4 + im) * 2304 + ic * 36 + pg * 4);
        char* xh = Xhi + im * C3_IMG;
        char* xl = Xlo + im * C3_IMG;
        __nv_bfloat16 h, l;
        pack_hl(v.x, &h, &l);
        *(__nv_bfloat16*)(xh + (pg * 4 + 0) * C3_XSTR + ic * 2) = h;
        *(__nv_bfloat16*)(xl + (pg * 4 + 0) * C3_XSTR + ic * 2) = l;
        pack_hl(v.y, &h, &l);
        *(__nv_bfloat16*)(xh + (pg * 4 + 1) * C3_XSTR + ic * 2) = h;
        *(__nv_bfloat16*)(xl + (pg * 4 + 1) * C3_XSTR + ic * 2) = l;
        pack_hl(v.z, &h, &l);
        *(__nv_bfloat16*)(xh + (pg * 4 + 2) * C3_XSTR + ic * 2) = h;
        *(__nv_bfloat16*)(xl + (pg * 4 + 2) * C3_XSTR + ic * 2) = l;
        pack_hl(v.w, &h, &l);
        *(__nv_bfloat16*)(xh + (pg * 4 + 3) * C3_XSTR + ic * 2) = h;
        *(__nv_bfloat16*)(xl + (pg * 4 + 3) * C3_XSTR + ic * 2) = l;
    }
    // B fill (pure copy): 576 rows x 16 ull
    for (int idx = tid; idx < 9216; idx += 256) {
        const int row = idx >> 4, c = idx & 15;
        *(ull*)(Bhi + row * C3_XSTR + c * 8) = c3wh[idx];
        *(ull*)(Blo + row * C3_XSTR + c * 8) = c3wl[idx];
    }
    __syncthreads();

    const int wid = tid >> 5, lane = tid & 31;
    const int g = lane >> 2, t = lane & 3;
    const int img = wid & 3;
    const int oc0 = (wid >> 2) * 32;
    const int n = n4 + img;

    float acc[4][4];
    #pragma unroll
    for (int nt = 0; nt < 4; nt++)
        #pragma unroll
        for (int r = 0; r < 4; r++) acc[nt][r] = 0.0f;

    const int ri_g = (g >> 2) * 6 + (g & 3);
    const char* Xh = Xhi + img * C3_IMG;
    const char* Xl = Xlo + img * C3_IMG;

    #pragma unroll
    for (int off = 0; off < 9; off++) {
        const int kh = off / 3, kw = off - kh * 3;
        const int rowA = (ri_g + kh * 6 + kw) * C3_XSTR;
        const char* Bo_hi = Bhi + (off * 64 + oc0) * C3_XSTR;
        const char* Bo_lo = Blo + (off * 64 + oc0) * C3_XSTR;

        #pragma unroll
        for (int ks = 0; ks < 4; ks++) {
            const int co = ks * 32 + t * 4;
            u32 ahi[4], alo[4], bhi[4][2], blo[4][2];
            const int rb = rowA + co;
            ahi[0] = *(const u32*)(Xh + rb);
            ahi[1] = *(const u32*)(Xh + rb + 12 * C3_XSTR);
            ahi[2] = *(const u32*)(Xh + rb + 16);
            ahi[3] = *(const u32*)(Xh + rb + 12 * C3_XSTR + 16);
            alo[0] = *(const u32*)(Xl + rb);
            alo[1] = *(const u32*)(Xl + rb + 12 * C3_XSTR);
            alo[2] = *(const u32*)(Xl + rb + 16);
            alo[3] = *(const u32*)(Xl + rb + 12 * C3_XSTR + 16);
            #pragma unroll
            for (int nt = 0; nt < 4; nt++) {
                const int bo = (nt * 8 + g) * C3_XSTR + co;
                bhi[nt][0] = *(const u32*)(Bo_hi + bo);
                bhi[nt][1] = *(const u32*)(Bo_hi + bo + 16);
                blo[nt][0] = *(const u32*)(Bo_lo + bo);
                blo[nt][1] = *(const u32*)(Bo_lo + bo + 16);
            }
            #pragma unroll
            for (int nt = 0; nt < 4; nt++) {
                mma16816(acc[nt], ahi, bhi[nt]);
                mma16816(acc[nt], alo, bhi[nt]);
                mma16816(acc[nt], ahi, blo[nt]);
            }
        }
    }

    // epilogue: out[n*1024 + oc*16 + r], r = g (d0,d1) and g+8 (d2,d3); bf16 hi/lo
    __nv_bfloat16* po = oh_g + (size_t)n * 1024;
    __nv_bfloat16* pl = ol_g + (size_t)n * 1024;
    #pragma unroll
    for (int nt = 0; nt < 4; nt++) {
        const int oc = oc0 + nt * 8 + 2 * t;
        const float b0 = sbias[oc], b1 = sbias[oc + 1];
        float v0 = acc[nt][0] + b0;  v0 = v0 > 0.0f ? v0 : 0.0f;
        float v1 = acc[nt][1] + b1;  v1 = v1 > 0.0f ? v1 : 0.0f;
        float v2 = acc[nt][2] + b0;  v2 = v2 > 0.0f ? v2 : 0.0f;
        float v3 = acc[nt][3] + b1;  v3 = v3 > 0.0f ? v3 : 0.0f;
        __nv_bfloat16 h, l;
        pack_hl(v0, &h, &l); po[oc * 16 + g] = h;           pl[oc * 16 + g] = l;
        pack_hl(v1, &h, &l); po[(oc + 1) * 16 + g] = h;     pl[(oc + 1) * 16 + g] = l;
        pack_hl(v2, &h, &l); po[oc * 16 + g + 8] = h;       pl[oc * 16 + g + 8] = l;
        pack_hl(v3, &h, &l); po[(oc + 1) * 16 + g + 8] = h; pl[(oc + 1) * 16 + g + 8] = l;
    }
}

// ===========================================================================
// GEMM (NT) via mma.sync on pre-converted bf16 hi/lo inputs (R9 validated)
// ===========================================================================
template <bool RELU, bool OUTBF>
__global__ __launch_bounds__(256, 2)
void gemm_hmma_pre(const __nv_bfloat16* __restrict__ Ah, const __nv_bfloat16* __restrict__ Al,
                   const __nv_bfloat16* __restrict__ Bh, const __nv_bfloat16* __restrict__ Bl,
                   const float* __restrict__ b1, const float* __restrict__ b2,
                   float* __restrict__ C,
                   __nv_bfloat16* __restrict__ Chi, __nv_bfloat16* __restrict__ Clo,
                   int K, int N)
{
    __shared__ __align__(16) char Ahi_s[128 * 80];
    __shared__ __align__(16) char Alo_s[128 * 80];
    __shared__ __align__(16) char Bhi_s[64 * 80];
    __shared__ __align__(16) char Blo_s[64 * 80];

    const int tid = threadIdx.x;
    const int m0 = blockIdx.y * 128;
    const int n0 = blockIdx.x * 64;
    const int wid = tid >> 5, lane = tid & 31;
    const int g = lane >> 2, t = lane & 3;
    const int wm = wid & 3;
    const int wn = wid >> 2;

    const int arow0 = tid >> 2;
    const int arow1 = (tid >> 2) + 64;
    const int brow  = tid >> 2;
    const int cgrp  = (tid & 3) * 8;

    float acc[2][4][4];
    #pragma unroll
    for (int ms = 0; ms < 2; ms++)
        #pragma unroll
        for (int nt = 0; nt < 4; nt++)
            #pragma unroll
            for (int r = 0; r < 4; r++) acc[ms][nt][r] = 0.0f;

    ulonglong2 pah0, pah1, pal0, pal1, pbh, pbl;
    pah0 = *(const ulonglong2*)(Ah + (size_t)(m0 + arow0) * K + cgrp);
    pah1 = *(const ulonglong2*)(Ah + (size_t)(m0 + arow1) * K + cgrp);
    pal0 = *(const ulonglong2*)(Al + (size_t)(m0 + arow0) * K + cgrp);
    pal1 = *(const ulonglong2*)(Al + (size_t)(m0 + arow1) * K + cgrp);
    pbh  = *(const ulonglong2*)(Bh + (size_t)(n0 + brow) * K + cgrp);
    pbl  = *(const ulonglong2*)(Bl + (size_t)(n0 + brow) * K + cgrp);

    for (int k0 = 0; k0 < K; k0 += 32) {
        *(ulonglong2*)(Ahi_s + arow0 * 80 + cgrp * 2) = pah0;
        *(ulonglong2*)(Ahi_s + arow1 * 80 + cgrp * 2) = pah1;
        *(ulonglong2*)(Alo_s + arow0 * 80 + cgrp * 2) = pal0;
        *(ulonglong2*)(Alo_s + arow1 * 80 + cgrp * 2) = pal1;
        *(ulonglong2*)(Bhi_s + brow * 80 + cgrp * 2) = pbh;
        *(ulonglong2*)(Blo_s + brow * 80 + cgrp * 2) = pbl;
        __syncthreads();

        if (k0 + 32 < K) {
            const int kn = k0 + 32;
            pah0 = *(const ulonglong2*)(Ah + (size_t)(m0 + arow0) * K + kn + cgrp);
            pah1 = *(const ulonglong2*)(Ah + (size_t)(m0 + arow1) * K + kn + cgrp);
            pal0 = *(const ulonglong2*)(Al + (size_t)(m0 + arow0) * K + kn + cgrp);
            pal1 = *(const ulonglong2*)(Al + (size_t)(m0 + arow1) * K + kn + cgrp);
            pbh  = *(const ulonglong2*)(Bh + (size_t)(n0 + brow) * K + kn + cgrp);
            pbl  = *(const ulonglong2*)(Bl + (size_t)(n0 + brow) * K + kn + cgrp);
        }

        #pragma unroll
        for (int ks = 0; ks < 2; ks++) {
            const int co = ks * 32 + t * 4;
            u32 ahi[2][4], alo[2][4], bhi[4][2], blo[4][2];
            #pragma unroll
            for (int ms = 0; ms < 2; ms++) {
                const int rb = (wm * 32 + ms * 16 + g) * 80 + co;
                ahi[ms][0] = *(const u32*)(Ahi_s + rb);
                ahi[ms][1] = *(const u32*)(Ahi_s + rb + 8 * 80);
                ahi[ms][2] = *(const u32*)(Ahi_s + rb + 16);
                ahi[ms][3] = *(const u32*)(Ahi_s + rb + 8 * 80 + 16);
                alo[ms][0] = *(const u32*)(Alo_s + rb);
                alo[ms][1] = *(const u32*)(Alo_s + rb + 8 * 80);
                alo[ms][2] = *(const u32*)(Alo_s + rb + 16);
                alo[ms][3] = *(const u32*)(Alo_s + rb + 8 * 80 + 16);
            }
            #pragma unroll
            for (int nt = 0; nt < 4; nt++) {
                const int bo = (wn * 32 + nt * 8 + g) * 80 + co;
                bhi[nt][0] = *(const u32*)(Bhi_s + bo);
                bhi[nt][1] = *(const u32*)(Bhi_s + bo + 16);
                blo[nt][0] = *(const u32*)(Blo_s + bo);
                blo[nt][1] = *(const u32*)(Blo_s + bo + 16);
            }
            #pragma unroll
            for (int ms = 0; ms < 2; ms++)
                #pragma unroll
                for (int nt = 0; nt < 4; nt++) {
                    mma16816(acc[ms][nt], ahi[ms], bhi[nt]);
                    mma16816(acc[ms][nt], alo[ms], bhi[nt]);
                    mma16816(acc[ms][nt], ahi[ms], blo[nt]);
                }
        }
        __syncthreads();
    }

    #pragma unroll
    for (int ms = 0; ms < 2; ms++) {
        #pragma unroll
        for (int half = 0; half < 2; half++) {
            const int row = m0 + wm * 32 + ms * 16 + g + half * 8;
            #pragma unroll
            for (int nt = 0; nt < 4; nt++) {
                const int col = n0 + wn * 32 + nt * 8 + 2 * t;
                float bb0 = b1[col]     + (b2 ? b2[col]     : 0.0f);
                float bb1 = b1[col + 1] + (b2 ? b2[col + 1] : 0.0f);
                float v0 = acc[ms][nt][half * 2]     + bb0;
                float v1 = acc[ms][nt][half * 2 + 1] + bb1;
                if (RELU) { v0 = v0 > 0.0f ? v0 : 0.0f; v1 = v1 > 0.0f ? v1 : 0.0f; }
                if (OUTBF) {
                    __nv_bfloat16 h0, l0, h1, l1;
                    pack_hl(v0, &h0, &l0);
                    pack_hl(v1, &h1, &l1);
                    __nv_bfloat162 ph; ph.x = h0; ph.y = h1;
                    __nv_bfloat162 pl; pl.x = l0; pl.y = l1;
                    *(__nv_bfloat162*)(Chi + (size_t)row * N + col) = ph;
                    *(__nv_bfloat162*)(Clo + (size_t)row * N + col) = pl;
                } else {
                    C[(size_t)row * N + col]     = v0;
                    C[(size_t)row * N + col + 1] = v1;
                }
            }
        }
    }
}

// ===========================================================================
// LSTM (R2, known-good): 64 blocks x 256 threads
// ===========================================================================
__global__ __launch_bounds__(256, 1)
void lstm_kernel(const float* __restrict__ gx, const float* __restrict__ whh,
                 const int* __restrict__ done,
                 const float* __restrict__ h0, const float* __restrict__ c0,
                 float* __restrict__ out)
{
    extern __shared__ float sm[];
    float* ws     = sm;
    float* h_s    = sm + 16 * 264;
    float* gate_s = h_s + 32 * 264;
    float* c_s    = gate_s + 512;

    const int tid = threadIdx.x;
    const int j0 = blockIdx.x * 4;

    #pragma unroll
    for (int l = 0; l < 4; l++) {
        const int id = tid + l * 256;
        const int r = id >> 6;
        const int c4 = (id & 63) * 4;
        const int g = r >> 2, jj = r & 3;
        *(float4*)(ws + r * 264 + c4) =
            *(const float4*)(whh + (size_t)(g * 256 + j0 + jj) * 256 + c4);
    }
    if (tid < 128) {
        const int b = tid >> 2, jj = tid & 3;
        c_s[tid] = c0[b * 256 + j0 + jj];
    }
    unsigned bar_gen = 0;
    if (tid == 0) bar_gen = *((volatile unsigned*)&g_gen);
    __syncthreads();

    const int u = tid & 7;
    const int b = tid >> 3;
    const int jj = u & 3, gh = u >> 2;
    const float* w0 = ws + ((2 * gh) * 4 + jj) * 264;
    const float* w1 = ws + ((2 * gh + 1) * 4 + jj) * 264;
    const float* hb = h_s + b * 264;

    for (int t = 0; t < 64; t++) {
        const float* hsrc = (t == 0) ? h0 : g_hbuf[(t - 1) & 1];
        const int* dn = done + t * 32;
        #pragma unroll
        for (int l = 0; l < 8; l++) {
            const int f = tid + l * 256;
            const int bb = f >> 6;
            const int kc = (f & 63) * 4;
            const float m = 1.0f - (float)dn[bb];
            float4 v = *(const float4*)(hsrc + bb * 256 + kc);
            v.x *= m; v.y *= m; v.z *= m; v.w *= m;
            *(float4*)(h_s + bb * 264 + kc) = v;
        }
        __syncthreads();

        float s00 = 0, s01 = 0, s02 = 0, s03 = 0;
        float s10 = 0, s11 = 0, s12 = 0, s13 = 0;
        #pragma unroll 8
        for (int k = 0; k < 256; k += 4) {
            const float4 h4 = *(const float4*)(hb + k);
            const float4 wa = *(const float4*)(w0 + k);
            const float4 wb4 = *(const float4*)(w1 + k);
            s00 += h4.x * wa.x;  s01 += h4.y * wa.y;
            s02 += h4.z * wa.z;  s03 += h4.w * wa.w;
            s10 += h4.x * wb4.x; s11 += h4.y * wb4.y;
            s12 += h4.z * wb4.z; s13 += h4.w * wb4.w;
        }
        const int row = t * 32 + b;
        const float g0v = ((s00 + s01) + (s02 + s03)) +
                          gx[(size_t)row * 1024 + (2 * gh) * 256 + j0 + jj];
        const float g1v = ((s10 + s11) + (s12 + s13)) +
                          gx[(size_t)row * 1024 + (2 * gh + 1) * 256 + j0 + jj];
        gate_s[(b * 4 + jj) * 4 + 2 * gh] = g0v;
        gate_s[(b * 4 + jj) * 4 + 2 * gh + 1] = g1v;
        __syncthreads();

        if (tid < 128) {
            const int bb = tid >> 2, j2 = tid & 3;
            const float* gp = gate_s + tid * 4;
            const float gi = gp[0], gf = gp[1], gg = gp[2], go = gp[3];
            const float m = 1.0f - (float)dn[bb];
            const float cold = c_s[tid] * m;
            const float si = 1.0f / (1.0f + __expf(-gi));
            const float sf = 1.0f / (1.0f + __expf(-gf));
            const float so = 1.0f / (1.0f + __expf(-go));
            const float cn = sf * cold + si * tanhf(gg);
            const float h = so * tanhf(cn);
            c_s[tid] = cn;
            const int j = j0 + j2;
            g_hbuf[t & 1][bb * 256 + j] = h;
            out[(size_t)(t * 32 + bb) * 256 + j] = h;
        }
        __threadfence();
        __syncthreads();

        if (t < 63) {
            if (tid == 0) {
                const unsigned prev = atomicAdd(&g_count, 1);
                if (prev == gridDim.x - 1) {
                    g_count = 0;
                    __threadfence();
                    atomicAdd(&g_gen, 1);
                } else {
                    while (*((volatile unsigned*)&g_gen) == bar_gen) { }
                }
                bar_gen++;
                __threadfence();
            }
            __syncthreads();
        }
    }
}

// ===========================================================================
extern "C" void kernel_launch(void* const* d_in, const int* in_sizes, int n_in,
                              void* d_out, int out_size)
{
    const float* x    = (const float*)d_in[0];
    const int*   done = (const int*)d_in[1];
    const float* w1   = (const float*)d_in[2];
    const float* b1   = (const float*)d_in[3];
    const float* w2   = (const float*)d_in[4];
    const float* b2   = (const float*)d_in[5];
    const float* w3   = (const float*)d_in[6];
    const float* b3   = (const float*)d_in[7];
    const float* fcw  = (const float*)d_in[8];
    const float* fcb  = (const float*)d_in[9];
    const float* wih  = (const float*)d_in[10];
    const float* whh  = (const float*)d_in[11];
    const float* bih  = (const float*)d_in[12];
    const float* bhh  = (const float*)d_in[13];
    const float* h0   = (const float*)d_in[14];
    const float* c0   = (const float*)d_in[15];
    float* out = (float*)d_out;

    float *buf2, *gatesx;
    __nv_bfloat16 *c2ah, *c2al, *b3h, *b3l, *fcwh, *fcwl, *wihh, *wihl, *fh, *fl;
    ull *c1wh, *c1wl, *c2wh, *c2wl, *c3wh, *c3wl;
    cudaGetSymbolAddress((void**)&buf2,   g_buf2);
    cudaGetSymbolAddress((void**)&gatesx, g_gatesx);
    cudaGetSymbolAddress((void**)&c2ah, g_c2a_h);
    cudaGetSymbolAddress((void**)&c2al, g_c2a_l);
    cudaGetSymbolAddress((void**)&c1wh, g_c1w_h);
    cudaGetSymbolAddress((void**)&c1wl, g_c1w_l);
    cudaGetSymbolAddress((void**)&c2wh, g_c2w_h);
    cudaGetSymbolAddress((void**)&c2wl, g_c2w_l);
    cudaGetSymbolAddress((void**)&c3wh, g_c3w_h);
    cudaGetSymbolAddress((void**)&c3wl, g_c3w_l);
    cudaGetSymbolAddress((void**)&b3h,  g_b3h);
    cudaGetSymbolAddress((void**)&b3l,  g_b3l);
    cudaGetSymbolAddress((void**)&fcwh, g_fcwh);
    cudaGetSymbolAddress((void**)&fcwl, g_fcwl);
    cudaGetSymbolAddress((void**)&wihh, g_wihh);
    cudaGetSymbolAddress((void**)&wihl, g_wihl);
    cudaGetSymbolAddress((void**)&fh,   g_fh);
    cudaGetSymbolAddress((void**)&fl,   g_fl);

    cudaFuncSetAttribute(conv1_mma_kernel, cudaFuncAttributeMaxDynamicSharedMemorySize, C1_SMEM);
    cudaFuncSetAttribute(conv2_mma_kernel, cudaFuncAttributeMaxDynamicSharedMemorySize, C2_SMEM);
    cudaFuncSetAttribute(conv3_mma_kernel, cudaFuncAttributeMaxDynamicSharedMemorySize, C3_SMEM);
    cudaFuncSetAttribute(lstm_kernel,  cudaFuncAttributeMaxDynamicSharedMemorySize, SMEML);

    cvt_c1w<<<8, 256>>>(w1, c1wh, c1wl);
    cvt_c2w<<<32, 256>>>(w2, c2wh, c2wl);
    cvt_c3w<<<36, 256>>>(w3, c3wh, c3wl);
    cvt_hilo<<<512, 256>>>((const float4*)fcw, (ull*)fcwh, (ull*)fcwl, 131072);
    cvt_hilo<<<512, 256>>>((const float4*)wih, (ull*)wihh, (ull*)wihl, 131072);
    conv1_mma_kernel<<<2048, 256, C1_SMEM>>>(x, c1wh, c1wl, b1, c2ah, c2al);
    conv2_mma_kernel<<<1024, 256, C2_SMEM>>>(c2ah, c2al, c2wh, c2wl, b2, buf2);
    conv3_mma_kernel<<<512, 256, C3_SMEM>>>(buf2, c3wh, c3wl, b3, b3h, b3l);
    gemm_hmma_pre<true, true><<<dim3(8, 16), 256>>>(
        b3h, b3l, fcwh, fcwl, fcb, nullptr, nullptr, fh, fl, 1024, 512);
    gemm_hmma_pre<false, false><<<dim3(16, 16), 256>>>(
        fh, fl, wihh, wihl, bih, bhh, gatesx, nullptr, nullptr, 512, 1024);
    lstm_kernel<<<64, 256, SMEML>>>(gatesx, whh, done, h0, c0, out);
}

// round 13
// speedup vs baseline: 1.4491x; 1.2605x over previous
#include <cuda_runtime.h>
#include <cuda_bf16.h>
#include <math.h>
#include <cstdint>

typedef unsigned long long ull;
typedef uint32_t u32;

// ===========================================================================
// Static scratch
// ===========================================================================
__device__ float g_buf2[2048 * 64 * 6 * 6];
__device__ float g_gatesx[2048 * 1024];
__device__ float g_hbuf[2][32 * 256];
__device__ unsigned g_count;
__device__ unsigned g_gen;
// pre-converted bf16 hi/lo operands
__device__ __nv_bfloat16 g_c2a_h[2048 * 64 * 128], g_c2a_l[2048 * 64 * 128];
__device__ ull g_c1w_h[2048], g_c1w_l[2048];
__device__ ull g_c2w_h[8192], g_c2w_l[8192];
__device__ ull g_c3w_h[9216], g_c3w_l[9216];
__device__ __nv_bfloat16 g_b3h[2048 * 1024], g_b3l[2048 * 1024];
__device__ __nv_bfloat16 g_fcwh[512 * 1024], g_fcwl[512 * 1024];
__device__ __nv_bfloat16 g_wihh[1024 * 512], g_wihl[1024 * 512];
__device__ __nv_bfloat16 g_fh[2048 * 512],  g_fl[2048 * 512];

// LSTM v3: 128 CTAs, 2 hidden cols each
#define WSTR 260
#define SMEML3 ((8 * WSTR + 32 * 264 + 256 + 64) * 4)

// ===========================================================================
// bf16 helpers
// ===========================================================================
__device__ __forceinline__ void mma16816(float* d, const u32* a, const u32* b) {
    asm volatile(
        "mma.sync.aligned.m16n8k16.row.col.f32.bf16.bf16.f32 "
        "{%0,%1,%2,%3}, {%4,%5,%6,%7}, {%8,%9}, {%0,%1,%2,%3};"
        : "+f"(d[0]), "+f"(d[1]), "+f"(d[2]), "+f"(d[3])
        : "r"(a[0]), "r"(a[1]), "r"(a[2]), "r"(a[3]), "r"(b[0]), "r"(b[1]));
}

__device__ __forceinline__ ull pack_hi4(float4 v, float4* rem) {
    __nv_bfloat16 h0 = __float2bfloat16_rn(v.x);
    __nv_bfloat16 h1 = __float2bfloat16_rn(v.y);
    __nv_bfloat16 h2 = __float2bfloat16_rn(v.z);
    __nv_bfloat16 h3 = __float2bfloat16_rn(v.w);
    rem->x = v.x - __bfloat162float(h0);
    rem->y = v.y - __bfloat162float(h1);
    rem->z = v.z - __bfloat162float(h2);
    rem->w = v.w - __bfloat162float(h3);
    return (ull)__bfloat16_as_ushort(h0) |
           ((ull)__bfloat16_as_ushort(h1) << 16) |
           ((ull)__bfloat16_as_ushort(h2) << 32) |
           ((ull)__bfloat16_as_ushort(h3) << 48);
}
__device__ __forceinline__ ull pack_lo4(float4 v) {
    return (ull)__bfloat16_as_ushort(__float2bfloat16_rn(v.x)) |
           ((ull)__bfloat16_as_ushort(__float2bfloat16_rn(v.y)) << 16) |
           ((ull)__bfloat16_as_ushort(__float2bfloat16_rn(v.z)) << 32) |
           ((ull)__bfloat16_as_ushort(__float2bfloat16_rn(v.w)) << 48);
}
__device__ __forceinline__ void pack_hl(float v, __nv_bfloat16* hi, __nv_bfloat16* lo) {
    __nv_bfloat16 h = __float2bfloat16_rn(v);
    *hi = h;
    *lo = __float2bfloat16_rn(v - __bfloat162float(h));
}

// ===========================================================================
// conversion kernels (fused)
// ===========================================================================
// fcw (131072 float4) + wih (131072 float4) in one kernel
__global__ __launch_bounds__(256)
void cvt_hilo2(const float4* __restrict__ s1, ull* __restrict__ h1v, ull* __restrict__ l1v,
               const float4* __restrict__ s2, ull* __restrict__ h2v, ull* __restrict__ l2v)
{
    const int i = blockIdx.x * 256 + threadIdx.x;
    const float4* src = (i < 131072) ? s1 : s2;
    ull* hi = (i < 131072) ? h1v : h2v;
    ull* lo = (i < 131072) ? l1v : l2v;
    const int j = (i < 131072) ? i : i - 131072;
    float4 v = src[j];
    float4 rem;
    hi[j] = pack_hi4(v, &rem);
    lo[j] = pack_lo4(rem);
}

// c1w (2048) + c2w (8192) + c3w (9216) in one kernel: 19456 items
__global__ __launch_bounds__(256)
void cvt_weights(const float* __restrict__ w1, const float* __restrict__ w2,
                 const float* __restrict__ w3,
                 ull* __restrict__ c1h, ull* __restrict__ c1l,
                 ull* __restrict__ c2h, ull* __restrict__ c2l,
                 ull* __restrict__ c3h, ull* __restrict__ c3l)
{
    int idx = blockIdx.x * 256 + threadIdx.x;
    if (idx < 2048) {
        const int q  = idx >> 9;
        const int oc = (idx >> 4) & 31;
        const int cs = idx & 15;
        const int c = cs >> 2, s = cs & 3;
        const int dh = q >> 1, dw = q & 1;
        float4 v = *(const float4*)(w1 + (size_t)((oc * 4 + c) * 8 + 4 * dh + s) * 8 + 4 * dw);
        float4 rem;
        c1h[idx] = pack_hi4(v, &rem);
        c1l[idx] = pack_lo4(rem);
    } else if (idx < 10240) {
        idx -= 2048;
        const int dh = idx >> 12;
        const int dw = (idx >> 11) & 1;
        const int oc = (idx >> 5) & 63;
        const int c  = idx & 31;
        const float* wp = w2 + (size_t)(oc * 32 + c) * 16;
        float4 v;
        v.x = wp[(2 * dh) * 4 + 2 * dw];
        v.y = wp[(2 * dh) * 4 + 2 * dw + 1];
        v.z = wp[(2 * dh + 1) * 4 + 2 * dw];
        v.w = wp[(2 * dh + 1) * 4 + 2 * dw + 1];
        float4 rem;
        const int row = dh * 128 + dw * 64 + oc;
        c2h[row * 32 + c] = pack_hi4(v, &rem);
        c2l[row * 32 + c] = pack_lo4(rem);
    } else if (idx < 19456) {
        idx -= 10240;
        const int off = idx >> 10;
        const int r   = idx & 1023;
        const int oc  = r >> 4;
        const int icq = r & 15;
        float4 v;
        v.x = w3[(size_t)(oc * 64 + icq * 4 + 0) * 9 + off];
        v.y = w3[(size_t)(oc * 64 + icq * 4 + 1) * 9 + off];
        v.z = w3[(size_t)(oc * 64 + icq * 4 + 2) * 9 + off];
        v.w = w3[(size_t)(oc * 64 + icq * 4 + 3) * 9 + off];
        float4 rem;
        c3h[idx] = pack_hi4(v, &rem);
        c3l[idx] = pack_lo4(rem);
    }
}

// ===========================================================================
// conv1 via mma.sync (bf16x3) — R10/R11 validated
// ===========================================================================
#define A_STRIDE 144
#define A_BYTES  (273 * A_STRIDE)
#define BQ_BYTES (32 * A_STRIDE)
#define OFF_AHI  128
#define OFF_ALO  (OFF_AHI + A_BYTES)
#define OFF_BHI  (OFF_ALO + A_BYTES)
#define OFF_BLO  (OFF_BHI + 4 * BQ_BYTES)
#define C1_SMEM  (OFF_BLO + 4 * BQ_BYTES)

__global__ __launch_bounds__(256, 1)
void conv1_mma_kernel(const float* __restrict__ x,
                      const ull* __restrict__ c1wh, const ull* __restrict__ c1wl,
                      const float* __restrict__ bias,
                      __nv_bfloat16* __restrict__ oAh, __nv_bfloat16* __restrict__ oAl)
{
    extern __shared__ __align__(16) char smem[];
    float* sbias = (float*)smem;
    char* Ahi = smem + OFF_AHI;
    char* Alo = smem + OFF_ALO;
    char* Bhi = smem + OFF_BHI;
    char* Blo = smem + OFF_BLO;

    const int tid = threadIdx.x;
    const int n = blockIdx.x;
    const float inv255 = 1.0f / 255.0f;

    if (tid < 32) sbias[tid] = bias[tid];

    for (int idx = tid; idx < 4096; idx += 256) {
        const int row = idx >> 4;
        const int cs  = idx & 15;
        const int c = cs >> 2, s = cs & 3;
        const int gh = row >> 4, gw = row & 15;
        float4 v = *(const float4*)(x + (size_t)((n * 4 + c) * 64 + 4 * gh + s) * 64 + 4 * gw);
        v.x *= inv255; v.y *= inv255; v.z *= inv255; v.w *= inv255;
        float4 rem;
        const ull ph = pack_hi4(v, &rem);
        const ull pl = pack_lo4(rem);
        const int off = row * A_STRIDE + cs * 8;
        *(ull*)(Ahi + off) = ph;
        *(ull*)(Alo + off) = pl;
    }
    for (int i = tid; i < 612; i += 256) {
        const int half = i / 306;
        const int off = 256 * A_STRIDE + (i - half * 306) * 8;
        *(ull*)((half ? Alo : Ahi) + off) = 0ull;
    }
    for (int i = tid; i < 2048; i += 256) {
        const int q = i >> 9, oc = (i >> 4) & 31, cs = i & 15;
        const int off = q * BQ_BYTES + oc * A_STRIDE + cs * 8;
        *(ull*)(Bhi + off) = c1wh[i];
        *(ull*)(Blo + off) = c1wl[i];
    }
    __syncthreads();

    const int wid = tid >> 5, lane = tid & 31;
    const int g = lane >> 2, t = lane & 3;

    float acc[2][4][4];
    #pragma unroll
    for (int m = 0; m < 2; m++)
        #pragma unroll
        for (int nt = 0; nt < 4; nt++)
            #pragma unroll
            for (int r = 0; r < 4; r++) acc[m][nt][r] = 0.0f;

    const int mt0 = wid, mt1 = wid + 8;

    #pragma unroll
    for (int q = 0; q < 4; q++) {
        const int r0 = (q >> 1) * 16 + (q & 1);
        const char* Bq_hi = Bhi + q * BQ_BYTES;
        const char* Bq_lo = Blo + q * BQ_BYTES;
        const int arow0 = (mt0 * 16 + r0 + g) * A_STRIDE;
        const int arow1 = (mt1 * 16 + r0 + g) * A_STRIDE;

        #pragma unroll
        for (int ks = 0; ks < 4; ks++) {
            const int co = ks * 32 + t * 4;
            u32 ahi[2][4], alo[2][4], bhi[4][2], blo[4][2];
            #pragma unroll
            for (int m = 0; m < 2; m++) {
                const int rb = (m ? arow1 : arow0) + co;
                ahi[m][0] = *(const u32*)(Ahi + rb);
                ahi[m][1] = *(const u32*)(Ahi + rb + 8 * A_STRIDE);
                ahi[m][2] = *(const u32*)(Ahi + rb + 16);
                ahi[m][3] = *(const u32*)(Ahi + rb + 8 * A_STRIDE + 16);
                alo[m][0] = *(const u32*)(Alo + rb);
                alo[m][1] = *(const u32*)(Alo + rb + 8 * A_STRIDE);
                alo[m][2] = *(const u32*)(Alo + rb + 16);
                alo[m][3] = *(const u32*)(Alo + rb + 8 * A_STRIDE + 16);
            }
            #pragma unroll
            for (int nt = 0; nt < 4; nt++) {
                const int bo = (nt * 8 + g) * A_STRIDE + co;
                bhi[nt][0] = *(const u32*)(Bq_hi + bo);
                bhi[nt][1] = *(const u32*)(Bq_hi + bo + 16);
                blo[nt][0] = *(const u32*)(Bq_lo + bo);
                blo[nt][1] = *(const u32*)(Bq_lo + bo + 16);
            }
            #pragma unroll
            for (int m = 0; m < 2; m++)
                #pragma unroll
                for (int nt = 0; nt < 4; nt++) {
                    mma16816(acc[m][nt], ahi[m], bhi[nt]);
                    mma16816(acc[m][nt], alo[m], bhi[nt]);
                    mma16816(acc[m][nt], ahi[m], blo[nt]);
                }
        }
    }

    __nv_bfloat16* oh_b = oAh + (size_t)n * 8192;
    __nv_bfloat16* ol_b = oAl + (size_t)n * 8192;
    #pragma unroll
    for (int m = 0; m < 2; m++) {
        const int mt = m ? mt1 : mt0;
        #pragma unroll
        for (int half = 0; half < 2; half++) {
            const int r = mt * 16 + g + half * 8;
            const int oh = r >> 4, ow = r & 15;
            const bool valid = (oh < 15) && (ow < 15);
            const int prow = (oh >> 1) * 8 + (ow >> 1);
            const int sp = (oh & 1) * 2 + (ow & 1);
            const int base = prow * 128 + sp;
            #pragma unroll
            for (int nt = 0; nt < 4; nt++) {
                const int c0 = nt * 8 + 2 * t;
                float v0 = 0.0f, v1 = 0.0f;
                if (valid) {
                    v0 = acc[m][nt][half * 2]     + sbias[c0];
                    v1 = acc[m][nt][half * 2 + 1] + sbias[c0 + 1];
                    v0 = v0 > 0.0f ? v0 : 0.0f;
                    v1 = v1 > 0.0f ? v1 : 0.0f;
                }
                __nv_bfloat16 h, l;
                pack_hl(v0, &h, &l);
                oh_b[base + c0 * 4] = h;
                ol_b[base + c0 * 4] = l;
                pack_hl(v1, &h, &l);
                oh_b[base + (c0 + 1) * 4] = h;
                ol_b[base + (c0 + 1) * 4] = l;
            }
        }
    }
}

// ===========================================================================
// conv2 via mma.sync (bf16x3) — R10/R11 validated
// ===========================================================================
#define C2_STRIDE  272
#define C2_A_SZ    (144 * C2_STRIDE)
#define C2_B_SZ    (256 * C2_STRIDE)
#define C2_OFF_AHI 512
#define C2_OFF_ALO (C2_OFF_AHI + C2_A_SZ)
#define C2_OFF_BHI (C2_OFF_ALO + C2_A_SZ)
#define C2_OFF_BLO (C2_OFF_BHI + C2_B_SZ)
#define C2_SMEM    (C2_OFF_BLO + C2_B_SZ)

__global__ __launch_bounds__(256, 1)
void conv2_mma_kernel(const __nv_bfloat16* __restrict__ Agh, const __nv_bfloat16* __restrict__ Agl,
                      const ull* __restrict__ c2wh, const ull* __restrict__ c2wl,
                      const float* __restrict__ bias, float* __restrict__ out)
{
    extern __shared__ __align__(16) char smem[];
    float* sbias = (float*)smem;
    char* Ahi = smem + C2_OFF_AHI;
    char* Alo = smem + C2_OFF_ALO;
    char* Bhi = smem + C2_OFF_BHI;
    char* Blo = smem + C2_OFF_BLO;

    const int tid = threadIdx.x;
    const int nb = blockIdx.x * 2;

    if (tid < 64) sbias[tid] = bias[tid];

    {
        const ulonglong2* sh = (const ulonglong2*)(Agh + (size_t)nb * 8192);
        const ulonglong2* sl = (const ulonglong2*)(Agl + (size_t)nb * 8192);
        for (int idx = tid; idx < 2048; idx += 256) {
            const int row = idx >> 4, ch = idx & 15;
            *(ulonglong2*)(Ahi + row * C2_STRIDE + ch * 16) = sh[idx];
            *(ulonglong2*)(Alo + row * C2_STRIDE + ch * 16) = sl[idx];
        }
    }
    for (int i = tid; i < 512; i += 256) {
        const int half = i >> 8;
        const int j = i & 255;
        const int off = (128 + (j >> 4)) * C2_STRIDE + (j & 15) * 16;
        ulonglong2 z; z.x = 0; z.y = 0;
        *(ulonglong2*)((half ? Alo : Ahi) + off) = z;
    }
    {
        const ulonglong2* sh = (const ulonglong2*)c2wh;
        const ulonglong2* sl = (const ulonglong2*)c2wl;
        for (int idx = tid; idx < 4096; idx += 256) {
            const int row = idx >> 4, ch = idx & 15;
            *(ulonglong2*)(Bhi + row * C2_STRIDE + ch * 16) = sh[idx];
            *(ulonglong2*)(Blo + row * C2_STRIDE + ch * 16) = sl[idx];
        }
    }
    __syncthreads();

    const int wid = tid >> 5, lane = tid & 31;
    const int g = lane >> 2, t = lane & 3;

    float acc[8][4];
    #pragma unroll
    for (int nt = 0; nt < 8; nt++)
        #pragma unroll
        for (int r = 0; r < 4; r++) acc[nt][r] = 0.0f;

    #pragma unroll
    for (int q = 0; q < 4; q++) {
        const int dh = q >> 1, dw = q & 1;
        const int roff = dh * 8 + dw;
        const char* Bq_hi = Bhi + (dh * 128 + dw * 64) * C2_STRIDE;
        const char* Bq_lo = Blo + (dh * 128 + dw * 64) * C2_STRIDE;
        const int arow = (wid * 16 + roff + g) * C2_STRIDE;

        #pragma unroll
        for (int ks = 0; ks < 8; ks++) {
            const int co = ks * 32 + t * 4;
            u32 ahi[4], alo[4], bhi[8][2], blo[8][2];
            const int rb = arow + co;
            ahi[0] = *(const u32*)(Ahi + rb);
            ahi[1] = *(const u32*)(Ahi + rb + 8 * C2_STRIDE);
            ahi[2] = *(const u32*)(Ahi + rb + 16);
            ahi[3] = *(const u32*)(Ahi + rb + 8 * C2_STRIDE + 16);
            alo[0] = *(const u32*)(Alo + rb);
            alo[1] = *(const u32*)(Alo + rb + 8 * C2_STRIDE);
            alo[2] = *(const u32*)(Alo + rb + 16);
            alo[3] = *(const u32*)(Alo + rb + 8 * C2_STRIDE + 16);
            #pragma unroll
            for (int nt = 0; nt < 8; nt++) {
                const int bo = (nt * 8 + g) * C2_STRIDE + co;
                bhi[nt][0] = *(const u32*)(Bq_hi + bo);
                bhi[nt][1] = *(const u32*)(Bq_hi + bo + 16);
                blo[nt][0] = *(const u32*)(Bq_lo + bo);
                blo[nt][1] = *(const u32*)(Bq_lo + bo + 16);
            }
            #pragma unroll
            for (int nt = 0; nt < 8; nt++) {
                mma16816(acc[nt], ahi, bhi[nt]);
                mma16816(acc[nt], alo, bhi[nt]);
                mma16816(acc[nt], ahi, blo[nt]);
            }
        }
    }

    #pragma unroll
    for (int half = 0; half < 2; half++) {
        const int r = wid * 16 + g + half * 8;
        const int im = r >> 6;
        const int rl = r & 63;
        const int oh = rl >> 3, ow = rl & 7;
        if (oh < 6 && ow < 6) {
            float* ob = out + (size_t)(nb + im) * 2304 + oh * 6 + ow;
            #pragma unroll
            for (int nt = 0; nt < 8; nt++) {
                const int oc = nt * 8 + 2 * t;
                float v0 = acc[nt][half * 2]     + sbias[oc];
                float v1 = acc[nt][half * 2 + 1] + sbias[oc + 1];
                ob[oc * 36]       = v0 > 0.0f ? v0 : 0.0f;
                ob[(oc + 1) * 36] = v1 > 0.0f ? v1 : 0.0f;
            }
        }
    }
}

// ===========================================================================
// conv3 via mma.sync (bf16x3) — R12 validated
// ===========================================================================
#define C3_XSTR  144
#define C3_IMG   (36 * C3_XSTR)
#define C3_XHI   256
#define C3_XLO   (C3_XHI + 4 * C3_IMG)
#define C3_BHI   (C3_XLO + 4 * C3_IMG)
#define C3_B_SZ  (576 * C3_XSTR)
#define C3_BLO   (C3_BHI + C3_B_SZ)
#define C3_SMEM  (C3_BLO + C3_B_SZ)

__global__ __launch_bounds__(256, 1)
void conv3_mma_kernel(const float* __restrict__ in,
                      const ull* __restrict__ c3wh, const ull* __restrict__ c3wl,
                      const float* __restrict__ bias,
                      __nv_bfloat16* __restrict__ oh_g, __nv_bfloat16* __restrict__ ol_g)
{
    extern __shared__ __align__(16) char smem[];
    float* sbias = (float*)smem;
    char* Xhi = smem + C3_XHI;
    char* Xlo = smem + C3_XLO;
    char* Bhi = smem + C3_BHI;
    char* Blo = smem + C3_BLO;

    const int tid = threadIdx.x;
    const int n4 = blockIdx.x * 4;

    if (tid < 64) sbias[tid] = bias[tid];

    for (int idx = tid; idx < 2304; idx += 256) {
        const int im = idx / 576;
        const int r  = idx - im * 576;
        const int ic = r / 9;
        const int pg = r - ic * 9;
        float4 v = *(const float4*)(in + (size_t)(n4 + im) * 2304 + ic * 36 + pg * 4);
        char* xh = Xhi + im * C3_IMG;
        char* xl = Xlo + im * C3_IMG;
        __nv_bfloat16 h, l;
        pack_hl(v.x, &h, &l);
        *(__nv_bfloat16*)(xh + (pg * 4 + 0) * C3_XSTR + ic * 2) = h;
        *(__nv_bfloat16*)(xl + (pg * 4 + 0) * C3_XSTR + ic * 2) = l;
        pack_hl(v.y, &h, &l);
        *(__nv_bfloat16*)(xh + (pg * 4 + 1) * C3_XSTR + ic * 2) = h;
        *(__nv_bfloat16*)(xl + (pg * 4 + 1) * C3_XSTR + ic * 2) = l;
        pack_hl(v.z, &h, &l);
        *(__nv_bfloat16*)(xh + (pg * 4 + 2) * C3_XSTR + ic * 2) = h;
        *(__nv_bfloat16*)(xl + (pg * 4 + 2) * C3_XSTR + ic * 2) = l;
        pack_hl(v.w, &h, &l);
        *(__nv_bfloat16*)(xh + (pg * 4 + 3) * C3_XSTR + ic * 2) = h;
        *(__nv_bfloat16*)(xl + (pg * 4 + 3) * C3_XSTR + ic * 2) = l;
    }
    for (int idx = tid; idx < 9216; idx += 256) {
        const int row = idx >> 4, c = idx & 15;
        *(ull*)(Bhi + row * C3_XSTR + c * 8) = c3wh[idx];
        *(ull*)(Blo + row * C3_XSTR + c * 8) = c3wl[idx];
    }
    __syncthreads();

    const int wid = tid >> 5, lane = tid & 31;
    const int g = lane >> 2, t = lane & 3;
    const int img = wid & 3;
    const int oc0 = (wid >> 2) * 32;
    const int n = n4 + img;

    float acc[4][4];
    #pragma unroll
    for (int nt = 0; nt < 4; nt++)
        #pragma unroll
        for (int r = 0; r < 4; r++) acc[nt][r] = 0.0f;

    const int ri_g = (g >> 2) * 6 + (g & 3);
    const char* Xh = Xhi + img * C3_IMG;
    const char* Xl = Xlo + img * C3_IMG;

    #pragma unroll
    for (int off = 0; off < 9; off++) {
        const int kh = off / 3, kw = off - kh * 3;
        const int rowA = (ri_g + kh * 6 + kw) * C3_XSTR;
        const char* Bo_hi = Bhi + (off * 64 + oc0) * C3_XSTR;
        const char* Bo_lo = Blo + (off * 64 + oc0) * C3_XSTR;

        #pragma unroll
        for (int ks = 0; ks < 4; ks++) {
            const int co = ks * 32 + t * 4;
            u32 ahi[4], alo[4], bhi[4][2], blo[4][2];
            const int rb = rowA + co;
            ahi[0] = *(const u32*)(Xh + rb);
            ahi[1] = *(const u32*)(Xh + rb + 12 * C3_XSTR);
            ahi[2] = *(const u32*)(Xh + rb + 16);
            ahi[3] = *(const u32*)(Xh + rb + 12 * C3_XSTR + 16);
            alo[0] = *(const u32*)(Xl + rb);
            alo[1] = *(const u32*)(Xl + rb + 12 * C3_XSTR);
            alo[2] = *(const u32*)(Xl + rb + 16);
            alo[3] = *(const u32*)(Xl + rb + 12 * C3_XSTR + 16);
            #pragma unroll
            for (int nt = 0; nt < 4; nt++) {
                const int bo = (nt * 8 + g) * C3_XSTR + co;
                bhi[nt][0] = *(const u32*)(Bo_hi + bo);
                bhi[nt][1] = *(const u32*)(Bo_hi + bo + 16);
                blo[nt][0] = *(const u32*)(Bo_lo + bo);
                blo[nt][1] = *(const u32*)(Bo_lo + bo + 16);
            }
            #pragma unroll
            for (int nt = 0; nt < 4; nt++) {
                mma16816(acc[nt], ahi, bhi[nt]);
                mma16816(acc[nt], alo, bhi[nt]);
                mma16816(acc[nt], ahi, blo[nt]);
            }
        }
    }

    __nv_bfloat16* po = oh_g + (size_t)n * 1024;
    __nv_bfloat16* pl = ol_g + (size_t)n * 1024;
    #pragma unroll
    for (int nt = 0; nt < 4; nt++) {
        const int oc = oc0 + nt * 8 + 2 * t;
        const float b0 = sbias[oc], b1 = sbias[oc + 1];
        float v0 = acc[nt][0] + b0;  v0 = v0 > 0.0f ? v0 : 0.0f;
        float v1 = acc[nt][1] + b1;  v1 = v1 > 0.0f ? v1 : 0.0f;
        float v2 = acc[nt][2] + b0;  v2 = v2 > 0.0f ? v2 : 0.0f;
        float v3 = acc[nt][3] + b1;  v3 = v3 > 0.0f ? v3 : 0.0f;
        __nv_bfloat16 h, l;
        pack_hl(v0, &h, &l); po[oc * 16 + g] = h;           pl[oc * 16 + g] = l;
        pack_hl(v1, &h, &l); po[(oc + 1) * 16 + g] = h;     pl[(oc + 1) * 16 + g] = l;
        pack_hl(v2, &h, &l); po[oc * 16 + g + 8] = h;       pl[oc * 16 + g + 8] = l;
        pack_hl(v3, &h, &l); po[(oc + 1) * 16 + g + 8] = h; pl[(oc + 1) * 16 + g + 8] = l;
    }
}

// ===========================================================================
// GEMM (NT) via mma.sync on pre-converted bf16 hi/lo inputs (R9 validated)
// ===========================================================================
template <bool RELU, bool OUTBF>
__global__ __launch_bounds__(256, 2)
void gemm_hmma_pre(const __nv_bfloat16* __restrict__ Ah, const __nv_bfloat16* __restrict__ Al,
                   const __nv_bfloat16* __restrict__ Bh, const __nv_bfloat16* __restrict__ Bl,
                   const float* __restrict__ b1, const float* __restrict__ b2,
                   float* __restrict__ C,
                   __nv_bfloat16* __restrict__ Chi, __nv_bfloat16* __restrict__ Clo,
                   int K, int N)
{
    __shared__ __align__(16) char Ahi_s[128 * 80];
    __shared__ __align__(16) char Alo_s[128 * 80];
    __shared__ __align__(16) char Bhi_s[64 * 80];
    __shared__ __align__(16) char Blo_s[64 * 80];

    const int tid = threadIdx.x;
    const int m0 = blockIdx.y * 128;
    const int n0 = blockIdx.x * 64;
    const int wid = tid >> 5, lane = tid & 31;
    const int g = lane >> 2, t = lane & 3;
    const int wm = wid & 3;
    const int wn = wid >> 2;

    const int arow0 = tid >> 2;
    const int arow1 = (tid >> 2) + 64;
    const int brow  = tid >> 2;
    const int cgrp  = (tid & 3) * 8;

    float acc[2][4][4];
    #pragma unroll
    for (int ms = 0; ms < 2; ms++)
        #pragma unroll
        for (int nt = 0; nt < 4; nt++)
            #pragma unroll
            for (int r = 0; r < 4; r++) acc[ms][nt][r] = 0.0f;

    ulonglong2 pah0, pah1, pal0, pal1, pbh, pbl;
    pah0 = *(const ulonglong2*)(Ah + (size_t)(m0 + arow0) * K + cgrp);
    pah1 = *(const ulonglong2*)(Ah + (size_t)(m0 + arow1) * K + cgrp);
    pal0 = *(const ulonglong2*)(Al + (size_t)(m0 + arow0) * K + cgrp);
    pal1 = *(const ulonglong2*)(Al + (size_t)(m0 + arow1) * K + cgrp);
    pbh  = *(const ulonglong2*)(Bh + (size_t)(n0 + brow) * K + cgrp);
    pbl  = *(const ulonglong2*)(Bl + (size_t)(n0 + brow) * K + cgrp);

    for (int k0 = 0; k0 < K; k0 += 32) {
        *(ulonglong2*)(Ahi_s + arow0 * 80 + cgrp * 2) = pah0;
        *(ulonglong2*)(Ahi_s + arow1 * 80 + cgrp * 2) = pah1;
        *(ulonglong2*)(Alo_s + arow0 * 80 + cgrp * 2) = pal0;
        *(ulonglong2*)(Alo_s + arow1 * 80 + cgrp * 2) = pal1;
        *(ulonglong2*)(Bhi_s + brow * 80 + cgrp * 2) = pbh;
        *(ulonglong2*)(Blo_s + brow * 80 + cgrp * 2) = pbl;
        __syncthreads();

        if (k0 + 32 < K) {
            const int kn = k0 + 32;
            pah0 = *(const ulonglong2*)(Ah + (size_t)(m0 + arow0) * K + kn + cgrp);
            pah1 = *(const ulonglong2*)(Ah + (size_t)(m0 + arow1) * K + kn + cgrp);
            pal0 = *(const ulonglong2*)(Al + (size_t)(m0 + arow0) * K + kn + cgrp);
            pal1 = *(const ulonglong2*)(Al + (size_t)(m0 + arow1) * K + kn + cgrp);
            pbh  = *(const ulonglong2*)(Bh + (size_t)(n0 + brow) * K + kn + cgrp);
            pbl  = *(const ulonglong2*)(Bl + (size_t)(n0 + brow) * K + kn + cgrp);
        }

        #pragma unroll
        for (int ks = 0; ks < 2; ks++) {
            const int co = ks * 32 + t * 4;
            u32 ahi[2][4], alo[2][4], bhi[4][2], blo[4][2];
            #pragma unroll
            for (int ms = 0; ms < 2; ms++) {
                const int rb = (wm * 32 + ms * 16 + g) * 80 + co;
                ahi[ms][0] = *(const u32*)(Ahi_s + rb);
                ahi[ms][1] = *(const u32*)(Ahi_s + rb + 8 * 80);
                ahi[ms][2] = *(const u32*)(Ahi_s + rb + 16);
                ahi[ms][3] = *(const u32*)(Ahi_s + rb + 8 * 80 + 16);
                alo[ms][0] = *(const u32*)(Alo_s + rb);
                alo[ms][1] = *(const u32*)(Alo_s + rb + 8 * 80);
                alo[ms][2] = *(const u32*)(Alo_s + rb + 16);
                alo[ms][3] = *(const u32*)(Alo_s + rb + 8 * 80 + 16);
            }
            #pragma unroll
            for (int nt = 0; nt < 4; nt++) {
                const int bo = (wn * 32 + nt * 8 + g) * 80 + co;
                bhi[nt][0] = *(const u32*)(Bhi_s + bo);
                bhi[nt][1] = *(const u32*)(Bhi_s + bo + 16);
                blo[nt][0] = *(const u32*)(Blo_s + bo);
                blo[nt][1] = *(const u32*)(Blo_s + bo + 16);
            }
            #pragma unroll
            for (int ms = 0; ms < 2; ms++)
                #pragma unroll
                for (int nt = 0; nt < 4; nt++) {
                    mma16816(acc[ms][nt], ahi[ms], bhi[nt]);
                    mma16816(acc[ms][nt], alo[ms], bhi[nt]);
                    mma16816(acc[ms][nt], ahi[ms], blo[nt]);
                }
        }
        __syncthreads();
    }

    #pragma unroll
    for (int ms = 0; ms < 2; ms++) {
        #pragma unroll
        for (int half = 0; half < 2; half++) {
            const int row = m0 + wm * 32 + ms * 16 + g + half * 8;
            #pragma unroll
            for (int nt = 0; nt < 4; nt++) {
                const int col = n0 + wn * 32 + nt * 8 + 2 * t;
                float bb0 = b1[col]     + (b2 ? b2[col]     : 0.0f);
                float bb1 = b1[col + 1] + (b2 ? b2[col + 1] : 0.0f);
                float v0 = acc[ms][nt][half * 2]     + bb0;
                float v1 = acc[ms][nt][half * 2 + 1] + bb1;
                if (RELU) { v0 = v0 > 0.0f ? v0 : 0.0f; v1 = v1 > 0.0f ? v1 : 0.0f; }
                if (OUTBF) {
                    __nv_bfloat16 h0, l0, h1, l1;
                    pack_hl(v0, &h0, &l0);
                    pack_hl(v1, &h1, &l1);
                    __nv_bfloat162 ph; ph.x = h0; ph.y = h1;
                    __nv_bfloat162 pl; pl.x = l0; pl.y = l1;
                    *(__nv_bfloat162*)(Chi + (size_t)row * N + col) = ph;
                    *(__nv_bfloat162*)(Clo + (size_t)row * N + col) = pl;
                } else {
                    C[(size_t)row * N + col]     = v0;
                    C[(size_t)row * N + col + 1] = v1;
                }
            }
        }
    }
}

// ===========================================================================
// LSTM v3: 128 blocks x 256 threads, 2 hidden cols per block.
// Thread = (batch b, col jj, gate gh): one 256-dot per thread per step.
// ws stride 260 -> conflict-free 8-row weight fragment loads.
// ===========================================================================
__global__ __launch_bounds__(256, 1)
void lstm3_kernel(const float* __restrict__ gx, const float* __restrict__ whh,
                  const int* __restrict__ done,
                  const float* __restrict__ h0, const float* __restrict__ c0,
                  float* __restrict__ out)
{
    extern __shared__ float sm[];
    float* ws     = sm;                    // 8 rows, stride WSTR
    float* h_s    = sm + 8 * WSTR;         // 32 rows, stride 264
    float* gate_s = h_s + 32 * 264;        // 256
    float* c_s    = gate_s + 256;          // 64

    const int tid = threadIdx.x;
    const int j0 = blockIdx.x * 2;

    // ws row r = gh*2 + jj  <-  whh[(gh*256 + j0 + jj) * 256 + :]
    #pragma unroll
    for (int l = 0; l < 2; l++) {
        const int id = tid + l * 256;      // 0..511
        const int r = id >> 6;
        const int c4 = (id & 63) * 4;
        *(float4*)(ws + r * WSTR + c4) =
            *(const float4*)(whh + (size_t)((r >> 1) * 256 + j0 + (r & 1)) * 256 + c4);
    }
    if (tid < 64) {
        const int b = tid >> 1, jj = tid & 1;
        c_s[tid] = c0[b * 256 + j0 + jj];
    }
    unsigned bar_gen = 0;
    if (tid == 0) bar_gen = *((volatile unsigned*)&g_gen);
    __syncthreads();

    const int u = tid & 7;
    const int b = tid >> 3;
    const int jj = u & 1, gh = u >> 1;
    const float* w0 = ws + (gh * 2 + jj) * WSTR;
    const float* hb = h_s + b * 264;

    for (int t = 0; t < 64; t++) {
        const float* hsrc = (t == 0) ? h0 : g_hbuf[(t - 1) & 1];
        const int* dn = done + t * 32;
        #pragma unroll
        for (int l = 0; l < 8; l++) {
            const int f = tid + l * 256;
            const int bb = f >> 6;
            const int kc = (f & 63) * 4;
            const float m = 1.0f - (float)dn[bb];
            float4 v = *(const float4*)(hsrc + bb * 256 + kc);
            v.x *= m; v.y *= m; v.z *= m; v.w *= m;
            *(float4*)(h_s + bb * 264 + kc) = v;
        }
        __syncthreads();

        float s0 = 0, s1 = 0, s2 = 0, s3 = 0;
        #pragma unroll 8
        for (int k = 0; k < 256; k += 4) {
            const float4 h4 = *(const float4*)(hb + k);
            const float4 wa = *(const float4*)(w0 + k);
            s0 += h4.x * wa.x;  s1 += h4.y * wa.y;
            s2 += h4.z * wa.z;  s3 += h4.w * wa.w;
        }
        const int row = t * 32 + b;
        const float gv = ((s0 + s1) + (s2 + s3)) +
                         gx[(size_t)row * 1024 + gh * 256 + j0 + jj];
        gate_s[(b * 2 + jj) * 4 + gh] = gv;
        __syncthreads();

        if (tid < 64) {
            const int bb = tid >> 1, j2 = tid & 1;
            const float* gp = gate_s + tid * 4;
            const float gi = gp[0], gf = gp[1], gg = gp[2], go = gp[3];
            const float m = 1.0f - (float)dn[bb];
            const float cold = c_s[tid] * m;
            const float si = 1.0f / (1.0f + __expf(-gi));
            const float sf = 1.0f / (1.0f + __expf(-gf));
            const float so = 1.0f / (1.0f + __expf(-go));
            const float cn = sf * cold + si * tanhf(gg);
            const float h = so * tanhf(cn);
            c_s[tid] = cn;
            const int j = j0 + j2;
            g_hbuf[t & 1][bb * 256 + j] = h;
            out[(size_t)(t * 32 + bb) * 256 + j] = h;
        }
        __threadfence();
        __syncthreads();

        if (t < 63) {
            if (tid == 0) {
                const unsigned prev = atomicAdd(&g_count, 1);
                if (prev == gridDim.x - 1) {
                    g_count = 0;
                    __threadfence();
                    atomicAdd(&g_gen, 1);
                } else {
                    while (*((volatile unsigned*)&g_gen) == bar_gen) { }
                }
                bar_gen++;
                __threadfence();
            }
            __syncthreads();
        }
    }
}

// ===========================================================================
extern "C" void kernel_launch(void* const* d_in, const int* in_sizes, int n_in,
                              void* d_out, int out_size)
{
    const float* x    = (const float*)d_in[0];
    const int*   done = (const int*)d_in[1];
    const float* w1   = (const float*)d_in[2];
    const float* b1   = (const float*)d_in[3];
    const float* w2   = (const float*)d_in[4];
    const float* b2   = (const float*)d_in[5];
    const float* w3   = (const float*)d_in[6];
    const float* b3   = (const float*)d_in[7];
    const float* fcw  = (const float*)d_in[8];
    const float* fcb  = (const float*)d_in[9];
    const float* wih  = (const float*)d_in[10];
    const float* whh  = (const float*)d_in[11];
    const float* bih  = (const float*)d_in[12];
    const float* bhh  = (const float*)d_in[13];
    const float* h0   = (const float*)d_in[14];
    const float* c0   = (const float*)d_in[15];
    float* out = (float*)d_out;

    float *buf2, *gatesx;
    __nv_bfloat16 *c2ah, *c2al, *b3h, *b3l, *fcwh, *fcwl, *wihh, *wihl, *fh, *fl;
    ull *c1wh, *c1wl, *c2wh, *c2wl, *c3wh, *c3wl;
    cudaGetSymbolAddress((void**)&buf2,   g_buf2);
    cudaGetSymbolAddress((void**)&gatesx, g_gatesx);
    cudaGetSymbolAddress((void**)&c2ah, g_c2a_h);
    cudaGetSymbolAddress((void**)&c2al, g_c2a_l);
    cudaGetSymbolAddress((void**)&c1wh, g_c1w_h);
    cudaGetSymbolAddress((void**)&c1wl, g_c1w_l);
    cudaGetSymbolAddress((void**)&c2wh, g_c2w_h);
    cudaGetSymbolAddress((void**)&c2wl, g_c2w_l);
    cudaGetSymbolAddress((void**)&c3wh, g_c3w_h);
    cudaGetSymbolAddress((void**)&c3wl, g_c3w_l);
    cudaGetSymbolAddress((void**)&b3h,  g_b3h);
    cudaGetSymbolAddress((void**)&b3l,  g_b3l);
    cudaGetSymbolAddress((void**)&fcwh, g_fcwh);
    cudaGetSymbolAddress((void**)&fcwl, g_fcwl);
    cudaGetSymbolAddress((void**)&wihh, g_wihh);
    cudaGetSymbolAddress((void**)&wihl, g_wihl);
    cudaGetSymbolAddress((void**)&fh,   g_fh);
    cudaGetSymbolAddress((void**)&fl,   g_fl);

    cudaFuncSetAttribute(conv1_mma_kernel, cudaFuncAttributeMaxDynamicSharedMemorySize, C1_SMEM);
    cudaFuncSetAttribute(conv2_mma_kernel, cudaFuncAttributeMaxDynamicSharedMemorySize, C2_SMEM);
    cudaFuncSetAttribute(conv3_mma_kernel, cudaFuncAttributeMaxDynamicSharedMemorySize, C3_SMEM);
    cudaFuncSetAttribute(lstm3_kernel, cudaFuncAttributeMaxDynamicSharedMemorySize, SMEML3);

    cvt_weights<<<76, 256>>>(w1, w2, w3, c1wh, c1wl, c2wh, c2wl, c3wh, c3wl);
    cvt_hilo2<<<1024, 256>>>((const float4*)fcw, (ull*)fcwh, (ull*)fcwl,
                             (const float4*)wih, (ull*)wihh, (ull*)wihl);
    conv1_mma_kernel<<<2048, 256, C1_SMEM>>>(x, c1wh, c1wl, b1, c2ah, c2al);
    conv2_mma_kernel<<<1024, 256, C2_SMEM>>>(c2ah, c2al, c2wh, c2wl, b2, buf2);
    conv3_mma_kernel<<<512, 256, C3_SMEM>>>(buf2, c3wh, c3wl, b3, b3h, b3l);
    gemm_hmma_pre<true, true><<<dim3(8, 16), 256>>>(
        b3h, b3l, fcwh, fcwl, fcb, nullptr, nullptr, fh, fl, 1024, 512);
    gemm_hmma_pre<false, false><<<dim3(16, 16), 256>>>(
        fh, fl, wihh, wihl, bih, bhh, gatesx, nullptr, nullptr, 512, 1024);
    lstm3_kernel<<<128, 256, SMEML3>>>(gatesx, whh, done, h0, c0, out);
}

// round 14
// speedup vs baseline: 1.4894x; 1.0278x over previous
#include <cuda_runtime.h>
#include <cuda_bf16.h>
#include <math.h>
#include <cstdint>

typedef unsigned long long ull;
typedef uint32_t u32;

// ===========================================================================
// Static scratch
// ===========================================================================
__device__ float g_buf2[2048 * 64 * 6 * 6];
__device__ float g_gatesx[2048 * 1024];
__device__ float g_hbuf[2][32 * 256];
__device__ unsigned g_count;
__device__ unsigned g_gen;
// pre-converted bf16 hi/lo operands
__device__ __nv_bfloat16 g_c2a_h[2048 * 64 * 128], g_c2a_l[2048 * 64 * 128];
__device__ ull g_c1w_h[2048], g_c1w_l[2048];
__device__ ull g_c2w_h[8192], g_c2w_l[8192];
__device__ ull g_c3w_h[9216], g_c3w_l[9216];
__device__ __nv_bfloat16 g_b3h[2048 * 1024], g_b3l[2048 * 1024];
__device__ __nv_bfloat16 g_fcwh[512 * 1024], g_fcwl[512 * 1024];
__device__ __nv_bfloat16 g_wihh[1024 * 512], g_wihl[1024 * 512];
__device__ __nv_bfloat16 g_fh[2048 * 512],  g_fl[2048 * 512];

// LSTM v3
#define WSTR 260
#define SMEML3 ((8 * WSTR + 32 * 264 + 256 + 64) * 4)

// ===========================================================================
// bf16 helpers
// ===========================================================================
__device__ __forceinline__ void mma16816(float* d, const u32* a, const u32* b) {
    asm volatile(
        "mma.sync.aligned.m16n8k16.row.col.f32.bf16.bf16.f32 "
        "{%0,%1,%2,%3}, {%4,%5,%6,%7}, {%8,%9}, {%0,%1,%2,%3};"
        : "+f"(d[0]), "+f"(d[1]), "+f"(d[2]), "+f"(d[3])
        : "r"(a[0]), "r"(a[1]), "r"(a[2]), "r"(a[3]), "r"(b[0]), "r"(b[1]));
}

__device__ __forceinline__ ull pack_hi4(float4 v, float4* rem) {
    __nv_bfloat16 h0 = __float2bfloat16_rn(v.x);
    __nv_bfloat16 h1 = __float2bfloat16_rn(v.y);
    __nv_bfloat16 h2 = __float2bfloat16_rn(v.z);
    __nv_bfloat16 h3 = __float2bfloat16_rn(v.w);
    rem->x = v.x - __bfloat162float(h0);
    rem->y = v.y - __bfloat162float(h1);
    rem->z = v.z - __bfloat162float(h2);
    rem->w = v.w - __bfloat162float(h3);
    return (ull)__bfloat16_as_ushort(h0) |
           ((ull)__bfloat16_as_ushort(h1) << 16) |
           ((ull)__bfloat16_as_ushort(h2) << 32) |
           ((ull)__bfloat16_as_ushort(h3) << 48);
}
__device__ __forceinline__ ull pack_lo4(float4 v) {
    return (ull)__bfloat16_as_ushort(__float2bfloat16_rn(v.x)) |
           ((ull)__bfloat16_as_ushort(__float2bfloat16_rn(v.y)) << 16) |
           ((ull)__bfloat16_as_ushort(__float2bfloat16_rn(v.z)) << 32) |
           ((ull)__bfloat16_as_ushort(__float2bfloat16_rn(v.w)) << 48);
}
__device__ __forceinline__ void pack_hl(float v, __nv_bfloat16* hi, __nv_bfloat16* lo) {
    __nv_bfloat16 h = __float2bfloat16_rn(v);
    *hi = h;
    *lo = __float2bfloat16_rn(v - __bfloat162float(h));
}

// ===========================================================================
// conversion kernels (fused)
// ===========================================================================
__global__ __launch_bounds__(256)
void cvt_hilo2(const float4* __restrict__ s1, ull* __restrict__ h1v, ull* __restrict__ l1v,
               const float4* __restrict__ s2, ull* __restrict__ h2v, ull* __restrict__ l2v)
{
    const int i = blockIdx.x * 256 + threadIdx.x;
    const float4* src = (i < 131072) ? s1 : s2;
    ull* hi = (i < 131072) ? h1v : h2v;
    ull* lo = (i < 131072) ? l1v : l2v;
    const int j = (i < 131072) ? i : i - 131072;
    float4 v = src[j];
    float4 rem;
    hi[j] = pack_hi4(v, &rem);
    lo[j] = pack_lo4(rem);
}

__global__ __launch_bounds__(256)
void cvt_weights(const float* __restrict__ w1, const float* __restrict__ w2,
                 const float* __restrict__ w3,
                 ull* __restrict__ c1h, ull* __restrict__ c1l,
                 ull* __restrict__ c2h, ull* __restrict__ c2l,
                 ull* __restrict__ c3h, ull* __restrict__ c3l)
{
    int idx = blockIdx.x * 256 + threadIdx.x;
    if (idx < 2048) {
        const int q  = idx >> 9;
        const int oc = (idx >> 4) & 31;
        const int cs = idx & 15;
        const int c = cs >> 2, s = cs & 3;
        const int dh = q >> 1, dw = q & 1;
        float4 v = *(const float4*)(w1 + (size_t)((oc * 4 + c) * 8 + 4 * dh + s) * 8 + 4 * dw);
        float4 rem;
        c1h[idx] = pack_hi4(v, &rem);
        c1l[idx] = pack_lo4(rem);
    } else if (idx < 10240) {
        idx -= 2048;
        const int dh = idx >> 12;
        const int dw = (idx >> 11) & 1;
        const int oc = (idx >> 5) & 63;
        const int c  = idx & 31;
        const float* wp = w2 + (size_t)(oc * 32 + c) * 16;
        float4 v;
        v.x = wp[(2 * dh) * 4 + 2 * dw];
        v.y = wp[(2 * dh) * 4 + 2 * dw + 1];
        v.z = wp[(2 * dh + 1) * 4 + 2 * dw];
        v.w = wp[(2 * dh + 1) * 4 + 2 * dw + 1];
        float4 rem;
        const int row = dh * 128 + dw * 64 + oc;
        c2h[row * 32 + c] = pack_hi4(v, &rem);
        c2l[row * 32 + c] = pack_lo4(rem);
    } else if (idx < 19456) {
        idx -= 10240;
        const int off = idx >> 10;
        const int r   = idx & 1023;
        const int oc  = r >> 4;
        const int icq = r & 15;
        float4 v;
        v.x = w3[(size_t)(oc * 64 + icq * 4 + 0) * 9 + off];
        v.y = w3[(size_t)(oc * 64 + icq * 4 + 1) * 9 + off];
        v.z = w3[(size_t)(oc * 64 + icq * 4 + 2) * 9 + off];
        v.w = w3[(size_t)(oc * 64 + icq * 4 + 3) * 9 + off];
        float4 rem;
        c3h[idx] = pack_hi4(v, &rem);
        c3l[idx] = pack_lo4(rem);
    }
}

// ===========================================================================
// conv1 via mma.sync (bf16x3) v2: 512 threads, 16 warps, 1 m-tile/warp.
// ===========================================================================
#define A_STRIDE 144
#define A_BYTES  (273 * A_STRIDE)
#define BQ_BYTES (32 * A_STRIDE)
#define OFF_AHI  128
#define OFF_ALO  (OFF_AHI + A_BYTES)
#define OFF_BHI  (OFF_ALO + A_BYTES)
#define OFF_BLO  (OFF_BHI + 4 * BQ_BYTES)
#define C1_SMEM  (OFF_BLO + 4 * BQ_BYTES)

__global__ __launch_bounds__(512, 1)
void conv1_mma_kernel(const float* __restrict__ x,
                      const ull* __restrict__ c1wh, const ull* __restrict__ c1wl,
                      const float* __restrict__ bias,
                      __nv_bfloat16* __restrict__ oAh, __nv_bfloat16* __restrict__ oAl)
{
    extern __shared__ __align__(16) char smem[];
    float* sbias = (float*)smem;
    char* Ahi = smem + OFF_AHI;
    char* Alo = smem + OFF_ALO;
    char* Bhi = smem + OFF_BHI;
    char* Blo = smem + OFF_BLO;

    const int tid = threadIdx.x;
    const int n = blockIdx.x;
    const float inv255 = 1.0f / 255.0f;

    if (tid < 32) sbias[tid] = bias[tid];

    for (int idx = tid; idx < 4096; idx += 512) {
        const int row = idx >> 4;
        const int cs  = idx & 15;
        const int c = cs >> 2, s = cs & 3;
        const int gh = row >> 4, gw = row & 15;
        float4 v = *(const float4*)(x + (size_t)((n * 4 + c) * 64 + 4 * gh + s) * 64 + 4 * gw);
        v.x *= inv255; v.y *= inv255; v.z *= inv255; v.w *= inv255;
        float4 rem;
        const ull ph = pack_hi4(v, &rem);
        const ull pl = pack_lo4(rem);
        const int off = row * A_STRIDE + cs * 8;
        *(ull*)(Ahi + off) = ph;
        *(ull*)(Alo + off) = pl;
    }
    for (int i = tid; i < 612; i += 512) {
        const int half = i / 306;
        const int off = 256 * A_STRIDE + (i - half * 306) * 8;
        *(ull*)((half ? Alo : Ahi) + off) = 0ull;
    }
    for (int i = tid; i < 2048; i += 512) {
        const int q = i >> 9, oc = (i >> 4) & 31, cs = i & 15;
        const int off = q * BQ_BYTES + oc * A_STRIDE + cs * 8;
        *(ull*)(Bhi + off) = c1wh[i];
        *(ull*)(Blo + off) = c1wl[i];
    }
    __syncthreads();

    const int wid = tid >> 5, lane = tid & 31;
    const int g = lane >> 2, t = lane & 3;
    const int mt = wid;                    // 16 warps -> 16 m-tiles

    float acc[4][4];
    #pragma unroll
    for (int nt = 0; nt < 4; nt++)
        #pragma unroll
        for (int r = 0; r < 4; r++) acc[nt][r] = 0.0f;

    #pragma unroll
    for (int q = 0; q < 4; q++) {
        const int r0 = (q >> 1) * 16 + (q & 1);
        const char* Bq_hi = Bhi + q * BQ_BYTES;
        const char* Bq_lo = Blo + q * BQ_BYTES;
        const int arow = (mt * 16 + r0 + g) * A_STRIDE;

        #pragma unroll
        for (int ks = 0; ks < 4; ks++) {
            const int co = ks * 32 + t * 4;
            u32 ahi[4], alo[4], bhi[4][2], blo[4][2];
            const int rb = arow + co;
            ahi[0] = *(const u32*)(Ahi + rb);
            ahi[1] = *(const u32*)(Ahi + rb + 8 * A_STRIDE);
            ahi[2] = *(const u32*)(Ahi + rb + 16);
            ahi[3] = *(const u32*)(Ahi + rb + 8 * A_STRIDE + 16);
            alo[0] = *(const u32*)(Alo + rb);
            alo[1] = *(const u32*)(Alo + rb + 8 * A_STRIDE);
            alo[2] = *(const u32*)(Alo + rb + 16);
            alo[3] = *(const u32*)(Alo + rb + 8 * A_STRIDE + 16);
            #pragma unroll
            for (int nt = 0; nt < 4; nt++) {
                const int bo = (nt * 8 + g) * A_STRIDE + co;
                bhi[nt][0] = *(const u32*)(Bq_hi + bo);
                bhi[nt][1] = *(const u32*)(Bq_hi + bo + 16);
                blo[nt][0] = *(const u32*)(Bq_lo + bo);
                blo[nt][1] = *(const u32*)(Bq_lo + bo + 16);
            }
            #pragma unroll
            for (int nt = 0; nt < 4; nt++) {
                mma16816(acc[nt], ahi, bhi[nt]);
                mma16816(acc[nt], alo, bhi[nt]);
                mma16816(acc[nt], ahi, blo[nt]);
            }
        }
    }

    __nv_bfloat16* oh_b = oAh + (size_t)n * 8192;
    __nv_bfloat16* ol_b = oAl + (size_t)n * 8192;
    #pragma unroll
    for (int half = 0; half < 2; half++) {
        const int r = mt * 16 + g + half * 8;
        const int oh = r >> 4, ow = r & 15;
        const bool valid = (oh < 15) && (ow < 15);
        const int prow = (oh >> 1) * 8 + (ow >> 1);
        const int sp = (oh & 1) * 2 + (ow & 1);
        const int base = prow * 128 + sp;
        #pragma unroll
        for (int nt = 0; nt < 4; nt++) {
            const int c0 = nt * 8 + 2 * t;
            float v0 = 0.0f, v1 = 0.0f;
            if (valid) {
                v0 = acc[nt][half * 2]     + sbias[c0];
                v1 = acc[nt][half * 2 + 1] + sbias[c0 + 1];
                v0 = v0 > 0.0f ? v0 : 0.0f;
                v1 = v1 > 0.0f ? v1 : 0.0f;
            }
            __nv_bfloat16 h, l;
            pack_hl(v0, &h, &l);
            oh_b[base + c0 * 4] = h;
            ol_b[base + c0 * 4] = l;
            pack_hl(v1, &h, &l);
            oh_b[base + (c0 + 1) * 4] = h;
            ol_b[base + (c0 + 1) * 4] = l;
        }
    }
}

// ===========================================================================
// conv2 via mma.sync (bf16x3) v2: 512 threads, 16 warps = (m-tile, nt-half).
// ===========================================================================
#define C2_STRIDE  272
#define C2_A_SZ    (144 * C2_STRIDE)
#define C2_B_SZ    (256 * C2_STRIDE)
#define C2_OFF_AHI 512
#define C2_OFF_ALO (C2_OFF_AHI + C2_A_SZ)
#define C2_OFF_BHI (C2_OFF_ALO + C2_A_SZ)
#define C2_OFF_BLO (C2_OFF_BHI + C2_B_SZ)
#define C2_SMEM    (C2_OFF_BLO + C2_B_SZ)

__global__ __launch_bounds__(512, 1)
void conv2_mma_kernel(const __nv_bfloat16* __restrict__ Agh, const __nv_bfloat16* __restrict__ Agl,
                      const ull* __restrict__ c2wh, const ull* __restrict__ c2wl,
                      const float* __restrict__ bias, float* __restrict__ out)
{
    extern __shared__ __align__(16) char smem[];
    float* sbias = (float*)smem;
    char* Ahi = smem + C2_OFF_AHI;
    char* Alo = smem + C2_OFF_ALO;
    char* Bhi = smem + C2_OFF_BHI;
    char* Blo = smem + C2_OFF_BLO;

    const int tid = threadIdx.x;
    const int nb = blockIdx.x * 2;

    if (tid < 64) sbias[tid] = bias[tid];

    {
        const ulonglong2* sh = (const ulonglong2*)(Agh + (size_t)nb * 8192);
        const ulonglong2* sl = (const ulonglong2*)(Agl + (size_t)nb * 8192);
        for (int idx = tid; idx < 2048; idx += 512) {
            const int row = idx >> 4, ch = idx & 15;
            *(ulonglong2*)(Ahi + row * C2_STRIDE + ch * 16) = sh[idx];
            *(ulonglong2*)(Alo + row * C2_STRIDE + ch * 16) = sl[idx];
        }
    }
    for (int i = tid; i < 512; i += 512) {
        const int half = i >> 8;
        const int j = i & 255;
        const int off = (128 + (j >> 4)) * C2_STRIDE + (j & 15) * 16;
        ulonglong2 z; z.x = 0; z.y = 0;
        *(ulonglong2*)((half ? Alo : Ahi) + off) = z;
    }
    {
        const ulonglong2* sh = (const ulonglong2*)c2wh;
        const ulonglong2* sl = (const ulonglong2*)c2wl;
        for (int idx = tid; idx < 4096; idx += 512) {
            const int row = idx >> 4, ch = idx & 15;
            *(ulonglong2*)(Bhi + row * C2_STRIDE + ch * 16) = sh[idx];
            *(ulonglong2*)(Blo + row * C2_STRIDE + ch * 16) = sl[idx];
        }
    }
    __syncthreads();

    const int wid = tid >> 5, lane = tid & 31;
    const int g = lane >> 2, t = lane & 3;
    const int mtile = wid & 7;       // 8 m-tiles (128 rows)
    const int nh = wid >> 3;         // nt half: 0 -> oc 0..31, 1 -> oc 32..63

    float acc[4][4];
    #pragma unroll
    for (int nt = 0; nt < 4; nt++)
        #pragma unroll
        for (int r = 0; r < 4; r++) acc[nt][r] = 0.0f;

    #pragma unroll
    for (int q = 0; q < 4; q++) {
        const int dh = q >> 1, dw = q & 1;
        const int roff = dh * 8 + dw;
        const char* Bq_hi = Bhi + (dh * 128 + dw * 64) * C2_STRIDE;
        const char* Bq_lo = Blo + (dh * 128 + dw * 64) * C2_STRIDE;
        const int arow = (mtile * 16 + roff + g) * C2_STRIDE;

        #pragma unroll
        for (int ks = 0; ks < 8; ks++) {
            const int co = ks * 32 + t * 4;
            u32 ahi[4], alo[4], bhi[4][2], blo[4][2];
            const int rb = arow + co;
            ahi[0] = *(const u32*)(Ahi + rb);
            ahi[1] = *(const u32*)(Ahi + rb + 8 * C2_STRIDE);
            ahi[2] = *(const u32*)(Ahi + rb + 16);
            ahi[3] = *(const u32*)(Ahi + rb + 8 * C2_STRIDE + 16);
            alo[0] = *(const u32*)(Alo + rb);
            alo[1] = *(const u32*)(Alo + rb + 8 * C2_STRIDE);
            alo[2] = *(const u32*)(Alo + rb + 16);
            alo[3] = *(const u32*)(Alo + rb + 8 * C2_STRIDE + 16);
            #pragma unroll
            for (int ntl = 0; ntl < 4; ntl++) {
                const int bo = ((nh * 4 + ntl) * 8 + g) * C2_STRIDE + co;
                bhi[ntl][0] = *(const u32*)(Bq_hi + bo);
                bhi[ntl][1] = *(const u32*)(Bq_hi + bo + 16);
                blo[ntl][0] = *(const u32*)(Bq_lo + bo);
                blo[ntl][1] = *(const u32*)(Bq_lo + bo + 16);
            }
            #pragma unroll
            for (int ntl = 0; ntl < 4; ntl++) {
                mma16816(acc[ntl], ahi, bhi[ntl]);
                mma16816(acc[ntl], alo, bhi[ntl]);
                mma16816(acc[ntl], ahi, blo[ntl]);
            }
        }
    }

    #pragma unroll
    for (int half = 0; half < 2; half++) {
        const int r = mtile * 16 + g + half * 8;
        const int im = r >> 6;
        const int rl = r & 63;
        const int oh = rl >> 3, ow = rl & 7;
        if (oh < 6 && ow < 6) {
            float* ob = out + (size_t)(nb + im) * 2304 + oh * 6 + ow;
            #pragma unroll
            for (int ntl = 0; ntl < 4; ntl++) {
                const int oc = (nh * 4 + ntl) * 8 + 2 * t;
                float v0 = acc[ntl][half * 2]     + sbias[oc];
                float v1 = acc[ntl][half * 2 + 1] + sbias[oc + 1];
                ob[oc * 36]       = v0 > 0.0f ? v0 : 0.0f;
                ob[(oc + 1) * 36] = v1 > 0.0f ? v1 : 0.0f;
            }
        }
    }
}

// ===========================================================================
// conv3 via mma.sync (bf16x3) — R12 validated
// ===========================================================================
#define C3_XSTR  144
#define C3_IMG   (36 * C3_XSTR)
#define C3_XHI   256
#define C3_XLO   (C3_XHI + 4 * C3_IMG)
#define C3_BHI   (C3_XLO + 4 * C3_IMG)
#define C3_B_SZ  (576 * C3_XSTR)
#define C3_BLO   (C3_BHI + C3_B_SZ)
#define C3_SMEM  (C3_BLO + C3_B_SZ)

__global__ __launch_bounds__(256, 1)
void conv3_mma_kernel(const float* __restrict__ in,
                      const ull* __restrict__ c3wh, const ull* __restrict__ c3wl,
                      const float* __restrict__ bias,
                      __nv_bfloat16* __restrict__ oh_g, __nv_bfloat16* __restrict__ ol_g)
{
    extern __shared__ __align__(16) char smem[];
    float* sbias = (float*)smem;
    char* Xhi = smem + C3_XHI;
    char* Xlo = smem + C3_XLO;
    char* Bhi = smem + C3_BHI;
    char* Blo = smem + C3_BLO;

    const int tid = threadIdx.x;
    const int n4 = blockIdx.x * 4;

    if (tid < 64) sbias[tid] = bias[tid];

    for (int idx = tid; idx < 2304; idx += 256) {
        const int im = idx / 576;
        const int r  = idx - im * 576;
        const int ic = r / 9;
        const int pg = r - ic * 9;
        float4 v = *(const float4*)(in + (size_t)(n4 + im) * 2304 + ic * 36 + pg * 4);
        char* xh = Xhi + im * C3_IMG;
        char* xl = Xlo + im * C3_IMG;
        __nv_bfloat16 h, l;
        pack_hl(v.x, &h, &l);
        *(__nv_bfloat16*)(xh + (pg * 4 + 0) * C3_XSTR + ic * 2) = h;
        *(__nv_bfloat16*)(xl + (pg * 4 + 0) * C3_XSTR + ic * 2) = l;
        pack_hl(v.y, &h, &l);
        *(__nv_bfloat16*)(xh + (pg * 4 + 1) * C3_XSTR + ic * 2) = h;
        *(__nv_bfloat16*)(xl + (pg * 4 + 1) * C3_XSTR + ic * 2) = l;
        pack_hl(v.z, &h, &l);
        *(__nv_bfloat16*)(xh + (pg * 4 + 2) * C3_XSTR + ic * 2) = h;
        *(__nv_bfloat16*)(xl + (pg * 4 + 2) * C3_XSTR + ic * 2) = l;
        pack_hl(v.w, &h, &l);
        *(__nv_bfloat16*)(xh + (pg * 4 + 3) * C3_XSTR + ic * 2) = h;
        *(__nv_bfloat16*)(xl + (pg * 4 + 3) * C3_XSTR + ic * 2) = l;
    }
    for (int idx = tid; idx < 9216; idx += 256) {
        const int row = idx >> 4, c = idx & 15;
        *(ull*)(Bhi + row * C3_XSTR + c * 8) = c3wh[idx];
        *(ull*)(Blo + row * C3_XSTR + c * 8) = c3wl[idx];
    }
    __syncthreads();

    const int wid = tid >> 5, lane = tid & 31;
    const int g = lane >> 2, t = lane & 3;
    const int img = wid & 3;
    const int oc0 = (wid >> 2) * 32;
    const int n = n4 + img;

    float acc[4][4];
    #pragma unroll
    for (int nt = 0; nt < 4; nt++)
        #pragma unroll
        for (int r = 0; r < 4; r++) acc[nt][r] = 0.0f;

    const int ri_g = (g >> 2) * 6 + (g & 3);
    const char* Xh = Xhi + img * C3_IMG;
    const char* Xl = Xlo + img * C3_IMG;

    #pragma unroll
    for (int off = 0; off < 9; off++) {
        const int kh = off / 3, kw = off - kh * 3;
        const int rowA = (ri_g + kh * 6 + kw) * C3_XSTR;
        const char* Bo_hi = Bhi + (off * 64 + oc0) * C3_XSTR;
        const char* Bo_lo = Blo + (off * 64 + oc0) * C3_XSTR;

        #pragma unroll
        for (int ks = 0; ks < 4; ks++) {
            const int co = ks * 32 + t * 4;
            u32 ahi[4], alo[4], bhi[4][2], blo[4][2];
            const int rb = rowA + co;
            ahi[0] = *(const u32*)(Xh + rb);
            ahi[1] = *(const u32*)(Xh + rb + 12 * C3_XSTR);
            ahi[2] = *(const u32*)(Xh + rb + 16);
            ahi[3] = *(const u32*)(Xh + rb + 12 * C3_XSTR + 16);
            alo[0] = *(const u32*)(Xl + rb);
            alo[1] = *(const u32*)(Xl + rb + 12 * C3_XSTR);
            alo[2] = *(const u32*)(Xl + rb + 16);
            alo[3] = *(const u32*)(Xl + rb + 12 * C3_XSTR + 16);
            #pragma unroll
            for (int nt = 0; nt < 4; nt++) {
                const int bo = (nt * 8 + g) * C3_XSTR + co;
                bhi[nt][0] = *(const u32*)(Bo_hi + bo);
                bhi[nt][1] = *(const u32*)(Bo_hi + bo + 16);
                blo[nt][0] = *(const u32*)(Bo_lo + bo);
                blo[nt][1] = *(const u32*)(Bo_lo + bo + 16);
            }
            #pragma unroll
            for (int nt = 0; nt < 4; nt++) {
                mma16816(acc[nt], ahi, bhi[nt]);
                mma16816(acc[nt], alo, bhi[nt]);
                mma16816(acc[nt], ahi, blo[nt]);
            }
        }
    }

    __nv_bfloat16* po = oh_g + (size_t)n * 1024;
    __nv_bfloat16* pl = ol_g + (size_t)n * 1024;
    #pragma unroll
    for (int nt = 0; nt < 4; nt++) {
        const int oc = oc0 + nt * 8 + 2 * t;
        const float b0 = sbias[oc], b1 = sbias[oc + 1];
        float v0 = acc[nt][0] + b0;  v0 = v0 > 0.0f ? v0 : 0.0f;
        float v1 = acc[nt][1] + b1;  v1 = v1 > 0.0f ? v1 : 0.0f;
        float v2 = acc[nt][2] + b0;  v2 = v2 > 0.0f ? v2 : 0.0f;
        float v3 = acc[nt][3] + b1;  v3 = v3 > 0.0f ? v3 : 0.0f;
        __nv_bfloat16 h, l;
        pack_hl(v0, &h, &l); po[oc * 16 + g] = h;           pl[oc * 16 + g] = l;
        pack_hl(v1, &h, &l); po[(oc + 1) * 16 + g] = h;     pl[(oc + 1) * 16 + g] = l;
        pack_hl(v2, &h, &l); po[oc * 16 + g + 8] = h;       pl[oc * 16 + g + 8] = l;
        pack_hl(v3, &h, &l); po[(oc + 1) * 16 + g + 8] = h; pl[(oc + 1) * 16 + g + 8] = l;
    }
}

// ===========================================================================
// GEMM (NT) via mma.sync on pre-converted bf16 hi/lo inputs (R9 validated)
// ===========================================================================
template <bool RELU, bool OUTBF>
__global__ __launch_bounds__(256, 2)
void gemm_hmma_pre(const __nv_bfloat16* __restrict__ Ah, const __nv_bfloat16* __restrict__ Al,
                   const __nv_bfloat16* __restrict__ Bh, const __nv_bfloat16* __restrict__ Bl,
                   const float* __restrict__ b1, const float* __restrict__ b2,
                   float* __restrict__ C,
                   __nv_bfloat16* __restrict__ Chi, __nv_bfloat16* __restrict__ Clo,
                   int K, int N)
{
    __shared__ __align__(16) char Ahi_s[128 * 80];
    __shared__ __align__(16) char Alo_s[128 * 80];
    __shared__ __align__(16) char Bhi_s[64 * 80];
    __shared__ __align__(16) char Blo_s[64 * 80];

    const int tid = threadIdx.x;
    const int m0 = blockIdx.y * 128;
    const int n0 = blockIdx.x * 64;
    const int wid = tid >> 5, lane = tid & 31;
    const int g = lane >> 2, t = lane & 3;
    const int wm = wid & 3;
    const int wn = wid >> 2;

    const int arow0 = tid >> 2;
    const int arow1 = (tid >> 2) + 64;
    const int brow  = tid >> 2;
    const int cgrp  = (tid & 3) * 8;

    float acc[2][4][4];
    #pragma unroll
    for (int ms = 0; ms < 2; ms++)
        #pragma unroll
        for (int nt = 0; nt < 4; nt++)
            #pragma unroll
            for (int r = 0; r < 4; r++) acc[ms][nt][r] = 0.0f;

    ulonglong2 pah0, pah1, pal0, pal1, pbh, pbl;
    pah0 = *(const ulonglong2*)(Ah + (size_t)(m0 + arow0) * K + cgrp);
    pah1 = *(const ulonglong2*)(Ah + (size_t)(m0 + arow1) * K + cgrp);
    pal0 = *(const ulonglong2*)(Al + (size_t)(m0 + arow0) * K + cgrp);
    pal1 = *(const ulonglong2*)(Al + (size_t)(m0 + arow1) * K + cgrp);
    pbh  = *(const ulonglong2*)(Bh + (size_t)(n0 + brow) * K + cgrp);
    pbl  = *(const ulonglong2*)(Bl + (size_t)(n0 + brow) * K + cgrp);

    for (int k0 = 0; k0 < K; k0 += 32) {
        *(ulonglong2*)(Ahi_s + arow0 * 80 + cgrp * 2) = pah0;
        *(ulonglong2*)(Ahi_s + arow1 * 80 + cgrp * 2) = pah1;
        *(ulonglong2*)(Alo_s + arow0 * 80 + cgrp * 2) = pal0;
        *(ulonglong2*)(Alo_s + arow1 * 80 + cgrp * 2) = pal1;
        *(ulonglong2*)(Bhi_s + brow * 80 + cgrp * 2) = pbh;
        *(ulonglong2*)(Blo_s + brow * 80 + cgrp * 2) = pbl;
        __syncthreads();

        if (k0 + 32 < K) {
            const int kn = k0 + 32;
            pah0 = *(const ulonglong2*)(Ah + (size_t)(m0 + arow0) * K + kn + cgrp);
            pah1 = *(const ulonglong2*)(Ah + (size_t)(m0 + arow1) * K + kn + cgrp);
            pal0 = *(const ulonglong2*)(Al + (size_t)(m0 + arow0) * K + kn + cgrp);
            pal1 = *(const ulonglong2*)(Al + (size_t)(m0 + arow1) * K + kn + cgrp);
            pbh  = *(const ulonglong2*)(Bh + (size_t)(n0 + brow) * K + kn + cgrp);
            pbl  = *(const ulonglong2*)(Bl + (size_t)(n0 + brow) * K + kn + cgrp);
        }

        #pragma unroll
        for (int ks = 0; ks < 2; ks++) {
            const int co = ks * 32 + t * 4;
            u32 ahi[2][4], alo[2][4], bhi[4][2], blo[4][2];
            #pragma unroll
            for (int ms = 0; ms < 2; ms++) {
                const int rb = (wm * 32 + ms * 16 + g) * 80 + co;
                ahi[ms][0] = *(const u32*)(Ahi_s + rb);
                ahi[ms][1] = *(const u32*)(Ahi_s + rb + 8 * 80);
                ahi[ms][2] = *(const u32*)(Ahi_s + rb + 16);
                ahi[ms][3] = *(const u32*)(Ahi_s + rb + 8 * 80 + 16);
                alo[ms][0] = *(const u32*)(Alo_s + rb);
                alo[ms][1] = *(const u32*)(Alo_s + rb + 8 * 80);
                alo[ms][2] = *(const u32*)(Alo_s + rb + 16);
                alo[ms][3] = *(const u32*)(Alo_s + rb + 8 * 80 + 16);
            }
            #pragma unroll
            for (int nt = 0; nt < 4; nt++) {
                const int bo = (wn * 32 + nt * 8 + g) * 80 + co;
                bhi[nt][0] = *(const u32*)(Bhi_s + bo);
                bhi[nt][1] = *(const u32*)(Bhi_s + bo + 16);
                blo[nt][0] = *(const u32*)(Blo_s + bo);
                blo[nt][1] = *(const u32*)(Blo_s + bo + 16);
            }
            #pragma unroll
            for (int ms = 0; ms < 2; ms++)
                #pragma unroll
                for (int nt = 0; nt < 4; nt++) {
                    mma16816(acc[ms][nt], ahi[ms], bhi[nt]);
                    mma16816(acc[ms][nt], alo[ms], bhi[nt]);
                    mma16816(acc[ms][nt], ahi[ms], blo[nt]);
                }
        }
        __syncthreads();
    }

    #pragma unroll
    for (int ms = 0; ms < 2; ms++) {
        #pragma unroll
        for (int half = 0; half < 2; half++) {
            const int row = m0 + wm * 32 + ms * 16 + g + half * 8;
            #pragma unroll
            for (int nt = 0; nt < 4; nt++) {
                const int col = n0 + wn * 32 + nt * 8 + 2 * t;
                float bb0 = b1[col]     + (b2 ? b2[col]     : 0.0f);
                float bb1 = b1[col + 1] + (b2 ? b2[col + 1] : 0.0f);
                float v0 = acc[ms][nt][half * 2]     + bb0;
                float v1 = acc[ms][nt][half * 2 + 1] + bb1;
                if (RELU) { v0 = v0 > 0.0f ? v0 : 0.0f; v1 = v1 > 0.0f ? v1 : 0.0f; }
                if (OUTBF) {
                    __nv_bfloat16 h0, l0, h1, l1;
                    pack_hl(v0, &h0, &l0);
                    pack_hl(v1, &h1, &l1);
                    __nv_bfloat162 ph; ph.x = h0; ph.y = h1;
                    __nv_bfloat162 pl; pl.x = l0; pl.y = l1;
                    *(__nv_bfloat162*)(Chi + (size_t)row * N + col) = ph;
                    *(__nv_bfloat162*)(Clo + (size_t)row * N + col) = pl;
                } else {
                    C[(size_t)row * N + col]     = v0;
                    C[(size_t)row * N + col + 1] = v1;
                }
            }
        }
    }
}

// ===========================================================================
// LSTM v3 — R13 validated: 128 blocks x 256 threads, 2 hidden cols per block
// ===========================================================================
__global__ __launch_bounds__(256, 1)
void lstm3_kernel(const float* __restrict__ gx, const float* __restrict__ whh,
                  const int* __restrict__ done,
                  const float* __restrict__ h0, const float* __restrict__ c0,
                  float* __restrict__ out)
{
    extern __shared__ float sm[];
    float* ws     = sm;
    float* h_s    = sm + 8 * WSTR;
    float* gate_s = h_s + 32 * 264;
    float* c_s    = gate_s + 256;

    const int tid = threadIdx.x;
    const int j0 = blockIdx.x * 2;

    #pragma unroll
    for (int l = 0; l < 2; l++) {
        const int id = tid + l * 256;
        const int r = id >> 6;
        const int c4 = (id & 63) * 4;
        *(float4*)(ws + r * WSTR + c4) =
            *(const float4*)(whh + (size_t)((r >> 1) * 256 + j0 + (r & 1)) * 256 + c4);
    }
    if (tid < 64) {
        const int b = tid >> 1, jj = tid & 1;
        c_s[tid] = c0[b * 256 + j0 + jj];
    }
    unsigned bar_gen = 0;
    if (tid == 0) bar_gen = *((volatile unsigned*)&g_gen);
    __syncthreads();

    const int u = tid & 7;
    const int b = tid >> 3;
    const int jj = u & 1, gh = u >> 1;
    const float* w0 = ws + (gh * 2 + jj) * WSTR;
    const float* hb = h_s + b * 264;

    for (int t = 0; t < 64; t++) {
        const float* hsrc = (t == 0) ? h0 : g_hbuf[(t - 1) & 1];
        const int* dn = done + t * 32;
        #pragma unroll
        for (int l = 0; l < 8; l++) {
            const int f = tid + l * 256;
            const int bb = f >> 6;
            const int kc = (f & 63) * 4;
            const float m = 1.0f - (float)dn[bb];
            float4 v = *(const float4*)(hsrc + bb * 256 + kc);
            v.x *= m; v.y *= m; v.z *= m; v.w *= m;
            *(float4*)(h_s + bb * 264 + kc) = v;
        }
        __syncthreads();

        float s0 = 0, s1 = 0, s2 = 0, s3 = 0;
        #pragma unroll 8
        for (int k = 0; k < 256; k += 4) {
            const float4 h4 = *(const float4*)(hb + k);
            const float4 wa = *(const float4*)(w0 + k);
            s0 += h4.x * wa.x;  s1 += h4.y * wa.y;
            s2 += h4.z * wa.z;  s3 += h4.w * wa.w;
        }
        const int row = t * 32 + b;
        const float gv = ((s0 + s1) + (s2 + s3)) +
                         gx[(size_t)row * 1024 + gh * 256 + j0 + jj];
        gate_s[(b * 2 + jj) * 4 + gh] = gv;
        __syncthreads();

        if (tid < 64) {
            const int bb = tid >> 1, j2 = tid & 1;
            const float* gp = gate_s + tid * 4;
            const float gi = gp[0], gf = gp[1], gg = gp[2], go = gp[3];
            const float m = 1.0f - (float)dn[bb];
            const float cold = c_s[tid] * m;
            const float si = 1.0f / (1.0f + __expf(-gi));
            const float sf = 1.0f / (1.0f + __expf(-gf));
            const float so = 1.0f / (1.0f + __expf(-go));
            const float cn = sf * cold + si * tanhf(gg);
            const float h = so * tanhf(cn);
            c_s[tid] = cn;
            const int j = j0 + j2;
            g_hbuf[t & 1][bb * 256 + j] = h;
            out[(size_t)(t * 32 + bb) * 256 + j] = h;
        }
        __threadfence();
        __syncthreads();

        if (t < 63) {
            if (tid == 0) {
                const unsigned prev = atomicAdd(&g_count, 1);
                if (prev == gridDim.x - 1) {
                    g_count = 0;
                    __threadfence();
                    atomicAdd(&g_gen, 1);
                } else {
                    while (*((volatile unsigned*)&g_gen) == bar_gen) { }
                }
                bar_gen++;
                __threadfence();
            }
            __syncthreads();
        }
    }
}

// ===========================================================================
extern "C" void kernel_launch(void* const* d_in, const int* in_sizes, int n_in,
                              void* d_out, int out_size)
{
    const float* x    = (const float*)d_in[0];
    const int*   done = (const int*)d_in[1];
    const float* w1   = (const float*)d_in[2];
    const float* b1   = (const float*)d_in[3];
    const float* w2   = (const float*)d_in[4];
    const float* b2   = (const float*)d_in[5];
    const float* w3   = (const float*)d_in[6];
    const float* b3   = (const float*)d_in[7];
    const float* fcw  = (const float*)d_in[8];
    const float* fcb  = (const float*)d_in[9];
    const float* wih  = (const float*)d_in[10];
    const float* whh  = (const float*)d_in[11];
    const float* bih  = (const float*)d_in[12];
    const float* bhh  = (const float*)d_in[13];
    const float* h0   = (const float*)d_in[14];
    const float* c0   = (const float*)d_in[15];
    float* out = (float*)d_out;

    float *buf2, *gatesx;
    __nv_bfloat16 *c2ah, *c2al, *b3h, *b3l, *fcwh, *fcwl, *wihh, *wihl, *fh, *fl;
    ull *c1wh, *c1wl, *c2wh, *c2wl, *c3wh, *c3wl;
    cudaGetSymbolAddress((void**)&buf2,   g_buf2);
    cudaGetSymbolAddress((void**)&gatesx, g_gatesx);
    cudaGetSymbolAddress((void**)&c2ah, g_c2a_h);
    cudaGetSymbolAddress((void**)&c2al, g_c2a_l);
    cudaGetSymbolAddress((void**)&c1wh, g_c1w_h);
    cudaGetSymbolAddress((void**)&c1wl, g_c1w_l);
    cudaGetSymbolAddress((void**)&c2wh, g_c2w_h);
    cudaGetSymbolAddress((void**)&c2wl, g_c2w_l);
    cudaGetSymbolAddress((void**)&c3wh, g_c3w_h);
    cudaGetSymbolAddress((void**)&c3wl, g_c3w_l);
    cudaGetSymbolAddress((void**)&b3h,  g_b3h);
    cudaGetSymbolAddress((void**)&b3l,  g_b3l);
    cudaGetSymbolAddress((void**)&fcwh, g_fcwh);
    cudaGetSymbolAddress((void**)&fcwl, g_fcwl);
    cudaGetSymbolAddress((void**)&wihh, g_wihh);
    cudaGetSymbolAddress((void**)&wihl, g_wihl);
    cudaGetSymbolAddress((void**)&fh,   g_fh);
    cudaGetSymbolAddress((void**)&fl,   g_fl);

    cudaFuncSetAttribute(conv1_mma_kernel, cudaFuncAttributeMaxDynamicSharedMemorySize, C1_SMEM);
    cudaFuncSetAttribute(conv2_mma_kernel, cudaFuncAttributeMaxDynamicSharedMemorySize, C2_SMEM);
    cudaFuncSetAttribute(conv3_mma_kernel, cudaFuncAttributeMaxDynamicSharedMemorySize, C3_SMEM);
    cudaFuncSetAttribute(lstm3_kernel, cudaFuncAttributeMaxDynamicSharedMemorySize, SMEML3);

    cvt_weights<<<76, 256>>>(w1, w2, w3, c1wh, c1wl, c2wh, c2wl, c3wh, c3wl);
    cvt_hilo2<<<1024, 256>>>((const float4*)fcw, (ull*)fcwh, (ull*)fcwl,
                             (const float4*)wih, (ull*)wihh, (ull*)wihl);
    conv1_mma_kernel<<<2048, 512, C1_SMEM>>>(x, c1wh, c1wl, b1, c2ah, c2al);
    conv2_mma_kernel<<<1024, 512, C2_SMEM>>>(c2ah, c2al, c2wh, c2wl, b2, buf2);
    conv3_mma_kernel<<<512, 256, C3_SMEM>>>(buf2, c3wh, c3wl, b3, b3h, b3l);
    gemm_hmma_pre<true, true><<<dim3(8, 16), 256>>>(
        b3h, b3l, fcwh, fcwl, fcb, nullptr, nullptr, fh, fl, 1024, 512);
    gemm_hmma_pre<false, false><<<dim3(16, 16), 256>>>(
        fh, fl, wihh, wihl, bih, bhh, gatesx, nullptr, nullptr, 512, 1024);
    lstm3_kernel<<<128, 256, SMEML3>>>(gatesx, whh, done, h0, c0, out);
}

// round 16
// speedup vs baseline: 1.5322x; 1.0287x over previous
#include <cuda_runtime.h>
#include <cuda_bf16.h>
#include <math.h>
#include <cstdint>

typedef unsigned long long ull;
typedef uint32_t u32;

// ===========================================================================
// Static scratch
// ===========================================================================
__device__ float g_buf2[2048 * 64 * 6 * 6];
__device__ float g_gatesx[2048 * 1024];
__device__ float g_hbuf[2][32 * 256];
__device__ unsigned g_count;
__device__ unsigned g_gen;
// pre-converted bf16 hi/lo operands
__device__ __nv_bfloat16 g_c2a_h[2048 * 64 * 128], g_c2a_l[2048 * 64 * 128];
__device__ ull g_c1w_h[2048], g_c1w_l[2048];
__device__ ull g_c2w_h[8192], g_c2w_l[8192];
__device__ ull g_c3w_h[9216], g_c3w_l[9216];
__device__ __nv_bfloat16 g_b3h[2048 * 1024], g_b3l[2048 * 1024];
__device__ __nv_bfloat16 g_fcwh[512 * 1024], g_fcwl[512 * 1024];
__device__ __nv_bfloat16 g_wihh[1024 * 512], g_wihl[1024 * 512];
__device__ __nv_bfloat16 g_fh[2048 * 512],  g_fl[2048 * 512];

// LSTM v3
#define WSTR 260
#define SMEML3 ((8 * WSTR + 32 * 264 + 256 + 64) * 4)

// ===========================================================================
// helpers
// ===========================================================================
__device__ __forceinline__ u32 smem_to_u32(const void* p) {
    u32 a;
    asm("{ .reg .u64 t; cvta.to.shared.u64 t, %1; cvt.u32.u64 %0, t; }"
        : "=r"(a) : "l"(p));
    return a;
}
__device__ __forceinline__ void ldsm_x4(u32& r0, u32& r1, u32& r2, u32& r3, u32 addr) {
    asm volatile("ldmatrix.sync.aligned.m8n8.x4.shared.b16 {%0,%1,%2,%3}, [%4];"
                 : "=r"(r0), "=r"(r1), "=r"(r2), "=r"(r3) : "r"(addr));
}
__device__ __forceinline__ void mma16816(float* d, const u32* a, const u32* b) {
    asm volatile(
        "mma.sync.aligned.m16n8k16.row.col.f32.bf16.bf16.f32 "
        "{%0,%1,%2,%3}, {%4,%5,%6,%7}, {%8,%9}, {%0,%1,%2,%3};"
        : "+f"(d[0]), "+f"(d[1]), "+f"(d[2]), "+f"(d[3])
        : "r"(a[0]), "r"(a[1]), "r"(a[2]), "r"(a[3]), "r"(b[0]), "r"(b[1]));
}

__device__ __forceinline__ ull pack_hi4(float4 v, float4* rem) {
    __nv_bfloat16 h0 = __float2bfloat16_rn(v.x);
    __nv_bfloat16 h1 = __float2bfloat16_rn(v.y);
    __nv_bfloat16 h2 = __float2bfloat16_rn(v.z);
    __nv_bfloat16 h3 = __float2bfloat16_rn(v.w);
    rem->x = v.x - __bfloat162float(h0);
    rem->y = v.y - __bfloat162float(h1);
    rem->z = v.z - __bfloat162float(h2);
    rem->w = v.w - __bfloat162float(h3);
    return (ull)__bfloat16_as_ushort(h0) |
           ((ull)__bfloat16_as_ushort(h1) << 16) |
           ((ull)__bfloat16_as_ushort(h2) << 32) |
           ((ull)__bfloat16_as_ushort(h3) << 48);
}
__device__ __forceinline__ ull pack_lo4(float4 v) {
    return (ull)__bfloat16_as_ushort(__float2bfloat16_rn(v.x)) |
           ((ull)__bfloat16_as_ushort(__float2bfloat16_rn(v.y)) << 16) |
           ((ull)__bfloat16_as_ushort(__float2bfloat16_rn(v.z)) << 32) |
           ((ull)__bfloat16_as_ushort(__float2bfloat16_rn(v.w)) << 48);
}
__device__ __forceinline__ void pack_hl(float v, __nv_bfloat16* hi, __nv_bfloat16* lo) {
    __nv_bfloat16 h = __float2bfloat16_rn(v);
    *hi = h;
    *lo = __float2bfloat16_rn(v - __bfloat162float(h));
}

// ===========================================================================
// conversion kernels (fused)
// ===========================================================================
__global__ __launch_bounds__(256)
void cvt_hilo2(const float4* __restrict__ s1, ull* __restrict__ h1v, ull* __restrict__ l1v,
               const float4* __restrict__ s2, ull* __restrict__ h2v, ull* __restrict__ l2v)
{
    const int i = blockIdx.x * 256 + threadIdx.x;
    const float4* src = (i < 131072) ? s1 : s2;
    ull* hi = (i < 131072) ? h1v : h2v;
    ull* lo = (i < 131072) ? l1v : l2v;
    const int j = (i < 131072) ? i : i - 131072;
    float4 v = src[j];
    float4 rem;
    hi[j] = pack_hi4(v, &rem);
    lo[j] = pack_lo4(rem);
}

__global__ __launch_bounds__(256)
void cvt_weights(const float* __restrict__ w1, const float* __restrict__ w2,
                 const float* __restrict__ w3,
                 ull* __restrict__ c1h, ull* __restrict__ c1l,
                 ull* __restrict__ c2h, ull* __restrict__ c2l,
                 ull* __restrict__ c3h, ull* __restrict__ c3l)
{
    int idx = blockIdx.x * 256 + threadIdx.x;
    if (idx < 2048) {
        const int q  = idx >> 9;
        const int oc = (idx >> 4) & 31;
        const int cs = idx & 15;
        const int c = cs >> 2, s = cs & 3;
        const int dh = q >> 1, dw = q & 1;
        float4 v = *(const float4*)(w1 + (size_t)((oc * 4 + c) * 8 + 4 * dh + s) * 8 + 4 * dw);
        float4 rem;
        c1h[idx] = pack_hi4(v, &rem);
        c1l[idx] = pack_lo4(rem);
    } else if (idx < 10240) {
        idx -= 2048;
        const int dh = idx >> 12;
        const int dw = (idx >> 11) & 1;
        const int oc = (idx >> 5) & 63;
        const int c  = idx & 31;
        const float* wp = w2 + (size_t)(oc * 32 + c) * 16;
        float4 v;
        v.x = wp[(2 * dh) * 4 + 2 * dw];
        v.y = wp[(2 * dh) * 4 + 2 * dw + 1];
        v.z = wp[(2 * dh + 1) * 4 + 2 * dw];
        v.w = wp[(2 * dh + 1) * 4 + 2 * dw + 1];
        float4 rem;
        const int row = dh * 128 + dw * 64 + oc;
        c2h[row * 32 + c] = pack_hi4(v, &rem);
        c2l[row * 32 + c] = pack_lo4(rem);
    } else if (idx < 19456) {
        idx -= 10240;
        const int off = idx >> 10;
        const int r   = idx & 1023;
        const int oc  = r >> 4;
        const int icq = r & 15;
        float4 v;
        v.x = w3[(size_t)(oc * 64 + icq * 4 + 0) * 9 + off];
        v.y = w3[(size_t)(oc * 64 + icq * 4 + 1) * 9 + off];
        v.z = w3[(size_t)(oc * 64 + icq * 4 + 2) * 9 + off];
        v.w = w3[(size_t)(oc * 64 + icq * 4 + 3) * 9 + off];
        float4 rem;
        c3h[idx] = pack_hi4(v, &rem);
        c3l[idx] = pack_lo4(rem);
    }
}

// ===========================================================================
// conv1 via mma.sync (bf16x3) v3: 512 threads, 16 warps, ldmatrix fragments.
// ===========================================================================
#define A_STRIDE 144
#define A_BYTES  (273 * A_STRIDE)
#define BQ_BYTES (32 * A_STRIDE)
#define OFF_AHI  128
#define OFF_ALO  (OFF_AHI + A_BYTES)
#define OFF_BHI  (OFF_ALO + A_BYTES)
#define OFF_BLO  (OFF_BHI + 4 * BQ_BYTES)
#define C1_SMEM  (OFF_BLO + 4 * BQ_BYTES)

__global__ __launch_bounds__(512, 1)
void conv1_mma_kernel(const float* __restrict__ x,
                      const ull* __restrict__ c1wh, const ull* __restrict__ c1wl,
                      const float* __restrict__ bias,
                      __nv_bfloat16* __restrict__ oAh, __nv_bfloat16* __restrict__ oAl)
{
    extern __shared__ __align__(16) char smem[];
    float* sbias = (float*)smem;
    char* Ahi = smem + OFF_AHI;
    char* Alo = smem + OFF_ALO;
    char* Bhi = smem + OFF_BHI;
    char* Blo = smem + OFF_BLO;

    const int tid = threadIdx.x;
    const int n = blockIdx.x;
    const float inv255 = 1.0f / 255.0f;

    if (tid < 32) sbias[tid] = bias[tid];

    for (int idx = tid; idx < 4096; idx += 512) {
        const int row = idx >> 4;
        const int cs  = idx & 15;
        const int c = cs >> 2, s = cs & 3;
        const int gh = row >> 4, gw = row & 15;
        float4 v = *(const float4*)(x + (size_t)((n * 4 + c) * 64 + 4 * gh + s) * 64 + 4 * gw);
        v.x *= inv255; v.y *= inv255; v.z *= inv255; v.w *= inv255;
        float4 rem;
        const ull ph = pack_hi4(v, &rem);
        const ull pl = pack_lo4(rem);
        const int off = row * A_STRIDE + cs * 8;
        *(ull*)(Ahi + off) = ph;
        *(ull*)(Alo + off) = pl;
    }
    for (int i = tid; i < 612; i += 512) {
        const int half = i / 306;
        const int off = 256 * A_STRIDE + (i - half * 306) * 8;
        *(ull*)((half ? Alo : Ahi) + off) = 0ull;
    }
    for (int i = tid; i < 2048; i += 512) {
        const int q = i >> 9, oc = (i >> 4) & 31, cs = i & 15;
        const int off = q * BQ_BYTES + oc * A_STRIDE + cs * 8;
        *(ull*)(Bhi + off) = c1wh[i];
        *(ull*)(Blo + off) = c1wl[i];
    }
    __syncthreads();

    const int wid = tid >> 5, lane = tid & 31;
    const int g = lane >> 2, t = lane & 3;
    const int mt = wid;

    const u32 AhiU = smem_to_u32(Ahi), AloU = smem_to_u32(Alo);
    const u32 BhiU = smem_to_u32(Bhi), BloU = smem_to_u32(Blo);
    const int alane = (lane & 15) * A_STRIDE + (lane >> 4) * 16;
    const int blane0 = (((lane >> 4) * 8) + (lane & 7)) * A_STRIDE + ((lane >> 3) & 1) * 16;
    const int blane1 = blane0 + 16 * A_STRIDE;

    float acc[4][4];
    #pragma unroll
    for (int nt = 0; nt < 4; nt++)
        #pragma unroll
        for (int r = 0; r < 4; r++) acc[nt][r] = 0.0f;

    #pragma unroll
    for (int q = 0; q < 4; q++) {
        const int r0 = (q >> 1) * 16 + (q & 1);
        const int arow = (mt * 16 + r0) * A_STRIDE;
        const int qb = q * BQ_BYTES;

        #pragma unroll
        for (int ks = 0; ks < 4; ks++) {
            const int co = ks * 32;
            u32 ahi[4], alo[4], bhi[4][2], blo[4][2];
            ldsm_x4(ahi[0], ahi[1], ahi[2], ahi[3], AhiU + arow + alane + co);
            ldsm_x4(alo[0], alo[1], alo[2], alo[3], AloU + arow + alane + co);
            ldsm_x4(bhi[0][0], bhi[0][1], bhi[1][0], bhi[1][1], BhiU + qb + blane0 + co);
            ldsm_x4(bhi[2][0], bhi[2][1], bhi[3][0], bhi[3][1], BhiU + qb + blane1 + co);
            ldsm_x4(blo[0][0], blo[0][1], blo[1][0], blo[1][1], BloU + qb + blane0 + co);
            ldsm_x4(blo[2][0], blo[2][1], blo[3][0], blo[3][1], BloU + qb + blane1 + co);
            #pragma unroll
            for (int nt = 0; nt < 4; nt++) {
                mma16816(acc[nt], ahi, bhi[nt]);
                mma16816(acc[nt], alo, bhi[nt]);
                mma16816(acc[nt], ahi, blo[nt]);
            }
        }
    }

    __nv_bfloat16* oh_b = oAh + (size_t)n * 8192;
    __nv_bfloat16* ol_b = oAl + (size_t)n * 8192;
    #pragma unroll
    for (int half = 0; half < 2; half++) {
        const int r = mt * 16 + g + half * 8;
        const int oh = r >> 4, ow = r & 15;
        const bool valid = (oh < 15) && (ow < 15);
        const int prow = (oh >> 1) * 8 + (ow >> 1);
        const int sp = (oh & 1) * 2 + (ow & 1);
        const int base = prow * 128 + sp;
        #pragma unroll
        for (int nt = 0; nt < 4; nt++) {
            const int c0 = nt * 8 + 2 * t;
            float v0 = 0.0f, v1 = 0.0f;
            if (valid) {
                v0 = acc[nt][half * 2]     + sbias[c0];
                v1 = acc[nt][half * 2 + 1] + sbias[c0 + 1];
                v0 = v0 > 0.0f ? v0 : 0.0f;
                v1 = v1 > 0.0f ? v1 : 0.0f;
            }
            __nv_bfloat16 h, l;
            pack_hl(v0, &h, &l);
            oh_b[base + c0 * 4] = h;
            ol_b[base + c0 * 4] = l;
            pack_hl(v1, &h, &l);
            oh_b[base + (c0 + 1) * 4] = h;
            ol_b[base + (c0 + 1) * 4] = l;
        }
    }
}

// ===========================================================================
// conv2 via mma.sync (bf16x3) v3: 512 threads, ldmatrix fragments.
// ===========================================================================
#define C2_STRIDE  272
#define C2_A_SZ    (144 * C2_STRIDE)
#define C2_B_SZ    (256 * C2_STRIDE)
#define C2_OFF_AHI 512
#define C2_OFF_ALO (C2_OFF_AHI + C2_A_SZ)
#define C2_OFF_BHI (C2_OFF_ALO + C2_A_SZ)
#define C2_OFF_BLO (C2_OFF_BHI + C2_B_SZ)
#define C2_SMEM    (C2_OFF_BLO + C2_B_SZ)

__global__ __launch_bounds__(512, 1)
void conv2_mma_kernel(const __nv_bfloat16* __restrict__ Agh, const __nv_bfloat16* __restrict__ Agl,
                      const ull* __restrict__ c2wh, const ull* __restrict__ c2wl,
                      const float* __restrict__ bias, float* __restrict__ out)
{
    extern __shared__ __align__(16) char smem[];
    float* sbias = (float*)smem;
    char* Ahi = smem + C2_OFF_AHI;
    char* Alo = smem + C2_OFF_ALO;
    char* Bhi = smem + C2_OFF_BHI;
    char* Blo = smem + C2_OFF_BLO;

    const int tid = threadIdx.x;
    const int nb = blockIdx.x * 2;

    if (tid < 64) sbias[tid] = bias[tid];

    {
        const ulonglong2* sh = (const ulonglong2*)(Agh + (size_t)nb * 8192);
        const ulonglong2* sl = (const ulonglong2*)(Agl + (size_t)nb * 8192);
        for (int idx = tid; idx < 2048; idx += 512) {
            const int row = idx >> 4, ch = idx & 15;
            *(ulonglong2*)(Ahi + row * C2_STRIDE + ch * 16) = sh[idx];
            *(ulonglong2*)(Alo + row * C2_STRIDE + ch * 16) = sl[idx];
        }
    }
    for (int i = tid; i < 512; i += 512) {
        const int half = i >> 8;
        const int j = i & 255;
        const int off = (128 + (j >> 4)) * C2_STRIDE + (j & 15) * 16;
        ulonglong2 z; z.x = 0; z.y = 0;
        *(ulonglong2*)((half ? Alo : Ahi) + off) = z;
    }
    {
        const ulonglong2* sh = (const ulonglong2*)c2wh;
        const ulonglong2* sl = (const ulonglong2*)c2wl;
        for (int idx = tid; idx < 4096; idx += 512) {
            const int row = idx >> 4, ch = idx & 15;
            *(ulonglong2*)(Bhi + row * C2_STRIDE + ch * 16) = sh[idx];
            *(ulonglong2*)(Blo + row * C2_STRIDE + ch * 16) = sl[idx];
        }
    }
    __syncthreads();

    const int wid = tid >> 5, lane = tid & 31;
    const int g = lane >> 2, t = lane & 3;
    const int mtile = wid & 7;
    const int nh = wid >> 3;

    const u32 AhiU = smem_to_u32(Ahi), AloU = smem_to_u32(Alo);
    const u32 BhiU = smem_to_u32(Bhi), BloU = smem_to_u32(Blo);
    const int alane = (lane & 15) * C2_STRIDE + (lane >> 4) * 16;
    const int blane0 = ((nh * 4 + (lane >> 4)) * 8 + (lane & 7)) * C2_STRIDE
                     + ((lane >> 3) & 1) * 16;
    const int blane1 = blane0 + 16 * C2_STRIDE;

    float acc[4][4];
    #pragma unroll
    for (int nt = 0; nt < 4; nt++)
        #pragma unroll
        for (int r = 0; r < 4; r++) acc[nt][r] = 0.0f;

    #pragma unroll
    for (int q = 0; q < 4; q++) {
        const int dh = q >> 1, dw = q & 1;
        const int roff = dh * 8 + dw;
        const int qb = (dh * 128 + dw * 64) * C2_STRIDE;
        const int arow = (mtile * 16 + roff) * C2_STRIDE;

        #pragma unroll
        for (int ks = 0; ks < 8; ks++) {
            const int co = ks * 32;
            u32 ahi[4], alo[4], bhi[4][2], blo[4][2];
            ldsm_x4(ahi[0], ahi[1], ahi[2], ahi[3], AhiU + arow + alane + co);
            ldsm_x4(alo[0], alo[1], alo[2], alo[3], AloU + arow + alane + co);
            ldsm_x4(bhi[0][0], bhi[0][1], bhi[1][0], bhi[1][1], BhiU + qb + blane0 + co);
            ldsm_x4(bhi[2][0], bhi[2][1], bhi[3][0], bhi[3][1], BhiU + qb + blane1 + co);
            ldsm_x4(blo[0][0], blo[0][1], blo[1][0], blo[1][1], BloU + qb + blane0 + co);
            ldsm_x4(blo[2][0], blo[2][1], blo[3][0], blo[3][1], BloU + qb + blane1 + co);
            #pragma unroll
            for (int ntl = 0; ntl < 4; ntl++) {
                mma16816(acc[ntl], ahi, bhi[ntl]);
                mma16816(acc[ntl], alo, bhi[ntl]);
                mma16816(acc[ntl], ahi, blo[ntl]);
            }
        }
    }

    #pragma unroll
    for (int half = 0; half < 2; half++) {
        const int r = mtile * 16 + g + half * 8;
        const int im = r >> 6;
        const int rl = r & 63;
        const int oh = rl >> 3, ow = rl & 7;
        if (oh < 6 && ow < 6) {
            float* ob = out + (size_t)(nb + im) * 2304 + oh * 6 + ow;
            #pragma unroll
            for (int ntl = 0; ntl < 4; ntl++) {
                const int oc = (nh * 4 + ntl) * 8 + 2 * t;
                float v0 = acc[ntl][half * 2]     + sbias[oc];
                float v1 = acc[ntl][half * 2 + 1] + sbias[oc + 1];
                ob[oc * 36]       = v0 > 0.0f ? v0 : 0.0f;
                ob[(oc + 1) * 36] = v1 > 0.0f ? v1 : 0.0f;
            }
        }
    }
}

// ===========================================================================
// conv3 via mma.sync (bf16x3) — R12 validated
// ===========================================================================
#define C3_XSTR  144
#define C3_IMG   (36 * C3_XSTR)
#define C3_XHI   256
#define C3_XLO   (C3_XHI + 4 * C3_IMG)
#define C3_BHI   (C3_XLO + 4 * C3_IMG)
#define C3_B_SZ  (576 * C3_XSTR)
#define C3_BLO   (C3_BHI + C3_B_SZ)
#define C3_SMEM  (C3_BLO + C3_B_SZ)

__global__ __launch_bounds__(256, 1)
void conv3_mma_kernel(const float* __restrict__ in,
                      const ull* __restrict__ c3wh, const ull* __restrict__ c3wl,
                      const float* __restrict__ bias,
                      __nv_bfloat16* __restrict__ oh_g, __nv_bfloat16* __restrict__ ol_g)
{
    extern __shared__ __align__(16) char smem[];
    float* sbias = (float*)smem;
    char* Xhi = smem + C3_XHI;
    char* Xlo = smem + C3_XLO;
    char* Bhi = smem + C3_BHI;
    char* Blo = smem + C3_BLO;

    const int tid = threadIdx.x;
    const int n4 = blockIdx.x * 4;

    if (tid < 64) sbias[tid] = bias[tid];

    for (int idx = tid; idx < 2304; idx += 256) {
        const int im = idx / 576;
        const int r  = idx - im * 576;
        const int ic = r / 9;
        const int pg = r - ic * 9;
        float4 v = *(const float4*)(in + (size_t)(n4 + im) * 2304 + ic * 36 + pg * 4);
        char* xh = Xhi + im * C3_IMG;
        char* xl = Xlo + im * C3_IMG;
        __nv_bfloat16 h, l;
        pack_hl(v.x, &h, &l);
        *(__nv_bfloat16*)(xh + (pg * 4 + 0) * C3_XSTR + ic * 2) = h;
        *(__nv_bfloat16*)(xl + (pg * 4 + 0) * C3_XSTR + ic * 2) = l;
        pack_hl(v.y, &h, &l);
        *(__nv_bfloat16*)(xh + (pg * 4 + 1) * C3_XSTR + ic * 2) = h;
        *(__nv_bfloat16*)(xl + (pg * 4 + 1) * C3_XSTR + ic * 2) = l;
        pack_hl(v.z, &h, &l);
        *(__nv_bfloat16*)(xh + (pg * 4 + 2) * C3_XSTR + ic * 2) = h;
        *(__nv_bfloat16*)(xl + (pg * 4 + 2) * C3_XSTR + ic * 2) = l;
        pack_hl(v.w, &h, &l);
        *(__nv_bfloat16*)(xh + (pg * 4 + 3) * C3_XSTR + ic * 2) = h;
        *(__nv_bfloat16*)(xl + (pg * 4 + 3) * C3_XSTR + ic * 2) = l;
    }
    for (int idx = tid; idx < 9216; idx += 256) {
        const int row = idx >> 4, c = idx & 15;
        *(ull*)(Bhi + row * C3_XSTR + c * 8) = c3wh[idx];
        *(ull*)(Blo + row * C3_XSTR + c * 8) = c3wl[idx];
    }
    __syncthreads();

    const int wid = tid >> 5, lane = tid & 31;
    const int g = lane >> 2, t = lane & 3;
    const int img = wid & 3;
    const int oc0 = (wid >> 2) * 32;
    const int n = n4 + img;

    float acc[4][4];
    #pragma unroll
    for (int nt = 0; nt < 4; nt++)
        #pragma unroll
        for (int r = 0; r < 4; r++) acc[nt][r] = 0.0f;

    const int ri_g = (g >> 2) * 6 + (g & 3);
    const char* Xh = Xhi + img * C3_IMG;
    const char* Xl = Xlo + img * C3_IMG;

    #pragma unroll
    for (int off = 0; off < 9; off++) {
        const int kh = off / 3, kw = off - kh * 3;
        const int rowA = (ri_g + kh * 6 + kw) * C3_XSTR;
        const char* Bo_hi = Bhi + (off * 64 + oc0) * C3_XSTR;
        const char* Bo_lo = Blo + (off * 64 + oc0) * C3_XSTR;

        #pragma unroll
        for (int ks = 0; ks < 4; ks++) {
            const int co = ks * 32 + t * 4;
            u32 ahi[4], alo[4], bhi[4][2], blo[4][2];
            const int rb = rowA + co;
            ahi[0] = *(const u32*)(Xh + rb);
            ahi[1] = *(const u32*)(Xh + rb + 12 * C3_XSTR);
            ahi[2] = *(const u32*)(Xh + rb + 16);
            ahi[3] = *(const u32*)(Xh + rb + 12 * C3_XSTR + 16);
            alo[0] = *(const u32*)(Xl + rb);
            alo[1] = *(const u32*)(Xl + rb + 12 * C3_XSTR);
            alo[2] = *(const u32*)(Xl + rb + 16);
            alo[3] = *(const u32*)(Xl + rb + 12 * C3_XSTR + 16);
            #pragma unroll
            for (int nt = 0; nt < 4; nt++) {
                const int bo = (nt * 8 + g) * C3_XSTR + co;
                bhi[nt][0] = *(const u32*)(Bo_hi + bo);
                bhi[nt][1] = *(const u32*)(Bo_hi + bo + 16);
                blo[nt][0] = *(const u32*)(Bo_lo + bo);
                blo[nt][1] = *(const u32*)(Bo_lo + bo + 16);
            }
            #pragma unroll
            for (int nt = 0; nt < 4; nt++) {
                mma16816(acc[nt], ahi, bhi[nt]);
                mma16816(acc[nt], alo, bhi[nt]);
                mma16816(acc[nt], ahi, blo[nt]);
            }
        }
    }

    __nv_bfloat16* po = oh_g + (size_t)n * 1024;
    __nv_bfloat16* pl = ol_g + (size_t)n * 1024;
    #pragma unroll
    for (int nt = 0; nt < 4; nt++) {
        const int oc = oc0 + nt * 8 + 2 * t;
        const float b0 = sbias[oc], b1 = sbias[oc + 1];
        float v0 = acc[nt][0] + b0;  v0 = v0 > 0.0f ? v0 : 0.0f;
        float v1 = acc[nt][1] + b1;  v1 = v1 > 0.0f ? v1 : 0.0f;
        float v2 = acc[nt][2] + b0;  v2 = v2 > 0.0f ? v2 : 0.0f;
        float v3 = acc[nt][3] + b1;  v3 = v3 > 0.0f ? v3 : 0.0f;
        __nv_bfloat16 h, l;
        pack_hl(v0, &h, &l); po[oc * 16 + g] = h;           pl[oc * 16 + g] = l;
        pack_hl(v1, &h, &l); po[(oc + 1) * 16 + g] = h;     pl[(oc + 1) * 16 + g] = l;
        pack_hl(v2, &h, &l); po[oc * 16 + g + 8] = h;       pl[oc * 16 + g + 8] = l;
        pack_hl(v3, &h, &l); po[(oc + 1) * 16 + g + 8] = h; pl[(oc + 1) * 16 + g + 8] = l;
    }
}

// ===========================================================================
// GEMM (NT) via mma.sync on pre-converted bf16 hi/lo inputs (R9 validated)
// ===========================================================================
template <bool RELU, bool OUTBF>
__global__ __launch_bounds__(256, 2)
void gemm_hmma_pre(const __nv_bfloat16* __restrict__ Ah, const __nv_bfloat16* __restrict__ Al,
                   const __nv_bfloat16* __restrict__ Bh, const __nv_bfloat16* __restrict__ Bl,
                   const float* __restrict__ b1, const float* __restrict__ b2,
                   float* __restrict__ C,
                   __nv_bfloat16* __restrict__ Chi, __nv_bfloat16* __restrict__ Clo,
                   int K, int N)
{
    __shared__ __align__(16) char Ahi_s[128 * 80];
    __shared__ __align__(16) char Alo_s[128 * 80];
    __shared__ __align__(16) char Bhi_s[64 * 80];
    __shared__ __align__(16) char Blo_s[64 * 80];

    const int tid = threadIdx.x;
    const int m0 = blockIdx.y * 128;
    const int n0 = blockIdx.x * 64;
    const int wid = tid >> 5, lane = tid & 31;
    const int g = lane >> 2, t = lane & 3;
    const int wm = wid & 3;
    const int wn = wid >> 2;

    const int arow0 = tid >> 2;
    const int arow1 = (tid >> 2) + 64;
    const int brow  = tid >> 2;
    const int cgrp  = (tid & 3) * 8;

    float acc[2][4][4];
    #pragma unroll
    for (int ms = 0; ms < 2; ms++)
        #pragma unroll
        for (int nt = 0; nt < 4; nt++)
            #pragma unroll
            for (int r = 0; r < 4; r++) acc[ms][nt][r] = 0.0f;

    ulonglong2 pah0, pah1, pal0, pal1, pbh, pbl;
    pah0 = *(const ulonglong2*)(Ah + (size_t)(m0 + arow0) * K + cgrp);
    pah1 = *(const ulonglong2*)(Ah + (size_t)(m0 + arow1) * K + cgrp);
    pal0 = *(const ulonglong2*)(Al + (size_t)(m0 + arow0) * K + cgrp);
    pal1 = *(const ulonglong2*)(Al + (size_t)(m0 + arow1) * K + cgrp);
    pbh  = *(const ulonglong2*)(Bh + (size_t)(n0 + brow) * K + cgrp);
    pbl  = *(const ulonglong2*)(Bl + (size_t)(n0 + brow) * K + cgrp);

    for (int k0 = 0; k0 < K; k0 += 32) {
        *(ulonglong2*)(Ahi_s + arow0 * 80 + cgrp * 2) = pah0;
        *(ulonglong2*)(Ahi_s + arow1 * 80 + cgrp * 2) = pah1;
        *(ulonglong2*)(Alo_s + arow0 * 80 + cgrp * 2) = pal0;
        *(ulonglong2*)(Alo_s + arow1 * 80 + cgrp * 2) = pal1;
        *(ulonglong2*)(Bhi_s + brow * 80 + cgrp * 2) = pbh;
        *(ulonglong2*)(Blo_s + brow * 80 + cgrp * 2) = pbl;
        __syncthreads();

        if (k0 + 32 < K) {
            const int kn = k0 + 32;
            pah0 = *(const ulonglong2*)(Ah + (size_t)(m0 + arow0) * K + kn + cgrp);
            pah1 = *(const ulonglong2*)(Ah + (size_t)(m0 + arow1) * K + kn + cgrp);
            pal0 = *(const ulonglong2*)(Al + (size_t)(m0 + arow0) * K + kn + cgrp);
            pal1 = *(const ulonglong2*)(Al + (size_t)(m0 + arow1) * K + kn + cgrp);
            pbh  = *(const ulonglong2*)(Bh + (size_t)(n0 + brow) * K + kn + cgrp);
            pbl  = *(const ulonglong2*)(Bl + (size_t)(n0 + brow) * K + kn + cgrp);
        }

        #pragma unroll
        for (int ks = 0; ks < 2; ks++) {
            const int co = ks * 32 + t * 4;
            u32 ahi[2][4], alo[2][4], bhi[4][2], blo[4][2];
            #pragma unroll
            for (int ms = 0; ms < 2; ms++) {
                const int rb = (wm * 32 + ms * 16 + g) * 80 + co;
                ahi[ms][0] = *(const u32*)(Ahi_s + rb);
                ahi[ms][1] = *(const u32*)(Ahi_s + rb + 8 * 80);
                ahi[ms][2] = *(const u32*)(Ahi_s + rb + 16);
                ahi[ms][3] = *(const u32*)(Ahi_s + rb + 8 * 80 + 16);
                alo[ms][0] = *(const u32*)(Alo_s + rb);
                alo[ms][1] = *(const u32*)(Alo_s + rb + 8 * 80);
                alo[ms][2] = *(const u32*)(Alo_s + rb + 16);
                alo[ms][3] = *(const u32*)(Alo_s + rb + 8 * 80 + 16);
            }
            #pragma unroll
            for (int nt = 0; nt < 4; nt++) {
                const int bo = (wn * 32 + nt * 8 + g) * 80 + co;
                bhi[nt][0] = *(const u32*)(Bhi_s + bo);
                bhi[nt][1] = *(const u32*)(Bhi_s + bo + 16);
                blo[nt][0] = *(const u32*)(Blo_s + bo);
                blo[nt][1] = *(const u32*)(Blo_s + bo + 16);
            }
            #pragma unroll
            for (int ms = 0; ms < 2; ms++)
                #pragma unroll
                for (int nt = 0; nt < 4; nt++) {
                    mma16816(acc[ms][nt], ahi[ms], bhi[nt]);
                    mma16816(acc[ms][nt], alo[ms], bhi[nt]);
                    mma16816(acc[ms][nt], ahi[ms], blo[nt]);
                }
        }
        __syncthreads();
    }

    #pragma unroll
    for (int ms = 0; ms < 2; ms++) {
        #pragma unroll
        for (int half = 0; half < 2; half++) {
            const int row = m0 + wm * 32 + ms * 16 + g + half * 8;
            #pragma unroll
            for (int nt = 0; nt < 4; nt++) {
                const int col = n0 + wn * 32 + nt * 8 + 2 * t;
                float bb0 = b1[col]     + (b2 ? b2[col]     : 0.0f);
                float bb1 = b1[col + 1] + (b2 ? b2[col + 1] : 0.0f);
                float v0 = acc[ms][nt][half * 2]     + bb0;
                float v1 = acc[ms][nt][half * 2 + 1] + bb1;
                if (RELU) { v0 = v0 > 0.0f ? v0 : 0.0f; v1 = v1 > 0.0f ? v1 : 0.0f; }
                if (OUTBF) {
                    __nv_bfloat16 h0, l0, h1, l1;
                    pack_hl(v0, &h0, &l0);
                    pack_hl(v1, &h1, &l1);
                    __nv_bfloat162 ph; ph.x = h0; ph.y = h1;
                    __nv_bfloat162 pl; pl.x = l0; pl.y = l1;
                    *(__nv_bfloat162*)(Chi + (size_t)row * N + col) = ph;
                    *(__nv_bfloat162*)(Clo + (size_t)row * N + col) = pl;
                } else {
                    C[(size_t)row * N + col]     = v0;
                    C[(size_t)row * N + col + 1] = v1;
                }
            }
        }
    }
}

// ===========================================================================
// LSTM v3 — R13 validated
// ===========================================================================
__global__ __launch_bounds__(256, 1)
void lstm3_kernel(const float* __restrict__ gx, const float* __restrict__ whh,
                  const int* __restrict__ done,
                  const float* __restrict__ h0, const float* __restrict__ c0,
                  float* __restrict__ out)
{
    extern __shared__ float sm[];
    float* ws     = sm;
    float* h_s    = sm + 8 * WSTR;
    float* gate_s = h_s + 32 * 264;
    float* c_s    = gate_s + 256;

    const int tid = threadIdx.x;
    const int j0 = blockIdx.x * 2;

    #pragma unroll
    for (int l = 0; l < 2; l++) {
        const int id = tid + l * 256;
        const int r = id >> 6;
        const int c4 = (id & 63) * 4;
        *(float4*)(ws + r * WSTR + c4) =
            *(const float4*)(whh + (size_t)((r >> 1) * 256 + j0 + (r & 1)) * 256 + c4);
    }
    if (tid < 64) {
        const int b = tid >> 1, jj = tid & 1;
        c_s[tid] = c0[b * 256 + j0 + jj];
    }
    unsigned bar_gen = 0;
    if (tid == 0) bar_gen = *((volatile unsigned*)&g_gen);
    __syncthreads();

    const int u = tid & 7;
    const int b = tid >> 3;
    const int jj = u & 1, gh = u >> 1;
    const float* w0 = ws + (gh * 2 + jj) * WSTR;
    const float* hb = h_s + b * 264;

    for (int t = 0; t < 64; t++) {
        const float* hsrc = (t == 0) ? h0 : g_hbuf[(t - 1) & 1];
        const int* dn = done + t * 32;
        #pragma unroll
        for (int l = 0; l < 8; l++) {
            const int f = tid + l * 256;
            const int bb = f >> 6;
            const int kc = (f & 63) * 4;
            const float m = 1.0f - (float)dn[bb];
            float4 v = *(const float4*)(hsrc + bb * 256 + kc);
            v.x *= m; v.y *= m; v.z *= m; v.w *= m;
            *(float4*)(h_s + bb * 264 + kc) = v;
        }
        __syncthreads();

        float s0 = 0, s1 = 0, s2 = 0, s3 = 0;
        #pragma unroll 8
        for (int k = 0; k < 256; k += 4) {
            const float4 h4 = *(const float4*)(hb + k);
            const float4 wa = *(const float4*)(w0 + k);
            s0 += h4.x * wa.x;  s1 += h4.y * wa.y;
            s2 += h4.z * wa.z;  s3 += h4.w * wa.w;
        }
        const int row = t * 32 + b;
        const float gv = ((s0 + s1) + (s2 + s3)) +
                         gx[(size_t)row * 1024 + gh * 256 + j0 + jj];
        gate_s[(b * 2 + jj) * 4 + gh] = gv;
        __syncthreads();

        if (tid < 64) {
            const int bb = tid >> 1, j2 = tid & 1;
            const float* gp = gate_s + tid * 4;
            const float gi = gp[0], gf = gp[1], gg = gp[2], go = gp[3];
            const float m = 1.0f - (float)dn[bb];
            const float cold = c_s[tid] * m;
            const float si = 1.0f / (1.0f + __expf(-gi));
            const float sf = 1.0f / (1.0f + __expf(-gf));
            const float so = 1.0f / (1.0f + __expf(-go));
            const float cn = sf * cold + si * tanhf(gg);
            const float h = so * tanhf(cn);
            c_s[tid] = cn;
            const int j = j0 + j2;
            g_hbuf[t & 1][bb * 256 + j] = h;
            out[(size_t)(t * 32 + bb) * 256 + j] = h;
        }
        __threadfence();
        __syncthreads();

        if (t < 63) {
            if (tid == 0) {
                const unsigned prev = atomicAdd(&g_count, 1);
                if (prev == gridDim.x - 1) {
                    g_count = 0;
                    __threadfence();
                    atomicAdd(&g_gen, 1);
                } else {
                    while (*((volatile unsigned*)&g_gen) == bar_gen) { }
                }
                bar_gen++;
                __threadfence();
            }
            __syncthreads();
        }
    }
}

// ===========================================================================
extern "C" void kernel_launch(void* const* d_in, const int* in_sizes, int n_in,
                              void* d_out, int out_size)
{
    const float* x    = (const float*)d_in[0];
    const int*   done = (const int*)d_in[1];
    const float* w1   = (const float*)d_in[2];
    const float* b1   = (const float*)d_in[3];
    const float* w2   = (const float*)d_in[4];
    const float* b2   = (const float*)d_in[5];
    const float* w3   = (const float*)d_in[6];
    const float* b3   = (const float*)d_in[7];
    const float* fcw  = (const float*)d_in[8];
    const float* fcb  = (const float*)d_in[9];
    const float* wih  = (const float*)d_in[10];
    const float* whh  = (const float*)d_in[11];
    const float* bih  = (const float*)d_in[12];
    const float* bhh  = (const float*)d_in[13];
    const float* h0   = (const float*)d_in[14];
    const float* c0   = (const float*)d_in[15];
    float* out = (float*)d_out;

    float *buf2, *gatesx;
    __nv_bfloat16 *c2ah, *c2al, *b3h, *b3l, *fcwh, *fcwl, *wihh, *wihl, *fh, *fl;
    ull *c1wh, *c1wl, *c2wh, *c2wl, *c3wh, *c3wl;
    cudaGetSymbolAddress((void**)&buf2,   g_buf2);
    cudaGetSymbolAddress((void**)&gatesx, g_gatesx);
    cudaGetSymbolAddress((void**)&c2ah, g_c2a_h);
    cudaGetSymbolAddress((void**)&c2al, g_c2a_l);
    cudaGetSymbolAddress((void**)&c1wh, g_c1w_h);
    cudaGetSymbolAddress((void**)&c1wl, g_c1w_l);
    cudaGetSymbolAddress((void**)&c2wh, g_c2w_h);
    cudaGetSymbolAddress((void**)&c2wl, g_c2w_l);
    cudaGetSymbolAddress((void**)&c3wh, g_c3w_h);
    cudaGetSymbolAddress((void**)&c3wl, g_c3w_l);
    cudaGetSymbolAddress((void**)&b3h,  g_b3h);
    cudaGetSymbolAddress((void**)&b3l,  g_b3l);
    cudaGetSymbolAddress((void**)&fcwh, g_fcwh);
    cudaGetSymbolAddress((void**)&fcwl, g_fcwl);
    cudaGetSymbolAddress((void**)&wihh, g_wihh);
    cudaGetSymbolAddress((void**)&wihl, g_wihl);
    cudaGetSymbolAddress((void**)&fh,   g_fh);
    cudaGetSymbolAddress((void**)&fl,   g_fl);

    cudaFuncSetAttribute(conv1_mma_kernel, cudaFuncAttributeMaxDynamicSharedMemorySize, C1_SMEM);
    cudaFuncSetAttribute(conv2_mma_kernel, cudaFuncAttributeMaxDynamicSharedMemorySize, C2_SMEM);
    cudaFuncSetAttribute(conv3_mma_kernel, cudaFuncAttributeMaxDynamicSharedMemorySize, C3_SMEM);
    cudaFuncSetAttribute(lstm3_kernel, cudaFuncAttributeMaxDynamicSharedMemorySize, SMEML3);

    cvt_weights<<<76, 256>>>(w1, w2, w3, c1wh, c1wl, c2wh, c2wl, c3wh, c3wl);
    cvt_hilo2<<<1024, 256>>>((const float4*)fcw, (ull*)fcwh, (ull*)fcwl,
                             (const float4*)wih, (ull*)wihh, (ull*)wihl);
    conv1_mma_kernel<<<2048, 512, C1_SMEM>>>(x, c1wh, c1wl, b1, c2ah, c2al);
    conv2_mma_kernel<<<1024, 512, C2_SMEM>>>(c2ah, c2al, c2wh, c2wl, b2, buf2);
    conv3_mma_kernel<<<512, 256, C3_SMEM>>>(buf2, c3wh, c3wl, b3, b3h, b3l);
    gemm_hmma_pre<true, true><<<dim3(8, 16), 256>>>(
        b3h, b3l, fcwh, fcwl, fcb, nullptr, nullptr, fh, fl, 1024, 512);
    gemm_hmma_pre<false, false><<<dim3(16, 16), 256>>>(
        fh, fl, wihh, wihl, bih, bhh, gatesx, nullptr, nullptr, 512, 1024);
    lstm3_kernel<<<128, 256, SMEML3>>>(gatesx, whh, done, h0, c0, out);
}